// round 5
// baseline (speedup 1.0000x reference)
#include <cuda_runtime.h>

// ===================== problem constants =====================
#define TSEG 22
#define NBT  44            // B*T = 2*22
#define PIX  49            // 7*7

// ===================== scratch (static device memory) =====================
__device__ float g_xt[(size_t)NBT * 2048 * PIX];      // (bt, c, p)
__device__ float g_mx[(size_t)NBT * 2048 * PIX];      // masked x
__device__ float g_Gx[(size_t)NBT * 2048 * PIX];      // conv_x(mx_t) with lstm_w x-part
__device__ float g_y1[(size_t)NBT * 1024 * PIX];
__device__ float g_y2[(size_t)NBT * 512 * PIX];
__device__ float g_mask[NBT * PIX];
__device__ float g_meanx[2 * 2048 * PIX];
__device__ float g_mxc[NBT * 2048];
__device__ float g_attfea[NBT];
__device__ float g_aw[NBT];
__device__ float g_tmp1[2 * 1024 * PIX];
__device__ float g_h[2 * 512 * PIX];
__device__ float g_cst[2 * 512 * PIX];
__device__ float g_gates0[2 * 2048 * PIX];
__device__ float g_part[(size_t)8 * 2 * 2048 * PIX];  // ksplit partials
__device__ float g_houts[TSEG * 2 * 512];

// ===================== f32x2 helpers =====================
__device__ __forceinline__ void fma2(unsigned long long &d, unsigned long long a, unsigned long long b) {
    asm("fma.rn.f32x2 %0, %1, %2, %3;" : "=l"(d) : "l"(a), "l"(b), "l"(d));
}
__device__ __forceinline__ unsigned long long pack2(float x) {
    unsigned long long r;
    asm("mov.b64 %0, {%1, %1};" : "=l"(r) : "f"(x));
    return r;
}
__device__ __forceinline__ float2 unpack2(unsigned long long v) {
    float2 f;
    asm("mov.b64 {%0, %1}, %2;" : "=f"(f.x), "=f"(f.y) : "l"(v));
    return f;
}

// ===================== generic 3x3 SAME conv on 7x7, NCHW =====================
// grid: (N, OC/64, nsplit); block: (49, 8)
// in: (N, IC, 49)  wt: (OC, wstride, 3, 3) using ic range [ic0, ic0+IC/nsplit)
// nsplit==1: writes final (postop==1 -> BN+ReLU) at out[(n*OC+oc)*49+p]
// nsplit>1 : writes raw partial at out[((ks*N+n)*OC+oc)*49+p]
#define OCT 64
#define ICC 8
__global__ __launch_bounds__(392) void conv3x3_k(
    const float* __restrict__ in, const float* __restrict__ wt,
    const float* __restrict__ bn, float* __restrict__ out,
    int IC, int OC, int wstride, int nsplit, int postop)
{
    int n = blockIdx.x;
    int N = gridDim.x;
    int ocbase = blockIdx.y * OCT;
    int ks = blockIdx.z;
    int icn = IC / nsplit;
    int ic0 = ks * icn;
    int p = threadIdx.x;          // 0..48
    int j = threadIdx.y;          // 0..7
    int tid = j * 49 + p;

    __shared__ __align__(16) float s_in[ICC][52];
    __shared__ __align__(16) float s_w[ICC * 9][OCT + 4];   // row stride 68 floats (16B aligned)

    int oh = p / 7, ow = p - oh * 7;
    int off[9]; float vmsk[9];
#pragma unroll
    for (int kh = 0; kh < 3; kh++)
#pragma unroll
        for (int kw = 0; kw < 3; kw++) {
            int ih = oh + kh - 1, iw = ow + kw - 1;
            int k = kh * 3 + kw;
            bool v = (ih >= 0) && (ih < 7) && (iw >= 0) && (iw < 7);
            vmsk[k] = v ? 1.f : 0.f;
            off[k] = v ? (ih * 7 + iw) : 0;
        }

    unsigned long long acc2[4] = {0ull, 0ull, 0ull, 0ull};
    const float* inN = in + ((size_t)n * IC + ic0) * PIX;

    for (int icb = 0; icb < icn; icb += ICC) {
        __syncthreads();
        {   // input chunk: exactly one element per thread (8*49 = 392)
            int ci = tid / 49, pp = tid - ci * 49;
            s_in[ci][pp] = inN[(size_t)(icb + ci) * PIX + pp];
        }
        // weights: 64*8*9 = 4608 elements; k fastest -> contiguous gmem reads
        for (int t = tid; t < OCT * ICC * 9; t += 392) {
            int ocl = t / (ICC * 9);
            int rem = t - ocl * (ICC * 9);      // = ci*9 + k
            s_w[rem][ocl] = wt[((size_t)(ocbase + ocl) * wstride + ic0 + icb) * 9 + rem];
        }
        __syncthreads();
#pragma unroll
        for (int ci = 0; ci < ICC; ci++) {
            float v[9];
#pragma unroll
            for (int k = 0; k < 9; k++) v[k] = s_in[ci][off[k]] * vmsk[k];
#pragma unroll
            for (int k = 0; k < 9; k++) {
                unsigned long long vv = pack2(v[k]);
                const ulonglong2* wr = (const ulonglong2*)&s_w[ci * 9 + k][j * 8];
                ulonglong2 wA = wr[0];
                ulonglong2 wB = wr[1];
                fma2(acc2[0], vv, wA.x);
                fma2(acc2[1], vv, wA.y);
                fma2(acc2[2], vv, wB.x);
                fma2(acc2[3], vv, wB.y);
            }
        }
    }

    float accf[8];
#pragma unroll
    for (int q = 0; q < 4; q++) { float2 f = unpack2(acc2[q]); accf[2 * q] = f.x; accf[2 * q + 1] = f.y; }

#pragma unroll
    for (int r = 0; r < 8; r++) {
        int oc = ocbase + j * 8 + r;
        float val = accf[r];
        if (nsplit == 1) {
            if (postop == 1) {
                float gg = bn[oc], bb = bn[OC + oc], mm = bn[2 * OC + oc], vv = bn[3 * OC + oc];
                val = (val - mm) * gg * rsqrtf(vv + 1e-5f) + bb;
                val = fmaxf(val, 0.f);
            }
            out[((size_t)n * OC + oc) * PIX + p] = val;
        } else {
            out[((size_t)(ks * N + n) * OC + oc) * PIX + p] = val;
        }
    }
}

// sum ksplit partials, optional BN+ReLU
__global__ void finish_k(const float* __restrict__ part, int nsplit, int chunk,
                         const float* __restrict__ bn, float* __restrict__ out,
                         int OC, int total, int postop)
{
    int i = blockIdx.x * blockDim.x + threadIdx.x;
    if (i >= total) return;
    float s = 0.f;
    for (int ks = 0; ks < nsplit; ks++) s += part[(size_t)ks * chunk + i];
    if (postop == 1) {
        int oc = (i / PIX) % OC;
        float g = bn[oc], b = bn[OC + oc], m = bn[2 * OC + oc], v = bn[3 * OC + oc];
        s = (s - m) * g * rsqrtf(v + 1e-5f) + b;
        s = fmaxf(s, 0.f);
    }
    out[i] = s;
}

// ===================== small kernels =====================
__global__ void transpose_k(const float* __restrict__ x, float* __restrict__ xt) {
    int i = blockIdx.x * blockDim.x + threadIdx.x;
    const int total = NBT * 2048 * PIX;
    if (i >= total) return;
    int p = i % PIX;
    int c = (i / PIX) % 2048;
    int bt = i / (PIX * 2048);
    int b = bt / TSEG, t = bt - b * TSEG;
    xt[i] = x[(((size_t)b * 2048 + c) * TSEG + t) * PIX + p];
}

__global__ void mask_final_k(const float* __restrict__ y2, const float* __restrict__ w3,
                             float* __restrict__ mask, float* __restrict__ outmask)
{
    int n = blockIdx.x;
    int p = threadIdx.x, g = threadIdx.y;
    int oh = p / 7, ow = p - oh * 7;
    float s = 0.f;
    for (int ic = g; ic < 512; ic += 8) {
        const float* row = y2 + ((size_t)n * 512 + ic) * PIX;
        const float* wr = w3 + ic * 9;
#pragma unroll
        for (int kh = 0; kh < 3; kh++)
#pragma unroll
            for (int kw = 0; kw < 3; kw++) {
                int ih = oh + kh - 1, iw = ow + kw - 1;
                if (ih >= 0 && ih < 7 && iw >= 0 && iw < 7)
                    s += row[ih * 7 + iw] * wr[kh * 3 + kw];
            }
    }
    __shared__ float red[8][49];
    red[g][p] = s;
    __syncthreads();
    if (g == 0) {
        float tot = 0.f;
#pragma unroll
        for (int q = 0; q < 8; q++) tot += red[q][p];
        float m = 1.f / (1.f + expf(-tot));
        mask[n * PIX + p] = m;
        outmask[n * PIX + p] = m;
    }
}

__global__ void mx_k(const float* __restrict__ xt, const float* __restrict__ mask, float* __restrict__ mx) {
    int i = blockIdx.x * blockDim.x + threadIdx.x;
    const int total = NBT * 2048 * PIX;
    if (i >= total) return;
    int p = i % PIX;
    int bt = i / (PIX * 2048);
    mx[i] = xt[i] * mask[bt * PIX + p];
}

__global__ void meanx_k(const float* __restrict__ mx, float* __restrict__ meanx) {
    int i = blockIdx.x * blockDim.x + threadIdx.x;
    const int inner = 2048 * PIX;
    if (i >= 2 * inner) return;
    int b = i / inner, r = i - b * inner;
    float s = 0.f;
    for (int t = 0; t < TSEG; t++) s += mx[((size_t)(b * TSEG + t)) * inner + r];
    meanx[i] = s * (1.f / (float)TSEG);
}

__global__ void mxc_k(const float* __restrict__ mx, float* __restrict__ mxc) {
    int i = blockIdx.x * blockDim.x + threadIdx.x;
    if (i >= NBT * 2048) return;
    const float* row = mx + (size_t)i * PIX;
    float s = 0.f;
    for (int p = 0; p < PIX; p++) s += row[p];
    mxc[i] = s * (1.f / (float)PIX);
}

__global__ void attfea_k(const float* __restrict__ mxc, const float* __restrict__ wf,
                         float* __restrict__ attfea)
{
    int bt = blockIdx.x;
    int tid = threadIdx.x;
    __shared__ float sr[256];
    float s = 0.f;
    for (int c = tid; c < 2048; c += 256) s += mxc[bt * 2048 + c] * wf[c];
    sr[tid] = s;
    __syncthreads();
    for (int st = 128; st > 0; st >>= 1) {
        if (tid < st) sr[tid] += sr[tid + st];
        __syncthreads();
    }
    if (tid == 0) attfea[bt] = sr[0];
}

// softmax over t per batch row; aw is constant across all steps (shift invariance)
__global__ void aw_k(const float* __restrict__ attfea, float* __restrict__ aw,
                     float* __restrict__ out_aws)
{
    int b = threadIdx.x;
    if (b >= 2) return;
    float m = -1e30f;
    for (int t = 0; t < TSEG; t++) m = fmaxf(m, attfea[b * TSEG + t]);
    float sum = 0.f;
    for (int t = 0; t < TSEG; t++) sum += expf(attfea[b * TSEG + t] - m);
    for (int t = 0; t < TSEG; t++) {
        float a = expf(attfea[b * TSEG + t] - m) / sum;
        aw[b * TSEG + t] = a;
        out_aws[b * TSEG + t] = a;
    }
}

// gates0[b][oc][p] = lstm_b[oc] + sum_t aw[b][t]*Gx[bt][oc][p]
__global__ void ginit_k(const float* __restrict__ Gx, const float* __restrict__ aw,
                        const float* __restrict__ lstm_b, float* __restrict__ gates0)
{
    int i = blockIdx.x * blockDim.x + threadIdx.x;
    const int total = 2 * 2048 * PIX;
    if (i >= total) return;
    int p = i % PIX;
    int oc = (i / PIX) % 2048;
    int b = i / (PIX * 2048);
    float s = lstm_b[oc];
    for (int t = 0; t < TSEG; t++)
        s += aw[b * TSEG + t] * Gx[(((size_t)(b * TSEG + t)) * 2048 + oc) * PIX + p];
    gates0[i] = s;
}

// pointwise LSTM update + per-channel spatial mean; block (49,8), grid (2,64)
__global__ void lstm_point_k(const float* __restrict__ gates0, const float* __restrict__ part,
                             float* __restrict__ h, float* __restrict__ cst,
                             float* __restrict__ houts, int t)
{
    int b = blockIdx.x;
    int c = blockIdx.y * 8 + threadIdx.y;
    int p = threadIdx.x;
    size_t base = ((size_t)b * 2048) * PIX + p;
    float gi = gates0[base + (size_t)c * PIX];
    float gf = gates0[base + (size_t)(512 + c) * PIX];
    float go = gates0[base + (size_t)(1024 + c) * PIX];
    float gg = gates0[base + (size_t)(1536 + c) * PIX];
#pragma unroll
    for (int ks = 0; ks < 4; ks++) {
        size_t pb = ((size_t)(ks * 2 + b) * 2048) * PIX + p;
        gi += part[pb + (size_t)c * PIX];
        gf += part[pb + (size_t)(512 + c) * PIX];
        go += part[pb + (size_t)(1024 + c) * PIX];
        gg += part[pb + (size_t)(1536 + c) * PIX];
    }
    size_t hidx = ((size_t)b * 512 + c) * PIX + p;
    float cprev = cst[hidx];
    float si = 1.f / (1.f + expf(-gi));
    float sf = 1.f / (1.f + expf(-gf));
    float so = 1.f / (1.f + expf(-go));
    float c2 = sf * cprev + si * tanhf(gg);
    float h2 = so * tanhf(c2);
    cst[hidx] = c2;
    h[hidx] = h2;
    __shared__ float red[8][49];
    red[threadIdx.y][p] = h2;
    __syncthreads();
    if (p == 0) {
        float s = 0.f;
        for (int q = 0; q < 49; q++) s += red[threadIdx.y][q];
        houts[((size_t)t * 2 + b) * 512 + c] = s * (1.f / (float)PIX);
    }
}

__global__ void final_k(const float* __restrict__ houts, const float* __restrict__ fc_w,
                        const float* __restrict__ fc_b, float* __restrict__ out)
{
    __shared__ float om[1024];
    int tid = threadIdx.x;
    for (int i = tid; i < 1024; i += 512) {
        int b = i / 512, c = i - b * 512;
        float s = 0.f;
        for (int t = 0; t < TSEG; t++) s += houts[((size_t)t * 2 + b) * 512 + c];
        om[i] = s * (1.f / (float)TSEG);
    }
    __syncthreads();
    for (int i = tid; i < 202; i += 512) {
        int b = i / 101, k = i - b * 101;
        float s = fc_b[k];
        for (int c = 0; c < 512; c++) s += om[b * 512 + c] * fc_w[k * 512 + c];
        out[i] = s;
    }
    if (tid == 0) { out[2402] = 0.f; out[2403] = 0.f; }
}

// ===================== host orchestration =====================
static float* symaddr(const void* sym) {
    void* p = nullptr;
    cudaGetSymbolAddress(&p, sym);
    return (float*)p;
}

extern "C" void kernel_launch(void* const* d_in, const int* in_sizes, int n_in,
                              void* d_out, int out_size)
{
    const float* x      = (const float*)d_in[0];
    const float* wf     = (const float*)d_in[1];
    // wh = d_in[2] is mathematically dead (softmax shift invariance)
    const float* fc_w   = (const float*)d_in[3];
    const float* fc_b   = (const float*)d_in[4];
    const float* h0_w1  = (const float*)d_in[5];
    const float* h0_bn1 = (const float*)d_in[6];
    const float* h0_w2  = (const float*)d_in[7];
    const float* h0_bn2 = (const float*)d_in[8];
    const float* c0_w1  = (const float*)d_in[9];
    const float* c0_bn1 = (const float*)d_in[10];
    const float* c0_w2  = (const float*)d_in[11];
    const float* c0_bn2 = (const float*)d_in[12];
    const float* mk_w1  = (const float*)d_in[13];
    const float* mk_bn1 = (const float*)d_in[14];
    const float* mk_w2  = (const float*)d_in[15];
    const float* mk_bn2 = (const float*)d_in[16];
    const float* mk_w3  = (const float*)d_in[17];
    const float* lstm_w = (const float*)d_in[18];
    const float* lstm_b = (const float*)d_in[19];
    float* out = (float*)d_out;

    float* xt     = symaddr(g_xt);
    float* mx     = symaddr(g_mx);
    float* Gx     = symaddr(g_Gx);
    float* y1     = symaddr(g_y1);
    float* y2     = symaddr(g_y2);
    float* mask   = symaddr(g_mask);
    float* meanx  = symaddr(g_meanx);
    float* mxc    = symaddr(g_mxc);
    float* attfea = symaddr(g_attfea);
    float* aw     = symaddr(g_aw);
    float* tmp1   = symaddr(g_tmp1);
    float* h      = symaddr(g_h);
    float* cst    = symaddr(g_cst);
    float* gates0 = symaddr(g_gates0);
    float* part   = symaddr(g_part);
    float* houts  = symaddr(g_houts);

    dim3 cb(49, 8);
    const int ETOT = NBT * 2048 * PIX;

    // ---- mask path ----
    transpose_k<<<(ETOT + 255) / 256, 256>>>(x, xt);
    conv3x3_k<<<dim3(NBT, 16, 1), cb>>>(xt, mk_w1, mk_bn1, y1, 2048, 1024, 2048, 1, 1);
    conv3x3_k<<<dim3(NBT, 8, 1), cb>>>(y1, mk_w2, mk_bn2, y2, 1024, 512, 1024, 1, 1);
    mask_final_k<<<NBT, cb>>>(y2, mk_w3, mask, out + 246);   // mask region of output

    // ---- masked features, reductions, attention (constant over steps) ----
    mx_k<<<(ETOT + 255) / 256, 256>>>(xt, mask, mx);
    meanx_k<<<(2 * 2048 * PIX + 255) / 256, 256>>>(mx, meanx);
    mxc_k<<<(NBT * 2048 + 255) / 256, 256>>>(mx, mxc);
    attfea_k<<<NBT, 256>>>(mxc, wf, attfea);
    aw_k<<<1, 32>>>(attfea, aw, out + 202);                  // aws[-1] region of output

    // ---- Gx = conv_x(mx_t) with lstm_w[:, :2048] (hoisted out of the recurrence) ----
    conv3x3_k<<<dim3(NBT, 32, 1), cb>>>(mx, lstm_w, nullptr, Gx, 2048, 2048, 2560, 1, 0);

    // ---- h0 / c0 init (k-split for parallelism, deterministic partials) ----
    conv3x3_k<<<dim3(2, 16, 8), cb>>>(meanx, h0_w1, nullptr, part, 2048, 1024, 2048, 8, 0);
    finish_k<<<(2 * 1024 * PIX + 255) / 256, 256>>>(part, 8, 2 * 1024 * PIX, h0_bn1, tmp1, 1024, 2 * 1024 * PIX, 1);
    conv3x3_k<<<dim3(2, 8, 8), cb>>>(tmp1, h0_w2, nullptr, part, 1024, 512, 1024, 8, 0);
    finish_k<<<(2 * 512 * PIX + 255) / 256, 256>>>(part, 8, 2 * 512 * PIX, h0_bn2, h, 512, 2 * 512 * PIX, 1);

    conv3x3_k<<<dim3(2, 16, 8), cb>>>(meanx, c0_w1, nullptr, part, 2048, 1024, 2048, 8, 0);
    finish_k<<<(2 * 1024 * PIX + 255) / 256, 256>>>(part, 8, 2 * 1024 * PIX, c0_bn1, tmp1, 1024, 2 * 1024 * PIX, 1);
    conv3x3_k<<<dim3(2, 8, 8), cb>>>(tmp1, c0_w2, nullptr, part, 1024, 512, 1024, 8, 0);
    finish_k<<<(2 * 512 * PIX + 255) / 256, 256>>>(part, 8, 2 * 512 * PIX, c0_bn2, cst, 512, 2 * 512 * PIX, 1);

    // ---- constant part of gates: bias + sum_t aw[t]*Gx[t] ----
    ginit_k<<<(2 * 2048 * PIX + 255) / 256, 256>>>(Gx, aw, lstm_b, gates0);

    // ---- recurrence: only conv_h(h) (512ch) is sequential ----
    for (int t = 0; t < TSEG; t++) {
        conv3x3_k<<<dim3(2, 32, 4), cb>>>(h, lstm_w + (size_t)2048 * 9, nullptr, part,
                                          512, 2048, 2560, 4, 0);
        lstm_point_k<<<dim3(2, 64), cb>>>(gates0, part, h, cst, houts, t);
    }

    // ---- final mean over steps + FC, plus zero losses ----
    final_k<<<1, 512>>>(houts, fc_w, fc_b, out);
}

// round 6
// speedup vs baseline: 1.0066x; 1.0066x over previous
#include <cuda_runtime.h>

// ===================== problem constants =====================
#define TSEG 22
#define NBT  44            // B*T = 2*22
#define PIX  49            // 7*7

// ===================== scratch (static device memory) =====================
__device__ float g_xt[(size_t)NBT * 2048 * PIX];      // (bt, c, p)
__device__ float g_mx[(size_t)NBT * 2048 * PIX];      // masked x
__device__ float g_Gx[(size_t)NBT * 2048 * PIX];      // conv_x(mx_t) with lstm_w x-part
__device__ float g_y1[(size_t)NBT * 1024 * PIX];
__device__ float g_y2[(size_t)NBT * 512 * PIX];
__device__ float g_mask[NBT * PIX];
__device__ float g_meanx[2 * 2048 * PIX];
__device__ float g_mxc[NBT * 2048];
__device__ float g_attfea[NBT];
__device__ float g_aw[NBT];
__device__ float g_tmp1[2 * 1024 * PIX];
__device__ float g_h[2 * 512 * PIX];
__device__ float g_cst[2 * 512 * PIX];
__device__ float g_gates0[2 * 2048 * PIX];
__device__ float g_part[(size_t)8 * 2 * 2048 * PIX];  // ksplit partials
__device__ float g_houts[TSEG * 2 * 512];

// ===================== f32x2 helpers =====================
__device__ __forceinline__ void fma2(unsigned long long &d, unsigned long long a, unsigned long long b) {
    asm("fma.rn.f32x2 %0, %1, %2, %3;" : "=l"(d) : "l"(a), "l"(b), "l"(d));
}
__device__ __forceinline__ unsigned long long pack2(float x) {
    unsigned long long r;
    asm("mov.b64 %0, {%1, %1};" : "=l"(r) : "f"(x));
    return r;
}
__device__ __forceinline__ float2 unpack2(unsigned long long v) {
    float2 f;
    asm("mov.b64 {%0, %1}, %2;" : "=f"(f.x), "=f"(f.y) : "l"(v));
    return f;
}

// ===================== generic 3x3 SAME conv on 7x7, NCHW =====================
// grid: (N, OC/64, nsplit); block: (49, 8)
// in: (N, IC, 49)  wt: (OC, wstride, 3, 3) using ic range [ic0, ic0+IC/nsplit)
// nsplit==1: writes final (postop==1 -> BN+ReLU) at out[(n*OC+oc)*49+p]
// nsplit>1 : writes raw partial at out[((ks*N+n)*OC+oc)*49+p]
#define OCT 64
#define ICC 8
__global__ __launch_bounds__(392) void conv3x3_k(
    const float* __restrict__ in, const float* __restrict__ wt,
    const float* __restrict__ bn, float* __restrict__ out,
    int IC, int OC, int wstride, int nsplit, int postop)
{
    int n = blockIdx.x;
    int N = gridDim.x;
    int ocbase = blockIdx.y * OCT;
    int ks = blockIdx.z;
    int icn = IC / nsplit;
    int ic0 = ks * icn;
    int p = threadIdx.x;          // 0..48
    int j = threadIdx.y;          // 0..7
    int tid = j * 49 + p;

    __shared__ __align__(16) float s_in[ICC][52];
    __shared__ __align__(16) float s_w[ICC * 9][OCT + 4];   // row stride 68 floats (16B aligned)

    int oh = p / 7, ow = p - oh * 7;
    int off[9]; float vmsk[9];
#pragma unroll
    for (int kh = 0; kh < 3; kh++)
#pragma unroll
        for (int kw = 0; kw < 3; kw++) {
            int ih = oh + kh - 1, iw = ow + kw - 1;
            int k = kh * 3 + kw;
            bool v = (ih >= 0) && (ih < 7) && (iw >= 0) && (iw < 7);
            vmsk[k] = v ? 1.f : 0.f;
            off[k] = v ? (ih * 7 + iw) : 0;
        }

    unsigned long long acc2[4] = {0ull, 0ull, 0ull, 0ull};
    const float* inN = in + ((size_t)n * IC + ic0) * PIX;

    for (int icb = 0; icb < icn; icb += ICC) {
        __syncthreads();
        {   // input chunk: exactly one element per thread (8*49 = 392)
            int ci = tid / 49, pp = tid - ci * 49;
            s_in[ci][pp] = inN[(size_t)(icb + ci) * PIX + pp];
        }
        // weights: 64*8*9 = 4608 elements; k fastest -> contiguous gmem reads
        for (int t = tid; t < OCT * ICC * 9; t += 392) {
            int ocl = t / (ICC * 9);
            int rem = t - ocl * (ICC * 9);      // = ci*9 + k
            s_w[rem][ocl] = wt[((size_t)(ocbase + ocl) * wstride + ic0 + icb) * 9 + rem];
        }
        __syncthreads();
#pragma unroll
        for (int ci = 0; ci < ICC; ci++) {
            float v[9];
#pragma unroll
            for (int k = 0; k < 9; k++) v[k] = s_in[ci][off[k]] * vmsk[k];
#pragma unroll
            for (int k = 0; k < 9; k++) {
                unsigned long long vv = pack2(v[k]);
                const ulonglong2* wr = (const ulonglong2*)&s_w[ci * 9 + k][j * 8];
                ulonglong2 wA = wr[0];
                ulonglong2 wB = wr[1];
                fma2(acc2[0], vv, wA.x);
                fma2(acc2[1], vv, wA.y);
                fma2(acc2[2], vv, wB.x);
                fma2(acc2[3], vv, wB.y);
            }
        }
    }

    float accf[8];
#pragma unroll
    for (int q = 0; q < 4; q++) { float2 f = unpack2(acc2[q]); accf[2 * q] = f.x; accf[2 * q + 1] = f.y; }

#pragma unroll
    for (int r = 0; r < 8; r++) {
        int oc = ocbase + j * 8 + r;
        float val = accf[r];
        if (nsplit == 1) {
            if (postop == 1) {
                float gg = bn[oc], bb = bn[OC + oc], mm = bn[2 * OC + oc], vv = bn[3 * OC + oc];
                val = (val - mm) * gg * rsqrtf(vv + 1e-5f) + bb;
                val = fmaxf(val, 0.f);
            }
            out[((size_t)n * OC + oc) * PIX + p] = val;
        } else {
            out[((size_t)(ks * N + n) * OC + oc) * PIX + p] = val;
        }
    }
}

// sum ksplit partials, optional BN+ReLU
__global__ void finish_k(const float* __restrict__ part, int nsplit, int chunk,
                         const float* __restrict__ bn, float* __restrict__ out,
                         int OC, int total, int postop)
{
    int i = blockIdx.x * blockDim.x + threadIdx.x;
    if (i >= total) return;
    float s = 0.f;
    for (int ks = 0; ks < nsplit; ks++) s += part[(size_t)ks * chunk + i];
    if (postop == 1) {
        int oc = (i / PIX) % OC;
        float g = bn[oc], b = bn[OC + oc], m = bn[2 * OC + oc], v = bn[3 * OC + oc];
        s = (s - m) * g * rsqrtf(v + 1e-5f) + b;
        s = fmaxf(s, 0.f);
    }
    out[i] = s;
}

// ===================== small kernels =====================
__global__ void transpose_k(const float* __restrict__ x, float* __restrict__ xt) {
    int i = blockIdx.x * blockDim.x + threadIdx.x;
    const int total = NBT * 2048 * PIX;
    if (i >= total) return;
    int p = i % PIX;
    int c = (i / PIX) % 2048;
    int bt = i / (PIX * 2048);
    int b = bt / TSEG, t = bt - b * TSEG;
    xt[i] = x[(((size_t)b * 2048 + c) * TSEG + t) * PIX + p];
}

__global__ void mask_final_k(const float* __restrict__ y2, const float* __restrict__ w3,
                             float* __restrict__ mask, float* __restrict__ outmask)
{
    int n = blockIdx.x;
    int p = threadIdx.x, g = threadIdx.y;
    int oh = p / 7, ow = p - oh * 7;
    float s = 0.f;
    for (int ic = g; ic < 512; ic += 8) {
        const float* row = y2 + ((size_t)n * 512 + ic) * PIX;
        const float* wr = w3 + ic * 9;
#pragma unroll
        for (int kh = 0; kh < 3; kh++)
#pragma unroll
            for (int kw = 0; kw < 3; kw++) {
                int ih = oh + kh - 1, iw = ow + kw - 1;
                if (ih >= 0 && ih < 7 && iw >= 0 && iw < 7)
                    s += row[ih * 7 + iw] * wr[kh * 3 + kw];
            }
    }
    __shared__ float red[8][49];
    red[g][p] = s;
    __syncthreads();
    if (g == 0) {
        float tot = 0.f;
#pragma unroll
        for (int q = 0; q < 8; q++) tot += red[q][p];
        float m = 1.f / (1.f + expf(-tot));
        mask[n * PIX + p] = m;
        outmask[n * PIX + p] = m;
    }
}

__global__ void mx_k(const float* __restrict__ xt, const float* __restrict__ mask, float* __restrict__ mx) {
    int i = blockIdx.x * blockDim.x + threadIdx.x;
    const int total = NBT * 2048 * PIX;
    if (i >= total) return;
    int p = i % PIX;
    int bt = i / (PIX * 2048);
    mx[i] = xt[i] * mask[bt * PIX + p];
}

__global__ void meanx_k(const float* __restrict__ mx, float* __restrict__ meanx) {
    int i = blockIdx.x * blockDim.x + threadIdx.x;
    const int inner = 2048 * PIX;
    if (i >= 2 * inner) return;
    int b = i / inner, r = i - b * inner;
    float s = 0.f;
    for (int t = 0; t < TSEG; t++) s += mx[((size_t)(b * TSEG + t)) * inner + r];
    meanx[i] = s * (1.f / (float)TSEG);
}

__global__ void mxc_k(const float* __restrict__ mx, float* __restrict__ mxc) {
    int i = blockIdx.x * blockDim.x + threadIdx.x;
    if (i >= NBT * 2048) return;
    const float* row = mx + (size_t)i * PIX;
    float s = 0.f;
    for (int p = 0; p < PIX; p++) s += row[p];
    mxc[i] = s * (1.f / (float)PIX);
}

__global__ void attfea_k(const float* __restrict__ mxc, const float* __restrict__ wf,
                         float* __restrict__ attfea)
{
    int bt = blockIdx.x;
    int tid = threadIdx.x;
    __shared__ float sr[256];
    float s = 0.f;
    for (int c = tid; c < 2048; c += 256) s += mxc[bt * 2048 + c] * wf[c];
    sr[tid] = s;
    __syncthreads();
    for (int st = 128; st > 0; st >>= 1) {
        if (tid < st) sr[tid] += sr[tid + st];
        __syncthreads();
    }
    if (tid == 0) attfea[bt] = sr[0];
}

// softmax over t per batch row; aw is constant across all steps (shift invariance)
__global__ void aw_k(const float* __restrict__ attfea, float* __restrict__ aw,
                     float* __restrict__ out_aws)
{
    int b = threadIdx.x;
    if (b >= 2) return;
    float m = -1e30f;
    for (int t = 0; t < TSEG; t++) m = fmaxf(m, attfea[b * TSEG + t]);
    float sum = 0.f;
    for (int t = 0; t < TSEG; t++) sum += expf(attfea[b * TSEG + t] - m);
    for (int t = 0; t < TSEG; t++) {
        float a = expf(attfea[b * TSEG + t] - m) / sum;
        aw[b * TSEG + t] = a;
        out_aws[b * TSEG + t] = a;
    }
}

// gates0[b][oc][p] = lstm_b[oc] + sum_t aw[b][t]*Gx[bt][oc][p]
__global__ void ginit_k(const float* __restrict__ Gx, const float* __restrict__ aw,
                        const float* __restrict__ lstm_b, float* __restrict__ gates0)
{
    int i = blockIdx.x * blockDim.x + threadIdx.x;
    const int total = 2 * 2048 * PIX;
    if (i >= total) return;
    int p = i % PIX;
    int oc = (i / PIX) % 2048;
    int b = i / (PIX * 2048);
    float s = lstm_b[oc];
    for (int t = 0; t < TSEG; t++)
        s += aw[b * TSEG + t] * Gx[(((size_t)(b * TSEG + t)) * 2048 + oc) * PIX + p];
    gates0[i] = s;
}

// pointwise LSTM update + per-channel spatial mean; block (49,8), grid (2,64)
__global__ void lstm_point_k(const float* __restrict__ gates0, const float* __restrict__ part,
                             float* __restrict__ h, float* __restrict__ cst,
                             float* __restrict__ houts, int t)
{
    int b = blockIdx.x;
    int c = blockIdx.y * 8 + threadIdx.y;
    int p = threadIdx.x;
    size_t base = ((size_t)b * 2048) * PIX + p;
    float gi = gates0[base + (size_t)c * PIX];
    float gf = gates0[base + (size_t)(512 + c) * PIX];
    float go = gates0[base + (size_t)(1024 + c) * PIX];
    float gg = gates0[base + (size_t)(1536 + c) * PIX];
#pragma unroll
    for (int ks = 0; ks < 4; ks++) {
        size_t pb = ((size_t)(ks * 2 + b) * 2048) * PIX + p;
        gi += part[pb + (size_t)c * PIX];
        gf += part[pb + (size_t)(512 + c) * PIX];
        go += part[pb + (size_t)(1024 + c) * PIX];
        gg += part[pb + (size_t)(1536 + c) * PIX];
    }
    size_t hidx = ((size_t)b * 512 + c) * PIX + p;
    float cprev = cst[hidx];
    float si = 1.f / (1.f + expf(-gi));
    float sf = 1.f / (1.f + expf(-gf));
    float so = 1.f / (1.f + expf(-go));
    float c2 = sf * cprev + si * tanhf(gg);
    float h2 = so * tanhf(c2);
    cst[hidx] = c2;
    h[hidx] = h2;
    __shared__ float red[8][49];
    red[threadIdx.y][p] = h2;
    __syncthreads();
    if (p == 0) {
        float s = 0.f;
        for (int q = 0; q < 49; q++) s += red[threadIdx.y][q];
        houts[((size_t)t * 2 + b) * 512 + c] = s * (1.f / (float)PIX);
    }
}

__global__ void final_k(const float* __restrict__ houts, const float* __restrict__ fc_w,
                        const float* __restrict__ fc_b, float* __restrict__ out)
{
    __shared__ float om[1024];
    int tid = threadIdx.x;
    for (int i = tid; i < 1024; i += 512) {
        int b = i / 512, c = i - b * 512;
        float s = 0.f;
        for (int t = 0; t < TSEG; t++) s += houts[((size_t)t * 2 + b) * 512 + c];
        om[i] = s * (1.f / (float)TSEG);
    }
    __syncthreads();
    for (int i = tid; i < 202; i += 512) {
        int b = i / 101, k = i - b * 101;
        float s = fc_b[k];
        for (int c = 0; c < 512; c++) s += om[b * 512 + c] * fc_w[k * 512 + c];
        out[i] = s;
    }
    if (tid == 0) { out[2402] = 0.f; out[2403] = 0.f; }
}

// ===================== host orchestration =====================
static float* symaddr(const void* sym) {
    void* p = nullptr;
    cudaGetSymbolAddress(&p, sym);
    return (float*)p;
}

extern "C" void kernel_launch(void* const* d_in, const int* in_sizes, int n_in,
                              void* d_out, int out_size)
{
    const float* x      = (const float*)d_in[0];
    const float* wf     = (const float*)d_in[1];
    // wh = d_in[2] is mathematically dead (softmax shift invariance)
    const float* fc_w   = (const float*)d_in[3];
    const float* fc_b   = (const float*)d_in[4];
    const float* h0_w1  = (const float*)d_in[5];
    const float* h0_bn1 = (const float*)d_in[6];
    const float* h0_w2  = (const float*)d_in[7];
    const float* h0_bn2 = (const float*)d_in[8];
    const float* c0_w1  = (const float*)d_in[9];
    const float* c0_bn1 = (const float*)d_in[10];
    const float* c0_w2  = (const float*)d_in[11];
    const float* c0_bn2 = (const float*)d_in[12];
    const float* mk_w1  = (const float*)d_in[13];
    const float* mk_bn1 = (const float*)d_in[14];
    const float* mk_w2  = (const float*)d_in[15];
    const float* mk_bn2 = (const float*)d_in[16];
    const float* mk_w3  = (const float*)d_in[17];
    const float* lstm_w = (const float*)d_in[18];
    const float* lstm_b = (const float*)d_in[19];
    float* out = (float*)d_out;

    float* xt     = symaddr(g_xt);
    float* mx     = symaddr(g_mx);
    float* Gx     = symaddr(g_Gx);
    float* y1     = symaddr(g_y1);
    float* y2     = symaddr(g_y2);
    float* mask   = symaddr(g_mask);
    float* meanx  = symaddr(g_meanx);
    float* mxc    = symaddr(g_mxc);
    float* attfea = symaddr(g_attfea);
    float* aw     = symaddr(g_aw);
    float* tmp1   = symaddr(g_tmp1);
    float* h      = symaddr(g_h);
    float* cst    = symaddr(g_cst);
    float* gates0 = symaddr(g_gates0);
    float* part   = symaddr(g_part);
    float* houts  = symaddr(g_houts);

    dim3 cb(49, 8);
    const int ETOT = NBT * 2048 * PIX;

    // ---- mask path ----
    transpose_k<<<(ETOT + 255) / 256, 256>>>(x, xt);
    conv3x3_k<<<dim3(NBT, 16, 1), cb>>>(xt, mk_w1, mk_bn1, y1, 2048, 1024, 2048, 1, 1);
    conv3x3_k<<<dim3(NBT, 8, 1), cb>>>(y1, mk_w2, mk_bn2, y2, 1024, 512, 1024, 1, 1);
    mask_final_k<<<NBT, cb>>>(y2, mk_w3, mask, out + 246);   // mask region of output

    // ---- masked features, reductions, attention (constant over steps) ----
    mx_k<<<(ETOT + 255) / 256, 256>>>(xt, mask, mx);
    meanx_k<<<(2 * 2048 * PIX + 255) / 256, 256>>>(mx, meanx);
    mxc_k<<<(NBT * 2048 + 255) / 256, 256>>>(mx, mxc);
    attfea_k<<<NBT, 256>>>(mxc, wf, attfea);
    aw_k<<<1, 32>>>(attfea, aw, out + 202);                  // aws[-1] region of output

    // ---- Gx = conv_x(mx_t) with lstm_w[:, :2048] (hoisted out of the recurrence) ----
    conv3x3_k<<<dim3(NBT, 32, 1), cb>>>(mx, lstm_w, nullptr, Gx, 2048, 2048, 2560, 1, 0);

    // ---- h0 / c0 init (k-split for parallelism, deterministic partials) ----
    conv3x3_k<<<dim3(2, 16, 8), cb>>>(meanx, h0_w1, nullptr, part, 2048, 1024, 2048, 8, 0);
    finish_k<<<(2 * 1024 * PIX + 255) / 256, 256>>>(part, 8, 2 * 1024 * PIX, h0_bn1, tmp1, 1024, 2 * 1024 * PIX, 1);
    conv3x3_k<<<dim3(2, 8, 8), cb>>>(tmp1, h0_w2, nullptr, part, 1024, 512, 1024, 8, 0);
    finish_k<<<(2 * 512 * PIX + 255) / 256, 256>>>(part, 8, 2 * 512 * PIX, h0_bn2, h, 512, 2 * 512 * PIX, 1);

    conv3x3_k<<<dim3(2, 16, 8), cb>>>(meanx, c0_w1, nullptr, part, 2048, 1024, 2048, 8, 0);
    finish_k<<<(2 * 1024 * PIX + 255) / 256, 256>>>(part, 8, 2 * 1024 * PIX, c0_bn1, tmp1, 1024, 2 * 1024 * PIX, 1);
    conv3x3_k<<<dim3(2, 8, 8), cb>>>(tmp1, c0_w2, nullptr, part, 1024, 512, 1024, 8, 0);
    finish_k<<<(2 * 512 * PIX + 255) / 256, 256>>>(part, 8, 2 * 512 * PIX, c0_bn2, cst, 512, 2 * 512 * PIX, 1);

    // ---- constant part of gates: bias + sum_t aw[t]*Gx[t] ----
    ginit_k<<<(2 * 2048 * PIX + 255) / 256, 256>>>(Gx, aw, lstm_b, gates0);

    // ---- recurrence: only conv_h(h) (512ch) is sequential ----
    for (int t = 0; t < TSEG; t++) {
        conv3x3_k<<<dim3(2, 32, 4), cb>>>(h, lstm_w + (size_t)2048 * 9, nullptr, part,
                                          512, 2048, 2560, 4, 0);
        lstm_point_k<<<dim3(2, 64), cb>>>(gates0, part, h, cst, houts, t);
    }

    // ---- final mean over steps + FC, plus zero losses ----
    final_k<<<1, 512>>>(houts, fc_w, fc_b, out);
}

// round 8
// speedup vs baseline: 6.3846x; 6.3426x over previous
#include <cuda_runtime.h>
#include <cuda_bf16.h>
#include <cstdint>

// ===================== problem constants =====================
#define TSEG 22
#define NBT  44
#define PIX  49
#define K18  18432     // 9*2048
#define K9   9216      // 9*1024
#define K45  4608      // 9*512
#define AM   2176      // 17*128 pad of 2156

// ===================== fp32 scratch =====================
__device__ float g_xt[(size_t)NBT * 2048 * PIX];
__device__ float g_mx[(size_t)NBT * 2048 * PIX];
__device__ float g_Gx[(size_t)NBT * 2048 * PIX];
__device__ float g_y1[(size_t)NBT * 1024 * PIX];
__device__ float g_y2[(size_t)NBT * 512 * PIX];
__device__ float g_mask[NBT * PIX];
__device__ float g_meanx[2 * 2048 * PIX];
__device__ float g_mxc[NBT * 2048];
__device__ float g_attfea[NBT];
__device__ float g_aw[NBT];
__device__ float g_h[2 * 512 * PIX];
__device__ float g_cst[2 * 512 * PIX];
__device__ float g_gates0[2 * 2048 * PIX];
__device__ float g_part[(size_t)8 * 2 * 2048 * PIX];
__device__ float g_houts[TSEG * 2 * 512];
__device__ float g_tmphc[2 * 2048 * PIX];
__device__ float g_bnc1[4 * 2048];

// ===================== split-bf16 buffers =====================
__device__ __nv_bfloat16 g_axt_h[(size_t)AM * K18],  g_axt_l[(size_t)AM * K18];
__device__ __nv_bfloat16 g_amx_h[(size_t)AM * K18],  g_amx_l[(size_t)AM * K18];
__device__ __nv_bfloat16 g_ay1_h[(size_t)AM * K9],   g_ay1_l[(size_t)AM * K9];
__device__ __nv_bfloat16 g_sa_h[(size_t)128 * K18],  g_sa_l[(size_t)128 * K18];
__device__ __nv_bfloat16 g_wmk1_h[(size_t)1024 * K18], g_wmk1_l[(size_t)1024 * K18];
__device__ __nv_bfloat16 g_wmk2_h[(size_t)512 * K9],   g_wmk2_l[(size_t)512 * K9];
__device__ __nv_bfloat16 g_wgx_h[(size_t)2048 * K18],  g_wgx_l[(size_t)2048 * K18];
__device__ __nv_bfloat16 g_whc1_h[(size_t)2048 * K18], g_whc1_l[(size_t)2048 * K18];
__device__ __nv_bfloat16 g_w2h_h[(size_t)512 * K9],    g_w2h_l[(size_t)512 * K9];
__device__ __nv_bfloat16 g_w2c_h[(size_t)512 * K9],    g_w2c_l[(size_t)512 * K9];
__device__ __nv_bfloat16 g_wlh_h[(size_t)2048 * K45],  g_wlh_l[(size_t)2048 * K45];

// ===================== base-ISA tensor helpers (sm_80+) =====================
__device__ __forceinline__ uint32_t smem_u32(const void* p) {
    uint32_t a;
    asm("{ .reg .u64 t; cvta.to.shared.u64 t, %1; cvt.u32.u64 %0, t; }" : "=r"(a) : "l"(p));
    return a;
}
__device__ __forceinline__ void ldsm4(uint32_t* r, uint32_t addr) {
    asm volatile("ldmatrix.sync.aligned.m8n8.x4.shared.b16 {%0,%1,%2,%3}, [%4];"
        : "=r"(r[0]), "=r"(r[1]), "=r"(r[2]), "=r"(r[3]) : "r"(addr));
}
__device__ __forceinline__ void mma16816(float* d, const uint32_t* a, const uint32_t* b) {
    asm volatile(
        "mma.sync.aligned.m16n8k16.row.col.f32.bf16.bf16.f32 "
        "{%0,%1,%2,%3}, {%4,%5,%6,%7}, {%8,%9}, {%0,%1,%2,%3};"
        : "+f"(d[0]), "+f"(d[1]), "+f"(d[2]), "+f"(d[3])
        : "r"(a[0]), "r"(a[1]), "r"(a[2]), "r"(a[3]), "r"(b[0]), "r"(b[1]));
}
#define CP_COMMIT() asm volatile("cp.async.commit_group;" ::: "memory")

// ===================== split-bf16 mma.sync GEMM =====================
// D(MxN) = (Ahi+Alo)(MxK) @ (Bhi+Blo)(NxK)^T, fp32 accum.
// grid (N/128, ceil(M/128), ksplit), block 256 (8 warps, 2x4 -> 64x32/warp).
// K-chunk 64 (128B rows, XOR-16B swizzle), 3-stage cp.async ring.
#define GEMM_SMEM (3 * 65536)
__global__ void __launch_bounds__(256, 1) gemm_mma_k(
    const __nv_bfloat16* __restrict__ Ahi, const __nv_bfloat16* __restrict__ Alo,
    const __nv_bfloat16* __restrict__ Bhi, const __nv_bfloat16* __restrict__ Blo,
    float* __restrict__ outp, int K, int Ktile, int Mreal, int OCtot,
    const float* __restrict__ bn, int postop, long long partChunk)
{
    extern __shared__ char dsm[];           // 3 stages x (Ah|Al|Bh|Bl) x 16KB
    __shared__ float s_sc[128], s_sh[128];

    int tid = threadIdx.x, lane = tid & 31, wid = tid >> 5;
    int wm = wid & 1, wn = wid >> 1;
    uint32_t sbase = smem_u32(dsm);

    int n0 = blockIdx.x * 128;
    int m0 = blockIdx.y * 128;
    long long kc0 = (long long)blockIdx.z * Ktile;
    int nChunks = Ktile / 64;

    // producer role: 64 threads per matrix
    int mytile = tid >> 6, tt = tid & 63;
    const __nv_bfloat16* mysrc =
        (mytile == 0) ? Ahi + (size_t)m0 * K + kc0 :
        (mytile == 1) ? Alo + (size_t)m0 * K + kc0 :
        (mytile == 2) ? Bhi + (size_t)n0 * K + kc0 :
                        Blo + (size_t)n0 * K + kc0;

    auto load_chunk = [&](int c, int stg) {
        const __nv_bfloat16* src = mysrc + (size_t)c * 64;
        uint32_t dbase = sbase + (uint32_t)stg * 65536u + (uint32_t)mytile * 16384u;
#pragma unroll
        for (int j = 0; j < 16; j++) {
            int idx = tt + j * 64;
            int r = idx >> 3, cs = idx & 7;
            const void* g = src + (size_t)r * K + cs * 8;
            uint32_t so = dbase + (uint32_t)(r * 128 + ((cs * 16) ^ ((r & 7) * 16)));
            asm volatile("cp.async.cg.shared.global [%0], [%1], 16;" :: "r"(so), "l"(g));
        }
    };

    float d[4][4][4];
#pragma unroll
    for (int a = 0; a < 4; a++)
#pragma unroll
        for (int b = 0; b < 4; b++)
#pragma unroll
            for (int c = 0; c < 4; c++) d[a][b][c] = 0.f;

    // prologue: prefetch 2 chunks
    if (nChunks > 0) { load_chunk(0, 0); CP_COMMIT(); }
    if (nChunks > 1) { load_chunk(1, 1); CP_COMMIT(); }

    for (int c = 0; c < nChunks; c++) {
        if (c + 1 < nChunks) asm volatile("cp.async.wait_group 1;" ::: "memory");
        else                 asm volatile("cp.async.wait_group 0;" ::: "memory");
        __syncthreads();
        if (c + 2 < nChunks) { load_chunk(c + 2, (c + 2) % 3); CP_COMMIT(); }

        int stg = c % 3;
        uint32_t sAh = sbase + (uint32_t)stg * 65536u;
        uint32_t sAl = sAh + 16384u;
        uint32_t sBh = sAh + 32768u;
        uint32_t sBl = sAh + 49152u;

#pragma unroll
        for (int k16 = 0; k16 < 4; k16++) {
            uint32_t ah[4][4], al[4][4], bh[4][2], bl[4][2];
#pragma unroll
            for (int mt = 0; mt < 4; mt++) {
                uint32_t r = (uint32_t)(wm * 64 + mt * 16 + (lane & 15));
                uint32_t cby = (uint32_t)(k16 * 32 + ((lane >> 4) << 4));
                uint32_t off = r * 128 + (cby ^ ((r & 7) << 4));
                ldsm4(ah[mt], sAh + off);
                ldsm4(al[mt], sAl + off);
            }
#pragma unroll
            for (int p = 0; p < 2; p++) {
                uint32_t r = (uint32_t)(wn * 32 + p * 16 + (((lane >> 4) & 1) << 3) + (lane & 7));
                uint32_t cby = (uint32_t)(k16 * 32 + (((lane >> 3) & 1) << 4));
                uint32_t off = r * 128 + (cby ^ ((r & 7) << 4));
                uint32_t t4[4];
                ldsm4(t4, sBh + off);
                bh[2 * p][0] = t4[0]; bh[2 * p][1] = t4[1];
                bh[2 * p + 1][0] = t4[2]; bh[2 * p + 1][1] = t4[3];
                ldsm4(t4, sBl + off);
                bl[2 * p][0] = t4[0]; bl[2 * p][1] = t4[1];
                bl[2 * p + 1][0] = t4[2]; bl[2 * p + 1][1] = t4[3];
            }
#pragma unroll
            for (int mt = 0; mt < 4; mt++)
#pragma unroll
                for (int nt = 0; nt < 4; nt++) {
                    mma16816(d[mt][nt], ah[mt], bh[nt]);
                    mma16816(d[mt][nt], ah[mt], bl[nt]);
                    mma16816(d[mt][nt], al[mt], bh[nt]);
                }
        }
        __syncthreads();
    }

    // epilogue: optional BN+ReLU, scattered NCHW write
    if (postop == 1 && tid < 128) {
        int oc = n0 + tid;
        float g = bn[oc], b = bn[OCtot + oc], m = bn[2 * OCtot + oc], v = bn[3 * OCtot + oc];
        float sc = g * rsqrtf(v + 1e-5f);
        s_sc[tid] = sc;
        s_sh[tid] = b - m * sc;
    }
    __syncthreads();

    float* obase0 = outp + (size_t)blockIdx.z * partChunk;
#pragma unroll
    for (int mt = 0; mt < 4; mt++) {
#pragma unroll
        for (int nt = 0; nt < 4; nt++) {
            int ln = wn * 32 + nt * 8 + 2 * (lane & 3);
            int r0 = m0 + wm * 64 + mt * 16 + (lane >> 2);
#pragma unroll
            for (int half = 0; half < 2; half++) {
                int mrow = r0 + half * 8;
                if (mrow < Mreal) {
                    int img = mrow / 49, p = mrow - img * 49;
                    float* ob = obase0 + ((size_t)img * OCtot + n0) * 49 + p;
                    float v0 = d[mt][nt][half * 2 + 0];
                    float v1 = d[mt][nt][half * 2 + 1];
                    if (postop) {
                        v0 = fmaxf(v0 * s_sc[ln] + s_sh[ln], 0.f);
                        v1 = fmaxf(v1 * s_sc[ln + 1] + s_sh[ln + 1], 0.f);
                    }
                    ob[(size_t)ln * 49] = v0;
                    ob[(size_t)(ln + 1) * 49] = v1;
                }
            }
        }
    }
}

// ===================== im2col (fp32 -> split bf16), k = kk*IC + ic =====================
__global__ void im2col_k(const float* __restrict__ in, int CHtot, int c0, int IC, int nRows,
                         __nv_bfloat16* __restrict__ hi, __nv_bfloat16* __restrict__ lo)
{
    int ICp = IC >> 1;
    long long idx = (long long)blockIdx.x * blockDim.x + threadIdx.x;
    long long tot = (long long)nRows * 9 * ICp;
    if (idx >= tot) return;
    int icp = (int)(idx % ICp);
    long long r2 = idx / ICp;
    int kk = (int)(r2 % 9);
    int row = (int)(r2 / 9);
    int img = row / 49, p = row - img * 49;
    int oh = p / 7, ow = p - oh * 7;
    int kh = kk / 3, kw = kk - kh * 3;
    int ih = oh + kh - 1, iw = ow + kw - 1;
    bool valid = (ih >= 0) && (ih < 7) && (iw >= 0) && (iw < 7);
    int q = valid ? (ih * 7 + iw) : 0;
    int ic = icp * 2;
    const float* base = in + ((size_t)img * CHtot + c0 + ic) * PIX + q;
    float v0 = valid ? base[0] : 0.f;
    float v1 = valid ? base[PIX] : 0.f;
    __nv_bfloat16 h0 = __float2bfloat16(v0);
    __nv_bfloat16 h1 = __float2bfloat16(v1);
    __nv_bfloat16 l0 = __float2bfloat16(v0 - __bfloat162float(h0));
    __nv_bfloat16 l1 = __float2bfloat16(v1 - __bfloat162float(h1));
    size_t o = (size_t)row * (IC * 9) + (size_t)kk * IC + ic;
    __nv_bfloat162 hh; hh.x = h0; hh.y = h1;
    __nv_bfloat162 ll; ll.x = l0; ll.y = l1;
    *(__nv_bfloat162*)(hi + o) = hh;
    *(__nv_bfloat162*)(lo + o) = ll;
}

// weight repack: dst[oc][kk*IC+ic] = src[(oc*srcStride + c0 + ic)*9 + kk], split bf16
__global__ void repack_k(const float* __restrict__ src, int srcStride, int c0, int IC, int OC,
                         __nv_bfloat16* __restrict__ hi, __nv_bfloat16* __restrict__ lo)
{
    int ICp = IC >> 1;
    long long idx = (long long)blockIdx.x * blockDim.x + threadIdx.x;
    long long tot = (long long)OC * 9 * ICp;
    if (idx >= tot) return;
    int icp = (int)(idx % ICp);
    long long r2 = idx / ICp;
    int kk = (int)(r2 % 9);
    int oc = (int)(r2 / 9);
    int ic = icp * 2;
    const float* b = src + ((size_t)oc * srcStride + c0 + ic) * 9 + kk;
    float v0 = b[0], v1 = b[9];
    __nv_bfloat16 h0 = __float2bfloat16(v0);
    __nv_bfloat16 h1 = __float2bfloat16(v1);
    __nv_bfloat16 l0 = __float2bfloat16(v0 - __bfloat162float(h0));
    __nv_bfloat16 l1 = __float2bfloat16(v1 - __bfloat162float(h1));
    size_t o = (size_t)oc * (IC * 9) + (size_t)kk * IC + ic;
    __nv_bfloat162 hh; hh.x = h0; hh.y = h1;
    __nv_bfloat162 ll; ll.x = l0; ll.y = l1;
    *(__nv_bfloat162*)(hi + o) = hh;
    *(__nv_bfloat162*)(lo + o) = ll;
}

__global__ void bnconcat_k(const float* __restrict__ a, const float* __restrict__ b,
                           float* __restrict__ dst)
{
    int i = blockIdx.x * blockDim.x + threadIdx.x;
    if (i >= 4 * 2048) return;
    int pr = i / 2048, j = i - pr * 2048;
    dst[i] = (j < 1024) ? a[pr * 1024 + j] : b[pr * 1024 + (j - 1024)];
}

// ===================== small kernels (unchanged from passing baseline) ==============
__global__ void finish_k(const float* __restrict__ part, int nsplit, int chunk,
                         const float* __restrict__ bn, float* __restrict__ out,
                         int OC, int total, int postop)
{
    int i = blockIdx.x * blockDim.x + threadIdx.x;
    if (i >= total) return;
    float s = 0.f;
    for (int ks = 0; ks < nsplit; ks++) s += part[(size_t)ks * chunk + i];
    if (postop == 1) {
        int oc = (i / PIX) % OC;
        float g = bn[oc], b = bn[OC + oc], m = bn[2 * OC + oc], v = bn[3 * OC + oc];
        s = (s - m) * g * rsqrtf(v + 1e-5f) + b;
        s = fmaxf(s, 0.f);
    }
    out[i] = s;
}

__global__ void transpose_k(const float* __restrict__ x, float* __restrict__ xt) {
    int i = blockIdx.x * blockDim.x + threadIdx.x;
    const int total = NBT * 2048 * PIX;
    if (i >= total) return;
    int p = i % PIX;
    int c = (i / PIX) % 2048;
    int bt = i / (PIX * 2048);
    int b = bt / TSEG, t = bt - b * TSEG;
    xt[i] = x[(((size_t)b * 2048 + c) * TSEG + t) * PIX + p];
}

__global__ void mask_final_k(const float* __restrict__ y2, const float* __restrict__ w3,
                             float* __restrict__ mask, float* __restrict__ outmask)
{
    int n = blockIdx.x;
    int p = threadIdx.x, g = threadIdx.y;
    int oh = p / 7, ow = p - oh * 7;
    float s = 0.f;
    for (int ic = g; ic < 512; ic += 8) {
        const float* row = y2 + ((size_t)n * 512 + ic) * PIX;
        const float* wr = w3 + ic * 9;
#pragma unroll
        for (int kh = 0; kh < 3; kh++)
#pragma unroll
            for (int kw = 0; kw < 3; kw++) {
                int ih = oh + kh - 1, iw = ow + kw - 1;
                if (ih >= 0 && ih < 7 && iw >= 0 && iw < 7)
                    s += row[ih * 7 + iw] * wr[kh * 3 + kw];
            }
    }
    __shared__ float red[8][49];
    red[g][p] = s;
    __syncthreads();
    if (g == 0) {
        float tot = 0.f;
#pragma unroll
        for (int q = 0; q < 8; q++) tot += red[q][p];
        float m = 1.f / (1.f + expf(-tot));
        mask[n * PIX + p] = m;
        outmask[n * PIX + p] = m;
    }
}

__global__ void mx_k(const float* __restrict__ xt, const float* __restrict__ mask, float* __restrict__ mx) {
    int i = blockIdx.x * blockDim.x + threadIdx.x;
    const int total = NBT * 2048 * PIX;
    if (i >= total) return;
    int p = i % PIX;
    int bt = i / (PIX * 2048);
    mx[i] = xt[i] * mask[bt * PIX + p];
}

__global__ void meanx_k(const float* __restrict__ mx, float* __restrict__ meanx) {
    int i = blockIdx.x * blockDim.x + threadIdx.x;
    const int inner = 2048 * PIX;
    if (i >= 2 * inner) return;
    int b = i / inner, r = i - b * inner;
    float s = 0.f;
    for (int t = 0; t < TSEG; t++) s += mx[((size_t)(b * TSEG + t)) * inner + r];
    meanx[i] = s * (1.f / (float)TSEG);
}

__global__ void mxc_k(const float* __restrict__ mx, float* __restrict__ mxc) {
    int i = blockIdx.x * blockDim.x + threadIdx.x;
    if (i >= NBT * 2048) return;
    const float* row = mx + (size_t)i * PIX;
    float s = 0.f;
    for (int p = 0; p < PIX; p++) s += row[p];
    mxc[i] = s * (1.f / (float)PIX);
}

__global__ void attfea_k(const float* __restrict__ mxc, const float* __restrict__ wf,
                         float* __restrict__ attfea)
{
    int bt = blockIdx.x;
    int tid = threadIdx.x;
    __shared__ float sr[256];
    float s = 0.f;
    for (int c = tid; c < 2048; c += 256) s += mxc[bt * 2048 + c] * wf[c];
    sr[tid] = s;
    __syncthreads();
    for (int st = 128; st > 0; st >>= 1) {
        if (tid < st) sr[tid] += sr[tid + st];
        __syncthreads();
    }
    if (tid == 0) attfea[bt] = sr[0];
}

__global__ void aw_k(const float* __restrict__ attfea, float* __restrict__ aw,
                     float* __restrict__ out_aws)
{
    int b = threadIdx.x;
    if (b >= 2) return;
    float m = -1e30f;
    for (int t = 0; t < TSEG; t++) m = fmaxf(m, attfea[b * TSEG + t]);
    float sum = 0.f;
    for (int t = 0; t < TSEG; t++) sum += expf(attfea[b * TSEG + t] - m);
    for (int t = 0; t < TSEG; t++) {
        float a = expf(attfea[b * TSEG + t] - m) / sum;
        aw[b * TSEG + t] = a;
        out_aws[b * TSEG + t] = a;
    }
}

__global__ void ginit_k(const float* __restrict__ Gx, const float* __restrict__ aw,
                        const float* __restrict__ lstm_b, float* __restrict__ gates0)
{
    int i = blockIdx.x * blockDim.x + threadIdx.x;
    const int total = 2 * 2048 * PIX;
    if (i >= total) return;
    int p = i % PIX;
    int oc = (i / PIX) % 2048;
    int b = i / (PIX * 2048);
    float s = lstm_b[oc];
    for (int t = 0; t < TSEG; t++)
        s += aw[b * TSEG + t] * Gx[(((size_t)(b * TSEG + t)) * 2048 + oc) * PIX + p];
    gates0[i] = s;
}

__global__ void lstm_point_k(const float* __restrict__ gates0, const float* __restrict__ part,
                             float* __restrict__ h, float* __restrict__ cst,
                             float* __restrict__ houts, int t)
{
    int b = blockIdx.x;
    int c = blockIdx.y * 8 + threadIdx.y;
    int p = threadIdx.x;
    size_t base = ((size_t)b * 2048) * PIX + p;
    float gi = gates0[base + (size_t)c * PIX];
    float gf = gates0[base + (size_t)(512 + c) * PIX];
    float go = gates0[base + (size_t)(1024 + c) * PIX];
    float gg = gates0[base + (size_t)(1536 + c) * PIX];
#pragma unroll
    for (int ks = 0; ks < 4; ks++) {
        size_t pb = ((size_t)(ks * 2 + b) * 2048) * PIX + p;
        gi += part[pb + (size_t)c * PIX];
        gf += part[pb + (size_t)(512 + c) * PIX];
        go += part[pb + (size_t)(1024 + c) * PIX];
        gg += part[pb + (size_t)(1536 + c) * PIX];
    }
    size_t hidx = ((size_t)b * 512 + c) * PIX + p;
    float cprev = cst[hidx];
    float si = 1.f / (1.f + expf(-gi));
    float sf = 1.f / (1.f + expf(-gf));
    float so = 1.f / (1.f + expf(-go));
    float c2 = sf * cprev + si * tanhf(gg);
    float h2 = so * tanhf(c2);
    cst[hidx] = c2;
    h[hidx] = h2;
    __shared__ float red[8][49];
    red[threadIdx.y][p] = h2;
    __syncthreads();
    if (p == 0) {
        float s = 0.f;
        for (int q = 0; q < 49; q++) s += red[threadIdx.y][q];
        houts[((size_t)t * 2 + b) * 512 + c] = s * (1.f / (float)PIX);
    }
}

__global__ void final_k(const float* __restrict__ houts, const float* __restrict__ fc_w,
                        const float* __restrict__ fc_b, float* __restrict__ out)
{
    __shared__ float om[1024];
    int tid = threadIdx.x;
    for (int i = tid; i < 1024; i += 512) {
        int b = i / 512, c = i - b * 512;
        float s = 0.f;
        for (int t = 0; t < TSEG; t++) s += houts[((size_t)t * 2 + b) * 512 + c];
        om[i] = s * (1.f / (float)TSEG);
    }
    __syncthreads();
    for (int i = tid; i < 202; i += 512) {
        int b = i / 101, k = i - b * 101;
        float s = fc_b[k];
        for (int c = 0; c < 512; c++) s += om[b * 512 + c] * fc_w[k * 512 + c];
        out[i] = s;
    }
    if (tid == 0) { out[2402] = 0.f; out[2403] = 0.f; }
}

// ===================== host =====================
static float* symaddr(const void* sym) { void* p = nullptr; cudaGetSymbolAddress(&p, sym); return (float*)p; }
static __nv_bfloat16* symaddrb(const void* sym) { void* p = nullptr; cudaGetSymbolAddress(&p, sym); return (__nv_bfloat16*)p; }

static inline void launch_gemm(const __nv_bfloat16* Ah, const __nv_bfloat16* Al,
                               const __nv_bfloat16* Bh, const __nv_bfloat16* Bl,
                               float* out, int K, int ksplit, int Mreal, int N,
                               const float* bn, int postop, long long partChunk)
{
    dim3 grid(N / 128, (Mreal + 127) / 128, ksplit);
    gemm_mma_k<<<grid, 256, GEMM_SMEM>>>(Ah, Al, Bh, Bl, out, K, K / ksplit, Mreal, N, bn, postop, partChunk);
}

extern "C" void kernel_launch(void* const* d_in, const int* in_sizes, int n_in,
                              void* d_out, int out_size)
{
    const float* x      = (const float*)d_in[0];
    const float* wf     = (const float*)d_in[1];
    const float* fc_w   = (const float*)d_in[3];
    const float* fc_b   = (const float*)d_in[4];
    const float* h0_w1  = (const float*)d_in[5];
    const float* h0_bn1 = (const float*)d_in[6];
    const float* h0_w2  = (const float*)d_in[7];
    const float* h0_bn2 = (const float*)d_in[8];
    const float* c0_w1  = (const float*)d_in[9];
    const float* c0_bn1 = (const float*)d_in[10];
    const float* c0_w2  = (const float*)d_in[11];
    const float* c0_bn2 = (const float*)d_in[12];
    const float* mk_w1  = (const float*)d_in[13];
    const float* mk_bn1 = (const float*)d_in[14];
    const float* mk_w2  = (const float*)d_in[15];
    const float* mk_bn2 = (const float*)d_in[16];
    const float* mk_w3  = (const float*)d_in[17];
    const float* lstm_w = (const float*)d_in[18];
    const float* lstm_b = (const float*)d_in[19];
    float* out = (float*)d_out;

    cudaFuncSetAttribute(gemm_mma_k, cudaFuncAttributeMaxDynamicSharedMemorySize, GEMM_SMEM);

    float *xt = symaddr(g_xt), *mx = symaddr(g_mx), *Gx = symaddr(g_Gx);
    float *y1 = symaddr(g_y1), *y2 = symaddr(g_y2), *mask = symaddr(g_mask);
    float *meanx = symaddr(g_meanx), *mxc = symaddr(g_mxc), *attfea = symaddr(g_attfea);
    float *aw = symaddr(g_aw), *h = symaddr(g_h), *cst = symaddr(g_cst);
    float *gates0 = symaddr(g_gates0), *part = symaddr(g_part), *houts = symaddr(g_houts);
    float *tmphc = symaddr(g_tmphc), *bnc1 = symaddr(g_bnc1);

    __nv_bfloat16 *axt_h = symaddrb(g_axt_h), *axt_l = symaddrb(g_axt_l);
    __nv_bfloat16 *amx_h = symaddrb(g_amx_h), *amx_l = symaddrb(g_amx_l);
    __nv_bfloat16 *ay1_h = symaddrb(g_ay1_h), *ay1_l = symaddrb(g_ay1_l);
    __nv_bfloat16 *sa_h = symaddrb(g_sa_h),   *sa_l = symaddrb(g_sa_l);
    __nv_bfloat16 *wmk1_h = symaddrb(g_wmk1_h), *wmk1_l = symaddrb(g_wmk1_l);
    __nv_bfloat16 *wmk2_h = symaddrb(g_wmk2_h), *wmk2_l = symaddrb(g_wmk2_l);
    __nv_bfloat16 *wgx_h = symaddrb(g_wgx_h),   *wgx_l = symaddrb(g_wgx_l);
    __nv_bfloat16 *whc1_h = symaddrb(g_whc1_h), *whc1_l = symaddrb(g_whc1_l);
    __nv_bfloat16 *w2h_h = symaddrb(g_w2h_h),   *w2h_l = symaddrb(g_w2h_l);
    __nv_bfloat16 *w2c_h = symaddrb(g_w2c_h),   *w2c_l = symaddrb(g_w2c_l);
    __nv_bfloat16 *wlh_h = symaddrb(g_wlh_h),   *wlh_l = symaddrb(g_wlh_l);

    const int ETOT = NBT * 2048 * PIX;
    dim3 cb(49, 8);
    auto blk = [](long long n) { return (unsigned)((n + 255) / 256); };

    // ---- weight repacks (input-only dependencies) ----
    repack_k<<<blk((long long)1024 * 9 * 1024), 256>>>(mk_w1, 2048, 0, 2048, 1024, wmk1_h, wmk1_l);
    repack_k<<<blk((long long)512 * 9 * 512), 256>>>(mk_w2, 1024, 0, 1024, 512, wmk2_h, wmk2_l);
    repack_k<<<blk((long long)2048 * 9 * 1024), 256>>>(lstm_w, 2560, 0, 2048, 2048, wgx_h, wgx_l);
    repack_k<<<blk((long long)2048 * 9 * 256), 256>>>(lstm_w, 2560, 2048, 512, 2048, wlh_h, wlh_l);
    repack_k<<<blk((long long)1024 * 9 * 1024), 256>>>(h0_w1, 2048, 0, 2048, 1024, whc1_h, whc1_l);
    repack_k<<<blk((long long)1024 * 9 * 1024), 256>>>(c0_w1, 2048, 0, 2048, 1024,
                                                       whc1_h + (size_t)1024 * K18, whc1_l + (size_t)1024 * K18);
    repack_k<<<blk((long long)512 * 9 * 512), 256>>>(h0_w2, 1024, 0, 1024, 512, w2h_h, w2h_l);
    repack_k<<<blk((long long)512 * 9 * 512), 256>>>(c0_w2, 1024, 0, 1024, 512, w2c_h, w2c_l);
    bnconcat_k<<<32, 256>>>(h0_bn1, c0_bn1, bnc1);

    // ---- mask path ----
    transpose_k<<<blk(ETOT), 256>>>(x, xt);
    im2col_k<<<blk((long long)2156 * 9 * 1024), 256>>>(xt, 2048, 0, 2048, 2156, axt_h, axt_l);
    launch_gemm(axt_h, axt_l, wmk1_h, wmk1_l, y1, K18, 1, 2156, 1024, mk_bn1, 1, 0);
    im2col_k<<<blk((long long)2156 * 9 * 512), 256>>>(y1, 1024, 0, 1024, 2156, ay1_h, ay1_l);
    launch_gemm(ay1_h, ay1_l, wmk2_h, wmk2_l, y2, K9, 1, 2156, 512, mk_bn2, 1, 0);
    mask_final_k<<<NBT, cb>>>(y2, mk_w3, mask, out + 246);

    // ---- masked features + attention (constant over steps) ----
    mx_k<<<blk(ETOT), 256>>>(xt, mask, mx);
    meanx_k<<<blk(2 * 2048 * PIX), 256>>>(mx, meanx);
    mxc_k<<<blk(NBT * 2048), 256>>>(mx, mxc);
    attfea_k<<<NBT, 256>>>(mxc, wf, attfea);
    aw_k<<<1, 32>>>(attfea, aw, out + 202);

    // ---- Gx = conv_x(mx) (hoisted LSTM x-path) ----
    im2col_k<<<blk((long long)2156 * 9 * 1024), 256>>>(mx, 2048, 0, 2048, 2156, amx_h, amx_l);
    launch_gemm(amx_h, amx_l, wgx_h, wgx_l, Gx, K18, 1, 2156, 2048, nullptr, 0, 0);

    // ---- h0/c0 init: layer1 N-concat (h||c), then per-branch layer2 ----
    im2col_k<<<blk((long long)98 * 9 * 1024), 256>>>(meanx, 2048, 0, 2048, 98, sa_h, sa_l);
    launch_gemm(sa_h, sa_l, whc1_h, whc1_l, part, K18, 8, 98, 2048, nullptr, 0, (long long)2 * 2048 * PIX);
    finish_k<<<blk(2 * 2048 * PIX), 256>>>(part, 8, 2 * 2048 * PIX, bnc1, tmphc, 2048, 2 * 2048 * PIX, 1);

    im2col_k<<<blk((long long)98 * 9 * 512), 256>>>(tmphc, 2048, 0, 1024, 98, sa_h, sa_l);
    launch_gemm(sa_h, sa_l, w2h_h, w2h_l, part, K9, 4, 98, 512, nullptr, 0, (long long)2 * 512 * PIX);
    finish_k<<<blk(2 * 512 * PIX), 256>>>(part, 4, 2 * 512 * PIX, h0_bn2, h, 512, 2 * 512 * PIX, 1);

    im2col_k<<<blk((long long)98 * 9 * 512), 256>>>(tmphc, 2048, 1024, 1024, 98, sa_h, sa_l);
    launch_gemm(sa_h, sa_l, w2c_h, w2c_l, part, K9, 4, 98, 512, nullptr, 0, (long long)2 * 512 * PIX);
    finish_k<<<blk(2 * 512 * PIX), 256>>>(part, 4, 2 * 512 * PIX, c0_bn2, cst, 512, 2 * 512 * PIX, 1);

    // ---- constant gate part ----
    ginit_k<<<blk(2 * 2048 * PIX), 256>>>(Gx, aw, lstm_b, gates0);

    // ---- recurrence: conv_h(h) on tensor cores each step ----
    for (int t = 0; t < TSEG; t++) {
        im2col_k<<<blk((long long)98 * 9 * 256), 256>>>(h, 512, 0, 512, 98, sa_h, sa_l);
        launch_gemm(sa_h, sa_l, wlh_h, wlh_l, part, K45, 4, 98, 2048, nullptr, 0, (long long)2 * 2048 * PIX);
        lstm_point_k<<<dim3(2, 64), cb>>>(gates0, part, h, cst, houts, t);
    }

    final_k<<<1, 512>>>(houts, fc_w, fc_b, out);
}

// round 9
// speedup vs baseline: 10.4967x; 1.6441x over previous
#include <cuda_runtime.h>
#include <cuda_bf16.h>
#include <cstdint>

// ===================== problem constants =====================
#define TSEG 22
#define NBT  44
#define PIX  49
#define K18  18432     // 9*2048
#define K9   9216      // 9*1024
#define K45  4608      // 9*512
#define AM   2176      // 17*128 pad of 2156

// ===================== fp32 scratch =====================
__device__ float g_xt[(size_t)NBT * 2048 * PIX];
__device__ float g_mx[(size_t)NBT * 2048 * PIX];
__device__ float g_xin[2 * 2048 * PIX];
__device__ float g_y1[(size_t)NBT * 1024 * PIX];
__device__ float g_y2[(size_t)NBT * 512 * PIX];
__device__ float g_mask[NBT * PIX];
__device__ float g_meanx[2 * 2048 * PIX];
__device__ float g_mxc[NBT * 2048];
__device__ float g_attfea[NBT];
__device__ float g_aw[NBT];
__device__ float g_h[2 * 512 * PIX];
__device__ float g_cst[2 * 512 * PIX];
__device__ float g_gates0[2 * 2048 * PIX];
__device__ float g_part[(size_t)8 * 2 * 2048 * PIX];
__device__ float g_houts[TSEG * 2 * 512];
__device__ float g_tmphc[2 * 2048 * PIX];
__device__ float g_bnc1[4 * 2048];

// ===================== split-bf16 buffers =====================
__device__ __nv_bfloat16 g_axt_h[(size_t)AM * K18],  g_axt_l[(size_t)AM * K18];
__device__ __nv_bfloat16 g_ay1_h[(size_t)AM * K9],   g_ay1_l[(size_t)AM * K9];
__device__ __nv_bfloat16 g_sa_h[(size_t)128 * K18],  g_sa_l[(size_t)128 * K18];
__device__ __nv_bfloat16 g_wmk1_h[(size_t)1024 * K18], g_wmk1_l[(size_t)1024 * K18];
__device__ __nv_bfloat16 g_wmk2_h[(size_t)512 * K9],   g_wmk2_l[(size_t)512 * K9];
__device__ __nv_bfloat16 g_wgx_h[(size_t)2048 * K18],  g_wgx_l[(size_t)2048 * K18];
__device__ __nv_bfloat16 g_whc1_h[(size_t)2048 * K18], g_whc1_l[(size_t)2048 * K18];
__device__ __nv_bfloat16 g_w2h_h[(size_t)512 * K9],    g_w2h_l[(size_t)512 * K9];
__device__ __nv_bfloat16 g_w2c_h[(size_t)512 * K9],    g_w2c_l[(size_t)512 * K9];
__device__ __nv_bfloat16 g_wlh_h[(size_t)2048 * K45],  g_wlh_l[(size_t)2048 * K45];

// ===================== base-ISA tensor helpers (sm_80+) =====================
__device__ __forceinline__ uint32_t smem_u32(const void* p) {
    uint32_t a;
    asm("{ .reg .u64 t; cvta.to.shared.u64 t, %1; cvt.u32.u64 %0, t; }" : "=r"(a) : "l"(p));
    return a;
}
__device__ __forceinline__ void ldsm4(uint32_t* r, uint32_t addr) {
    asm volatile("ldmatrix.sync.aligned.m8n8.x4.shared.b16 {%0,%1,%2,%3}, [%4];"
        : "=r"(r[0]), "=r"(r[1]), "=r"(r[2]), "=r"(r[3]) : "r"(addr));
}
__device__ __forceinline__ void mma16816(float* d, const uint32_t* a, const uint32_t* b) {
    asm volatile(
        "mma.sync.aligned.m16n8k16.row.col.f32.bf16.bf16.f32 "
        "{%0,%1,%2,%3}, {%4,%5,%6,%7}, {%8,%9}, {%0,%1,%2,%3};"
        : "+f"(d[0]), "+f"(d[1]), "+f"(d[2]), "+f"(d[3])
        : "r"(a[0]), "r"(a[1]), "r"(a[2]), "r"(a[3]), "r"(b[0]), "r"(b[1]));
}
#define CP_COMMIT() asm volatile("cp.async.commit_group;" ::: "memory")

// ===================== split-bf16 mma.sync GEMM =====================
// D(MxN) = (Ahi+Alo)(MxK) @ (Bhi+Blo)(NxK)^T, fp32 accum.
// grid (N/128, ceil(M/128), ksplit), block 256 (8 warps, 2x4 -> 64x32/warp).
// K-chunk 64 (128B rows, XOR-16B swizzle), 3-stage cp.async ring.
#define GEMM_SMEM (3 * 65536)
__global__ void __launch_bounds__(256, 1) gemm_mma_k(
    const __nv_bfloat16* __restrict__ Ahi, const __nv_bfloat16* __restrict__ Alo,
    const __nv_bfloat16* __restrict__ Bhi, const __nv_bfloat16* __restrict__ Blo,
    float* __restrict__ outp, int K, int Ktile, int Mreal, int OCtot,
    const float* __restrict__ bn, int postop, long long partChunk)
{
    extern __shared__ char dsm[];           // 3 stages x (Ah|Al|Bh|Bl) x 16KB
    __shared__ float s_sc[128], s_sh[128];

    int tid = threadIdx.x, lane = tid & 31, wid = tid >> 5;
    int wm = wid & 1, wn = wid >> 1;
    uint32_t sbase = smem_u32(dsm);

    int n0 = blockIdx.x * 128;
    int m0 = blockIdx.y * 128;
    long long kc0 = (long long)blockIdx.z * Ktile;
    int nChunks = Ktile / 64;

    // producer role: 64 threads per matrix
    int mytile = tid >> 6, tt = tid & 63;
    const __nv_bfloat16* mysrc =
        (mytile == 0) ? Ahi + (size_t)m0 * K + kc0 :
        (mytile == 1) ? Alo + (size_t)m0 * K + kc0 :
        (mytile == 2) ? Bhi + (size_t)n0 * K + kc0 :
                        Blo + (size_t)n0 * K + kc0;

    auto load_chunk = [&](int c, int stg) {
        const __nv_bfloat16* src = mysrc + (size_t)c * 64;
        uint32_t dbase = sbase + (uint32_t)stg * 65536u + (uint32_t)mytile * 16384u;
#pragma unroll
        for (int j = 0; j < 16; j++) {
            int idx = tt + j * 64;
            int r = idx >> 3, cs = idx & 7;
            const void* g = src + (size_t)r * K + cs * 8;
            uint32_t so = dbase + (uint32_t)(r * 128 + ((cs * 16) ^ ((r & 7) * 16)));
            asm volatile("cp.async.cg.shared.global [%0], [%1], 16;" :: "r"(so), "l"(g));
        }
    };

    float d[4][4][4];
#pragma unroll
    for (int a = 0; a < 4; a++)
#pragma unroll
        for (int b = 0; b < 4; b++)
#pragma unroll
            for (int c = 0; c < 4; c++) d[a][b][c] = 0.f;

    // prologue: prefetch 2 chunks
    if (nChunks > 0) { load_chunk(0, 0); CP_COMMIT(); }
    if (nChunks > 1) { load_chunk(1, 1); CP_COMMIT(); }

    for (int c = 0; c < nChunks; c++) {
        if (c + 1 < nChunks) asm volatile("cp.async.wait_group 1;" ::: "memory");
        else                 asm volatile("cp.async.wait_group 0;" ::: "memory");
        __syncthreads();
        if (c + 2 < nChunks) { load_chunk(c + 2, (c + 2) % 3); CP_COMMIT(); }

        int stg = c % 3;
        uint32_t sAh = sbase + (uint32_t)stg * 65536u;
        uint32_t sAl = sAh + 16384u;
        uint32_t sBh = sAh + 32768u;
        uint32_t sBl = sAh + 49152u;

#pragma unroll
        for (int k16 = 0; k16 < 4; k16++) {
            uint32_t ah[4][4], al[4][4], bh[4][2], bl[4][2];
#pragma unroll
            for (int mt = 0; mt < 4; mt++) {
                uint32_t r = (uint32_t)(wm * 64 + mt * 16 + (lane & 15));
                uint32_t cby = (uint32_t)(k16 * 32 + ((lane >> 4) << 4));
                uint32_t off = r * 128 + (cby ^ ((r & 7) << 4));
                ldsm4(ah[mt], sAh + off);
                ldsm4(al[mt], sAl + off);
            }
#pragma unroll
            for (int p = 0; p < 2; p++) {
                uint32_t r = (uint32_t)(wn * 32 + p * 16 + (((lane >> 4) & 1) << 3) + (lane & 7));
                uint32_t cby = (uint32_t)(k16 * 32 + (((lane >> 3) & 1) << 4));
                uint32_t off = r * 128 + (cby ^ ((r & 7) << 4));
                uint32_t t4[4];
                ldsm4(t4, sBh + off);
                bh[2 * p][0] = t4[0]; bh[2 * p][1] = t4[1];
                bh[2 * p + 1][0] = t4[2]; bh[2 * p + 1][1] = t4[3];
                ldsm4(t4, sBl + off);
                bl[2 * p][0] = t4[0]; bl[2 * p][1] = t4[1];
                bl[2 * p + 1][0] = t4[2]; bl[2 * p + 1][1] = t4[3];
            }
#pragma unroll
            for (int mt = 0; mt < 4; mt++)
#pragma unroll
                for (int nt = 0; nt < 4; nt++) {
                    mma16816(d[mt][nt], ah[mt], bh[nt]);
                    mma16816(d[mt][nt], ah[mt], bl[nt]);
                    mma16816(d[mt][nt], al[mt], bh[nt]);
                }
        }
        __syncthreads();
    }

    // epilogue: optional BN+ReLU, scattered NCHW write
    if (postop == 1 && tid < 128) {
        int oc = n0 + tid;
        float g = bn[oc], b = bn[OCtot + oc], m = bn[2 * OCtot + oc], v = bn[3 * OCtot + oc];
        float sc = g * rsqrtf(v + 1e-5f);
        s_sc[tid] = sc;
        s_sh[tid] = b - m * sc;
    }
    __syncthreads();

    float* obase0 = outp + (size_t)blockIdx.z * partChunk;
#pragma unroll
    for (int mt = 0; mt < 4; mt++) {
#pragma unroll
        for (int nt = 0; nt < 4; nt++) {
            int ln = wn * 32 + nt * 8 + 2 * (lane & 3);
            int r0 = m0 + wm * 64 + mt * 16 + (lane >> 2);
#pragma unroll
            for (int half = 0; half < 2; half++) {
                int mrow = r0 + half * 8;
                if (mrow < Mreal) {
                    int img = mrow / 49, p = mrow - img * 49;
                    float* ob = obase0 + ((size_t)img * OCtot + n0) * 49 + p;
                    float v0 = d[mt][nt][half * 2 + 0];
                    float v1 = d[mt][nt][half * 2 + 1];
                    if (postop) {
                        v0 = fmaxf(v0 * s_sc[ln] + s_sh[ln], 0.f);
                        v1 = fmaxf(v1 * s_sc[ln + 1] + s_sh[ln + 1], 0.f);
                    }
                    ob[(size_t)ln * 49] = v0;
                    ob[(size_t)(ln + 1) * 49] = v1;
                }
            }
        }
    }
}

// ===================== im2col (fp32 -> split bf16), k = kk*IC + ic =====================
__global__ void im2col_k(const float* __restrict__ in, int CHtot, int c0, int IC, int nRows,
                         __nv_bfloat16* __restrict__ hi, __nv_bfloat16* __restrict__ lo)
{
    int ICp = IC >> 1;
    long long idx = (long long)blockIdx.x * blockDim.x + threadIdx.x;
    long long tot = (long long)nRows * 9 * ICp;
    if (idx >= tot) return;
    int icp = (int)(idx % ICp);
    long long r2 = idx / ICp;
    int kk = (int)(r2 % 9);
    int row = (int)(r2 / 9);
    int img = row / 49, p = row - img * 49;
    int oh = p / 7, ow = p - oh * 7;
    int kh = kk / 3, kw = kk - kh * 3;
    int ih = oh + kh - 1, iw = ow + kw - 1;
    bool valid = (ih >= 0) && (ih < 7) && (iw >= 0) && (iw < 7);
    int q = valid ? (ih * 7 + iw) : 0;
    int ic = icp * 2;
    const float* base = in + ((size_t)img * CHtot + c0 + ic) * PIX + q;
    float v0 = valid ? base[0] : 0.f;
    float v1 = valid ? base[PIX] : 0.f;
    __nv_bfloat16 h0 = __float2bfloat16(v0);
    __nv_bfloat16 h1 = __float2bfloat16(v1);
    __nv_bfloat16 l0 = __float2bfloat16(v0 - __bfloat162float(h0));
    __nv_bfloat16 l1 = __float2bfloat16(v1 - __bfloat162float(h1));
    size_t o = (size_t)row * (IC * 9) + (size_t)kk * IC + ic;
    __nv_bfloat162 hh; hh.x = h0; hh.y = h1;
    __nv_bfloat162 ll; ll.x = l0; ll.y = l1;
    *(__nv_bfloat162*)(hi + o) = hh;
    *(__nv_bfloat162*)(lo + o) = ll;
}

// weight repack: dst[oc][kk*IC+ic] = src[(oc*srcStride + c0 + ic)*9 + kk], split bf16
__global__ void repack_k(const float* __restrict__ src, int srcStride, int c0, int IC, int OC,
                         __nv_bfloat16* __restrict__ hi, __nv_bfloat16* __restrict__ lo)
{
    int ICp = IC >> 1;
    long long idx = (long long)blockIdx.x * blockDim.x + threadIdx.x;
    long long tot = (long long)OC * 9 * ICp;
    if (idx >= tot) return;
    int icp = (int)(idx % ICp);
    long long r2 = idx / ICp;
    int kk = (int)(r2 % 9);
    int oc = (int)(r2 / 9);
    int ic = icp * 2;
    const float* b = src + ((size_t)oc * srcStride + c0 + ic) * 9 + kk;
    float v0 = b[0], v1 = b[9];
    __nv_bfloat16 h0 = __float2bfloat16(v0);
    __nv_bfloat16 h1 = __float2bfloat16(v1);
    __nv_bfloat16 l0 = __float2bfloat16(v0 - __bfloat162float(h0));
    __nv_bfloat16 l1 = __float2bfloat16(v1 - __bfloat162float(h1));
    size_t o = (size_t)oc * (IC * 9) + (size_t)kk * IC + ic;
    __nv_bfloat162 hh; hh.x = h0; hh.y = h1;
    __nv_bfloat162 ll; ll.x = l0; ll.y = l1;
    *(__nv_bfloat162*)(hi + o) = hh;
    *(__nv_bfloat162*)(lo + o) = ll;
}

__global__ void bnconcat_k(const float* __restrict__ a, const float* __restrict__ b,
                           float* __restrict__ dst)
{
    int i = blockIdx.x * blockDim.x + threadIdx.x;
    if (i >= 4 * 2048) return;
    int pr = i / 2048, j = i - pr * 2048;
    dst[i] = (j < 1024) ? a[pr * 1024 + j] : b[pr * 1024 + (j - 1024)];
}

// ===================== small kernels =====================
__global__ void finish_k(const float* __restrict__ part, int nsplit, int chunk,
                         const float* __restrict__ bn, float* __restrict__ out,
                         int OC, int total, int postop)
{
    int i = blockIdx.x * blockDim.x + threadIdx.x;
    if (i >= total) return;
    float s = 0.f;
    for (int ks = 0; ks < nsplit; ks++) s += part[(size_t)ks * chunk + i];
    if (postop == 1) {
        int oc = (i / PIX) % OC;
        float g = bn[oc], b = bn[OC + oc], m = bn[2 * OC + oc], v = bn[3 * OC + oc];
        s = (s - m) * g * rsqrtf(v + 1e-5f) + b;
        s = fmaxf(s, 0.f);
    }
    out[i] = s;
}

__global__ void transpose_k(const float* __restrict__ x, float* __restrict__ xt) {
    int i = blockIdx.x * blockDim.x + threadIdx.x;
    const int total = NBT * 2048 * PIX;
    if (i >= total) return;
    int p = i % PIX;
    int c = (i / PIX) % 2048;
    int bt = i / (PIX * 2048);
    int b = bt / TSEG, t = bt - b * TSEG;
    xt[i] = x[(((size_t)b * 2048 + c) * TSEG + t) * PIX + p];
}

__global__ void mask_final_k(const float* __restrict__ y2, const float* __restrict__ w3,
                             float* __restrict__ mask, float* __restrict__ outmask)
{
    int n = blockIdx.x;
    int p = threadIdx.x, g = threadIdx.y;
    int oh = p / 7, ow = p - oh * 7;
    float s = 0.f;
    for (int ic = g; ic < 512; ic += 8) {
        const float* row = y2 + ((size_t)n * 512 + ic) * PIX;
        const float* wr = w3 + ic * 9;
#pragma unroll
        for (int kh = 0; kh < 3; kh++)
#pragma unroll
            for (int kw = 0; kw < 3; kw++) {
                int ih = oh + kh - 1, iw = ow + kw - 1;
                if (ih >= 0 && ih < 7 && iw >= 0 && iw < 7)
                    s += row[ih * 7 + iw] * wr[kh * 3 + kw];
            }
    }
    __shared__ float red[8][49];
    red[g][p] = s;
    __syncthreads();
    if (g == 0) {
        float tot = 0.f;
#pragma unroll
        for (int q = 0; q < 8; q++) tot += red[q][p];
        float m = 1.f / (1.f + expf(-tot));
        mask[n * PIX + p] = m;
        outmask[n * PIX + p] = m;
    }
}

__global__ void mx_k(const float* __restrict__ xt, const float* __restrict__ mask, float* __restrict__ mx) {
    int i = blockIdx.x * blockDim.x + threadIdx.x;
    const int total = NBT * 2048 * PIX;
    if (i >= total) return;
    int p = i % PIX;
    int bt = i / (PIX * 2048);
    mx[i] = xt[i] * mask[bt * PIX + p];
}

__global__ void meanx_k(const float* __restrict__ mx, float* __restrict__ meanx) {
    int i = blockIdx.x * blockDim.x + threadIdx.x;
    const int inner = 2048 * PIX;
    if (i >= 2 * inner) return;
    int b = i / inner, r = i - b * inner;
    float s = 0.f;
    for (int t = 0; t < TSEG; t++) s += mx[((size_t)(b * TSEG + t)) * inner + r];
    meanx[i] = s * (1.f / (float)TSEG);
}

// xin[b,c,p] = sum_t aw[b,t] * mx[b,t,c,p]   (conv linearity: one GEMM instead of 22)
__global__ void xin_k(const float* __restrict__ mx, const float* __restrict__ aw,
                      float* __restrict__ xin)
{
    int i = blockIdx.x * blockDim.x + threadIdx.x;
    const int inner = 2048 * PIX;
    if (i >= 2 * inner) return;
    int b = i / inner, r = i - b * inner;
    float s = 0.f;
    for (int t = 0; t < TSEG; t++)
        s += aw[b * TSEG + t] * mx[((size_t)(b * TSEG + t)) * inner + r];
    xin[i] = s;
}

__global__ void mxc_k(const float* __restrict__ mx, float* __restrict__ mxc) {
    int i = blockIdx.x * blockDim.x + threadIdx.x;
    if (i >= NBT * 2048) return;
    const float* row = mx + (size_t)i * PIX;
    float s = 0.f;
    for (int p = 0; p < PIX; p++) s += row[p];
    mxc[i] = s * (1.f / (float)PIX);
}

__global__ void attfea_k(const float* __restrict__ mxc, const float* __restrict__ wf,
                         float* __restrict__ attfea)
{
    int bt = blockIdx.x;
    int tid = threadIdx.x;
    __shared__ float sr[256];
    float s = 0.f;
    for (int c = tid; c < 2048; c += 256) s += mxc[bt * 2048 + c] * wf[c];
    sr[tid] = s;
    __syncthreads();
    for (int st = 128; st > 0; st >>= 1) {
        if (tid < st) sr[tid] += sr[tid + st];
        __syncthreads();
    }
    if (tid == 0) attfea[bt] = sr[0];
}

__global__ void aw_k(const float* __restrict__ attfea, float* __restrict__ aw,
                     float* __restrict__ out_aws)
{
    int b = threadIdx.x;
    if (b >= 2) return;
    float m = -1e30f;
    for (int t = 0; t < TSEG; t++) m = fmaxf(m, attfea[b * TSEG + t]);
    float sum = 0.f;
    for (int t = 0; t < TSEG; t++) sum += expf(attfea[b * TSEG + t] - m);
    for (int t = 0; t < TSEG; t++) {
        float a = expf(attfea[b * TSEG + t] - m) / sum;
        aw[b * TSEG + t] = a;
        out_aws[b * TSEG + t] = a;
    }
}

// gates0 = lstm_b + sum of 8 xin-GEMM partials
__global__ void ginit8_k(const float* __restrict__ part, const float* __restrict__ lstm_b,
                         float* __restrict__ gates0)
{
    int i = blockIdx.x * blockDim.x + threadIdx.x;
    const int total = 2 * 2048 * PIX;
    if (i >= total) return;
    int oc = (i / PIX) % 2048;
    float s = lstm_b[oc];
#pragma unroll
    for (int ks = 0; ks < 8; ks++) s += part[(size_t)ks * total + i];
    gates0[i] = s;
}

// pointwise LSTM update + per-channel spatial mean; sums 8 conv_h partials
__global__ void lstm_point_k(const float* __restrict__ gates0, const float* __restrict__ part,
                             float* __restrict__ h, float* __restrict__ cst,
                             float* __restrict__ houts, int t)
{
    int b = blockIdx.x;
    int c = blockIdx.y * 8 + threadIdx.y;
    int p = threadIdx.x;
    size_t base = ((size_t)b * 2048) * PIX + p;
    float gi = gates0[base + (size_t)c * PIX];
    float gf = gates0[base + (size_t)(512 + c) * PIX];
    float go = gates0[base + (size_t)(1024 + c) * PIX];
    float gg = gates0[base + (size_t)(1536 + c) * PIX];
#pragma unroll
    for (int ks = 0; ks < 8; ks++) {
        size_t pb = ((size_t)(ks * 2 + b) * 2048) * PIX + p;
        gi += part[pb + (size_t)c * PIX];
        gf += part[pb + (size_t)(512 + c) * PIX];
        go += part[pb + (size_t)(1024 + c) * PIX];
        gg += part[pb + (size_t)(1536 + c) * PIX];
    }
    size_t hidx = ((size_t)b * 512 + c) * PIX + p;
    float cprev = cst[hidx];
    float si = 1.f / (1.f + expf(-gi));
    float sf = 1.f / (1.f + expf(-gf));
    float so = 1.f / (1.f + expf(-go));
    float c2 = sf * cprev + si * tanhf(gg);
    float h2 = so * tanhf(c2);
    cst[hidx] = c2;
    h[hidx] = h2;
    __shared__ float red[8][49];
    red[threadIdx.y][p] = h2;
    __syncthreads();
    if (p == 0) {
        float s = 0.f;
        for (int q = 0; q < 49; q++) s += red[threadIdx.y][q];
        houts[((size_t)t * 2 + b) * 512 + c] = s * (1.f / (float)PIX);
    }
}

__global__ void final_k(const float* __restrict__ houts, const float* __restrict__ fc_w,
                        const float* __restrict__ fc_b, float* __restrict__ out)
{
    __shared__ float om[1024];
    int tid = threadIdx.x;
    for (int i = tid; i < 1024; i += 512) {
        int b = i / 512, c = i - b * 512;
        float s = 0.f;
        for (int t = 0; t < TSEG; t++) s += houts[((size_t)t * 2 + b) * 512 + c];
        om[i] = s * (1.f / (float)TSEG);
    }
    __syncthreads();
    for (int i = tid; i < 202; i += 512) {
        int b = i / 101, k = i - b * 101;
        float s = fc_b[k];
        for (int c = 0; c < 512; c++) s += om[b * 512 + c] * fc_w[k * 512 + c];
        out[i] = s;
    }
    if (tid == 0) { out[2402] = 0.f; out[2403] = 0.f; }
}

// ===================== host =====================
static float* symaddr(const void* sym) { void* p = nullptr; cudaGetSymbolAddress(&p, sym); return (float*)p; }
static __nv_bfloat16* symaddrb(const void* sym) { void* p = nullptr; cudaGetSymbolAddress(&p, sym); return (__nv_bfloat16*)p; }

static inline void launch_gemm(const __nv_bfloat16* Ah, const __nv_bfloat16* Al,
                               const __nv_bfloat16* Bh, const __nv_bfloat16* Bl,
                               float* out, int K, int ksplit, int Mreal, int N,
                               const float* bn, int postop, long long partChunk)
{
    dim3 grid(N / 128, (Mreal + 127) / 128, ksplit);
    gemm_mma_k<<<grid, 256, GEMM_SMEM>>>(Ah, Al, Bh, Bl, out, K, K / ksplit, Mreal, N, bn, postop, partChunk);
}

extern "C" void kernel_launch(void* const* d_in, const int* in_sizes, int n_in,
                              void* d_out, int out_size)
{
    const float* x      = (const float*)d_in[0];
    const float* wf     = (const float*)d_in[1];
    const float* fc_w   = (const float*)d_in[3];
    const float* fc_b   = (const float*)d_in[4];
    const float* h0_w1  = (const float*)d_in[5];
    const float* h0_bn1 = (const float*)d_in[6];
    const float* h0_w2  = (const float*)d_in[7];
    const float* h0_bn2 = (const float*)d_in[8];
    const float* c0_w1  = (const float*)d_in[9];
    const float* c0_bn1 = (const float*)d_in[10];
    const float* c0_w2  = (const float*)d_in[11];
    const float* c0_bn2 = (const float*)d_in[12];
    const float* mk_w1  = (const float*)d_in[13];
    const float* mk_bn1 = (const float*)d_in[14];
    const float* mk_w2  = (const float*)d_in[15];
    const float* mk_bn2 = (const float*)d_in[16];
    const float* mk_w3  = (const float*)d_in[17];
    const float* lstm_w = (const float*)d_in[18];
    const float* lstm_b = (const float*)d_in[19];
    float* out = (float*)d_out;

    cudaFuncSetAttribute(gemm_mma_k, cudaFuncAttributeMaxDynamicSharedMemorySize, GEMM_SMEM);

    float *xt = symaddr(g_xt), *mx = symaddr(g_mx), *xin = symaddr(g_xin);
    float *y1 = symaddr(g_y1), *y2 = symaddr(g_y2), *mask = symaddr(g_mask);
    float *meanx = symaddr(g_meanx), *mxc = symaddr(g_mxc), *attfea = symaddr(g_attfea);
    float *aw = symaddr(g_aw), *h = symaddr(g_h), *cst = symaddr(g_cst);
    float *gates0 = symaddr(g_gates0), *part = symaddr(g_part), *houts = symaddr(g_houts);
    float *tmphc = symaddr(g_tmphc), *bnc1 = symaddr(g_bnc1);

    __nv_bfloat16 *axt_h = symaddrb(g_axt_h), *axt_l = symaddrb(g_axt_l);
    __nv_bfloat16 *ay1_h = symaddrb(g_ay1_h), *ay1_l = symaddrb(g_ay1_l);
    __nv_bfloat16 *sa_h = symaddrb(g_sa_h),   *sa_l = symaddrb(g_sa_l);
    __nv_bfloat16 *wmk1_h = symaddrb(g_wmk1_h), *wmk1_l = symaddrb(g_wmk1_l);
    __nv_bfloat16 *wmk2_h = symaddrb(g_wmk2_h), *wmk2_l = symaddrb(g_wmk2_l);
    __nv_bfloat16 *wgx_h = symaddrb(g_wgx_h),   *wgx_l = symaddrb(g_wgx_l);
    __nv_bfloat16 *whc1_h = symaddrb(g_whc1_h), *whc1_l = symaddrb(g_whc1_l);
    __nv_bfloat16 *w2h_h = symaddrb(g_w2h_h),   *w2h_l = symaddrb(g_w2h_l);
    __nv_bfloat16 *w2c_h = symaddrb(g_w2c_h),   *w2c_l = symaddrb(g_w2c_l);
    __nv_bfloat16 *wlh_h = symaddrb(g_wlh_h),   *wlh_l = symaddrb(g_wlh_l);

    const int ETOT = NBT * 2048 * PIX;
    dim3 cb(49, 8);
    auto blk = [](long long n) { return (unsigned)((n + 255) / 256); };

    // ---- weight repacks (input-only dependencies) ----
    repack_k<<<blk((long long)1024 * 9 * 1024), 256>>>(mk_w1, 2048, 0, 2048, 1024, wmk1_h, wmk1_l);
    repack_k<<<blk((long long)512 * 9 * 512), 256>>>(mk_w2, 1024, 0, 1024, 512, wmk2_h, wmk2_l);
    repack_k<<<blk((long long)2048 * 9 * 1024), 256>>>(lstm_w, 2560, 0, 2048, 2048, wgx_h, wgx_l);
    repack_k<<<blk((long long)2048 * 9 * 256), 256>>>(lstm_w, 2560, 2048, 512, 2048, wlh_h, wlh_l);
    repack_k<<<blk((long long)1024 * 9 * 1024), 256>>>(h0_w1, 2048, 0, 2048, 1024, whc1_h, whc1_l);
    repack_k<<<blk((long long)1024 * 9 * 1024), 256>>>(c0_w1, 2048, 0, 2048, 1024,
                                                       whc1_h + (size_t)1024 * K18, whc1_l + (size_t)1024 * K18);
    repack_k<<<blk((long long)512 * 9 * 512), 256>>>(h0_w2, 1024, 0, 1024, 512, w2h_h, w2h_l);
    repack_k<<<blk((long long)512 * 9 * 512), 256>>>(c0_w2, 1024, 0, 1024, 512, w2c_h, w2c_l);
    bnconcat_k<<<32, 256>>>(h0_bn1, c0_bn1, bnc1);

    // ---- mask path ----
    transpose_k<<<blk(ETOT), 256>>>(x, xt);
    im2col_k<<<blk((long long)2156 * 9 * 1024), 256>>>(xt, 2048, 0, 2048, 2156, axt_h, axt_l);
    launch_gemm(axt_h, axt_l, wmk1_h, wmk1_l, y1, K18, 1, 2156, 1024, mk_bn1, 1, 0);
    im2col_k<<<blk((long long)2156 * 9 * 512), 256>>>(y1, 1024, 0, 1024, 2156, ay1_h, ay1_l);
    launch_gemm(ay1_h, ay1_l, wmk2_h, wmk2_l, y2, K9, 1, 2156, 512, mk_bn2, 1, 0);
    mask_final_k<<<NBT, cb>>>(y2, mk_w3, mask, out + 246);

    // ---- masked features + attention (constant over steps) ----
    mx_k<<<blk(ETOT), 256>>>(xt, mask, mx);
    meanx_k<<<blk(2 * 2048 * PIX), 256>>>(mx, meanx);
    mxc_k<<<blk(NBT * 2048), 256>>>(mx, mxc);
    attfea_k<<<NBT, 256>>>(mxc, wf, attfea);
    aw_k<<<1, 32>>>(attfea, aw, out + 202);

    // ---- xin = sum_t aw[t]*mx_t, then ONE conv_x GEMM (linearity of conv) ----
    xin_k<<<blk(2 * 2048 * PIX), 256>>>(mx, aw, xin);
    im2col_k<<<blk((long long)98 * 9 * 1024), 256>>>(xin, 2048, 0, 2048, 98, sa_h, sa_l);
    launch_gemm(sa_h, sa_l, wgx_h, wgx_l, part, K18, 8, 98, 2048, nullptr, 0, (long long)2 * 2048 * PIX);
    ginit8_k<<<blk(2 * 2048 * PIX), 256>>>(part, lstm_b, gates0);

    // ---- h0/c0 init: layer1 N-concat (h||c), then per-branch layer2 ----
    im2col_k<<<blk((long long)98 * 9 * 1024), 256>>>(meanx, 2048, 0, 2048, 98, sa_h, sa_l);
    launch_gemm(sa_h, sa_l, whc1_h, whc1_l, part, K18, 8, 98, 2048, nullptr, 0, (long long)2 * 2048 * PIX);
    finish_k<<<blk(2 * 2048 * PIX), 256>>>(part, 8, 2 * 2048 * PIX, bnc1, tmphc, 2048, 2 * 2048 * PIX, 1);

    im2col_k<<<blk((long long)98 * 9 * 512), 256>>>(tmphc, 2048, 0, 1024, 98, sa_h, sa_l);
    launch_gemm(sa_h, sa_l, w2h_h, w2h_l, part, K9, 4, 98, 512, nullptr, 0, (long long)2 * 512 * PIX);
    finish_k<<<blk(2 * 512 * PIX), 256>>>(part, 4, 2 * 512 * PIX, h0_bn2, h, 512, 2 * 512 * PIX, 1);

    im2col_k<<<blk((long long)98 * 9 * 512), 256>>>(tmphc, 2048, 1024, 1024, 98, sa_h, sa_l);
    launch_gemm(sa_h, sa_l, w2c_h, w2c_l, part, K9, 4, 98, 512, nullptr, 0, (long long)2 * 512 * PIX);
    finish_k<<<blk(2 * 512 * PIX), 256>>>(part, 4, 2 * 512 * PIX, c0_bn2, cst, 512, 2 * 512 * PIX, 1);

    // ---- recurrence: conv_h(h) on tensor cores each step (ksplit 8 -> 128 CTAs) ----
    for (int t = 0; t < TSEG; t++) {
        im2col_k<<<blk((long long)98 * 9 * 256), 256>>>(h, 512, 0, 512, 98, sa_h, sa_l);
        launch_gemm(sa_h, sa_l, wlh_h, wlh_l, part, K45, 8, 98, 2048, nullptr, 0, (long long)2 * 2048 * PIX);
        lstm_point_k<<<dim3(2, 64), cb>>>(gates0, part, h, cst, houts, t);
    }

    final_k<<<1, 512>>>(houts, fc_w, fc_b, out);
}

// round 10
// speedup vs baseline: 10.7481x; 1.0240x over previous
#include <cuda_runtime.h>
#include <cuda_bf16.h>
#include <cstdint>

// ===================== problem constants =====================
#define TSEG 22
#define NBT  44
#define PIX  49
#define K18  18432     // 9*2048
#define K9   9216      // 9*1024
#define K45  4608      // 9*512
#define AM   2176      // 17*128 pad of 2156

// ===================== fp32 scratch =====================
__device__ float g_mx[(size_t)NBT * 2048 * PIX];
__device__ float g_xin[2 * 2048 * PIX];
__device__ float g_y2[(size_t)NBT * 512 * PIX];
__device__ float g_mask[NBT * PIX];
__device__ float g_meanx[2 * 2048 * PIX];
__device__ float g_mxc[NBT * 2048];
__device__ float g_attfea[NBT];
__device__ float g_aw[NBT];
__device__ float g_h[2 * 512 * PIX];
__device__ float g_cst[2 * 512 * PIX];
__device__ float g_gates0[2 * 2048 * PIX];
__device__ float g_part[2400000];                 // max(8*200704, 2*44*512*49)
__device__ float g_houts[TSEG * 2 * 512];
__device__ float g_tmphc[2 * 2048 * PIX];
__device__ float g_bnc1[4 * 2048];

// ===================== split-bf16 buffers (zero-init at module load) ==========
__device__ __nv_bfloat16 g_axt_h[(size_t)AM * K18],  g_axt_l[(size_t)AM * K18];
__device__ __nv_bfloat16 g_ay1_h[(size_t)AM * K9],   g_ay1_l[(size_t)AM * K9];
__device__ __nv_bfloat16 g_sa_h[(size_t)128 * K18],  g_sa_l[(size_t)128 * K18];
__device__ __nv_bfloat16 g_slh_h[(size_t)128 * K45], g_slh_l[(size_t)128 * K45];
__device__ __nv_bfloat16 g_wmk1_h[(size_t)1024 * K18], g_wmk1_l[(size_t)1024 * K18];
__device__ __nv_bfloat16 g_wmk2_h[(size_t)512 * K9],   g_wmk2_l[(size_t)512 * K9];
__device__ __nv_bfloat16 g_wgx_h[(size_t)2048 * K18],  g_wgx_l[(size_t)2048 * K18];
__device__ __nv_bfloat16 g_whc1_h[(size_t)2048 * K18], g_whc1_l[(size_t)2048 * K18];
__device__ __nv_bfloat16 g_w2h_h[(size_t)512 * K9],    g_w2h_l[(size_t)512 * K9];
__device__ __nv_bfloat16 g_w2c_h[(size_t)512 * K9],    g_w2c_l[(size_t)512 * K9];
__device__ __nv_bfloat16 g_wlh_h[(size_t)2048 * K45],  g_wlh_l[(size_t)2048 * K45];

// ===================== base-ISA tensor helpers (sm_80+) =====================
__device__ __forceinline__ uint32_t smem_u32(const void* p) {
    uint32_t a;
    asm("{ .reg .u64 t; cvta.to.shared.u64 t, %1; cvt.u32.u64 %0, t; }" : "=r"(a) : "l"(p));
    return a;
}
__device__ __forceinline__ void ldsm4(uint32_t* r, uint32_t addr) {
    asm volatile("ldmatrix.sync.aligned.m8n8.x4.shared.b16 {%0,%1,%2,%3}, [%4];"
        : "=r"(r[0]), "=r"(r[1]), "=r"(r[2]), "=r"(r[3]) : "r"(addr));
}
__device__ __forceinline__ void mma16816(float* d, const uint32_t* a, const uint32_t* b) {
    asm volatile(
        "mma.sync.aligned.m16n8k16.row.col.f32.bf16.bf16.f32 "
        "{%0,%1,%2,%3}, {%4,%5,%6,%7}, {%8,%9}, {%0,%1,%2,%3};"
        : "+f"(d[0]), "+f"(d[1]), "+f"(d[2]), "+f"(d[3])
        : "r"(a[0]), "r"(a[1]), "r"(a[2]), "r"(a[3]), "r"(b[0]), "r"(b[1]));
}
#define CP_COMMIT() asm volatile("cp.async.commit_group;" ::: "memory")

__device__ __forceinline__ void split_bf16(float v, __nv_bfloat16& h, __nv_bfloat16& l) {
    h = __float2bfloat16(v);
    l = __float2bfloat16(v - __bfloat162float(h));
}

// ===================== split-bf16 mma.sync GEMM =====================
// D(MxN) = (Ahi+Alo)(MxK) @ (Bhi+Blo)(NxK)^T, fp32 accum.
// grid (N/128, ceil(M/128), ksplit), block 256 (8 warps, 2x4 -> 64x32/warp).
// postop: 0 raw fp32 out, 1 BN+ReLU fp32 out, 2 BN+ReLU scattered split-bf16 im2col out.
#define GEMM_SMEM (3 * 65536)
__global__ void __launch_bounds__(256, 1) gemm_mma_k(
    const __nv_bfloat16* __restrict__ Ahi, const __nv_bfloat16* __restrict__ Alo,
    const __nv_bfloat16* __restrict__ Bhi, const __nv_bfloat16* __restrict__ Blo,
    float* __restrict__ outp, int K, int Ktile, int Mreal, int OCtot,
    const float* __restrict__ bn, int postop, long long partChunk,
    __nv_bfloat16* __restrict__ ic_h, __nv_bfloat16* __restrict__ ic_l)
{
    extern __shared__ char dsm[];           // 3 stages x (Ah|Al|Bh|Bl) x 16KB
    __shared__ float s_sc[128], s_sh[128];

    int tid = threadIdx.x, lane = tid & 31, wid = tid >> 5;
    int wm = wid & 1, wn = wid >> 1;
    uint32_t sbase = smem_u32(dsm);

    int n0 = blockIdx.x * 128;
    int m0 = blockIdx.y * 128;
    long long kc0 = (long long)blockIdx.z * Ktile;
    int nChunks = Ktile / 64;

    int mytile = tid >> 6, tt = tid & 63;
    const __nv_bfloat16* mysrc =
        (mytile == 0) ? Ahi + (size_t)m0 * K + kc0 :
        (mytile == 1) ? Alo + (size_t)m0 * K + kc0 :
        (mytile == 2) ? Bhi + (size_t)n0 * K + kc0 :
                        Blo + (size_t)n0 * K + kc0;

    auto load_chunk = [&](int c, int stg) {
        const __nv_bfloat16* src = mysrc + (size_t)c * 64;
        uint32_t dbase = sbase + (uint32_t)stg * 65536u + (uint32_t)mytile * 16384u;
#pragma unroll
        for (int j = 0; j < 16; j++) {
            int idx = tt + j * 64;
            int r = idx >> 3, cs = idx & 7;
            const void* g = src + (size_t)r * K + cs * 8;
            uint32_t so = dbase + (uint32_t)(r * 128 + ((cs * 16) ^ ((r & 7) * 16)));
            asm volatile("cp.async.cg.shared.global [%0], [%1], 16;" :: "r"(so), "l"(g));
        }
    };

    float d[4][4][4];
#pragma unroll
    for (int a = 0; a < 4; a++)
#pragma unroll
        for (int b = 0; b < 4; b++)
#pragma unroll
            for (int c = 0; c < 4; c++) d[a][b][c] = 0.f;

    if (nChunks > 0) { load_chunk(0, 0); CP_COMMIT(); }
    if (nChunks > 1) { load_chunk(1, 1); CP_COMMIT(); }

    for (int c = 0; c < nChunks; c++) {
        if (c + 1 < nChunks) asm volatile("cp.async.wait_group 1;" ::: "memory");
        else                 asm volatile("cp.async.wait_group 0;" ::: "memory");
        __syncthreads();
        if (c + 2 < nChunks) { load_chunk(c + 2, (c + 2) % 3); CP_COMMIT(); }

        int stg = c % 3;
        uint32_t sAh = sbase + (uint32_t)stg * 65536u;
        uint32_t sAl = sAh + 16384u;
        uint32_t sBh = sAh + 32768u;
        uint32_t sBl = sAh + 49152u;

#pragma unroll
        for (int k16 = 0; k16 < 4; k16++) {
            uint32_t ah[4][4], al[4][4], bh[4][2], bl[4][2];
#pragma unroll
            for (int mt = 0; mt < 4; mt++) {
                uint32_t r = (uint32_t)(wm * 64 + mt * 16 + (lane & 15));
                uint32_t cby = (uint32_t)(k16 * 32 + ((lane >> 4) << 4));
                uint32_t off = r * 128 + (cby ^ ((r & 7) << 4));
                ldsm4(ah[mt], sAh + off);
                ldsm4(al[mt], sAl + off);
            }
#pragma unroll
            for (int p = 0; p < 2; p++) {
                uint32_t r = (uint32_t)(wn * 32 + p * 16 + (((lane >> 4) & 1) << 3) + (lane & 7));
                uint32_t cby = (uint32_t)(k16 * 32 + (((lane >> 3) & 1) << 4));
                uint32_t off = r * 128 + (cby ^ ((r & 7) << 4));
                uint32_t t4[4];
                ldsm4(t4, sBh + off);
                bh[2 * p][0] = t4[0]; bh[2 * p][1] = t4[1];
                bh[2 * p + 1][0] = t4[2]; bh[2 * p + 1][1] = t4[3];
                ldsm4(t4, sBl + off);
                bl[2 * p][0] = t4[0]; bl[2 * p][1] = t4[1];
                bl[2 * p + 1][0] = t4[2]; bl[2 * p + 1][1] = t4[3];
            }
#pragma unroll
            for (int mt = 0; mt < 4; mt++)
#pragma unroll
                for (int nt = 0; nt < 4; nt++) {
                    mma16816(d[mt][nt], ah[mt], bh[nt]);
                    mma16816(d[mt][nt], ah[mt], bl[nt]);
                    mma16816(d[mt][nt], al[mt], bh[nt]);
                }
        }
        __syncthreads();
    }

    if (postop >= 1 && tid < 128) {
        int oc = n0 + tid;
        float g = bn[oc], b = bn[OCtot + oc], m = bn[2 * OCtot + oc], v = bn[3 * OCtot + oc];
        float sc = g * rsqrtf(v + 1e-5f);
        s_sc[tid] = sc;
        s_sh[tid] = b - m * sc;
    }
    __syncthreads();

    if (postop == 2) {
        // BN+ReLU, then scatter split-bf16 into next conv's im2col operand.
        // Value at pixel q contributes to row (img*49 + p') at k = kk*OCtot + oc
        // for the 9 kk whose p' = q - off(kk) is in-bounds. Out-of-bounds slots
        // are never written (zero from module init).
        int Kdst = OCtot * 9;
#pragma unroll
        for (int mt = 0; mt < 4; mt++) {
#pragma unroll
            for (int nt = 0; nt < 4; nt++) {
                int ln = wn * 32 + nt * 8 + 2 * (lane & 3);
                int r0 = m0 + wm * 64 + mt * 16 + (lane >> 2);
#pragma unroll
                for (int half = 0; half < 2; half++) {
                    int mrow = r0 + half * 8;
                    if (mrow < Mreal) {
                        int img = mrow / 49, p = mrow - img * 49;
                        float v0 = fmaxf(d[mt][nt][half * 2 + 0] * s_sc[ln] + s_sh[ln], 0.f);
                        float v1 = fmaxf(d[mt][nt][half * 2 + 1] * s_sc[ln + 1] + s_sh[ln + 1], 0.f);
                        __nv_bfloat162 hh, ll;
                        split_bf16(v0, hh.x, ll.x);
                        split_bf16(v1, hh.y, ll.y);
                        int qh = p / 7, qw = p - qh * 7;
                        int oc = n0 + ln;
#pragma unroll
                        for (int kk = 0; kk < 9; kk++) {
                            int oh = qh - (kk / 3 - 1), ow = qw - (kk % 3 - 1);
                            if (oh >= 0 && oh < 7 && ow >= 0 && ow < 7) {
                                size_t o = (size_t)(img * 49 + oh * 7 + ow) * Kdst + kk * OCtot + oc;
                                *(__nv_bfloat162*)(ic_h + o) = hh;
                                *(__nv_bfloat162*)(ic_l + o) = ll;
                            }
                        }
                    }
                }
            }
        }
        return;
    }

    float* obase0 = outp + (size_t)blockIdx.z * partChunk;
#pragma unroll
    for (int mt = 0; mt < 4; mt++) {
#pragma unroll
        for (int nt = 0; nt < 4; nt++) {
            int ln = wn * 32 + nt * 8 + 2 * (lane & 3);
            int r0 = m0 + wm * 64 + mt * 16 + (lane >> 2);
#pragma unroll
            for (int half = 0; half < 2; half++) {
                int mrow = r0 + half * 8;
                if (mrow < Mreal) {
                    int img = mrow / 49, p = mrow - img * 49;
                    float* ob = obase0 + ((size_t)img * OCtot + n0) * 49 + p;
                    float v0 = d[mt][nt][half * 2 + 0];
                    float v1 = d[mt][nt][half * 2 + 1];
                    if (postop) {
                        v0 = fmaxf(v0 * s_sc[ln] + s_sh[ln], 0.f);
                        v1 = fmaxf(v1 * s_sc[ln + 1] + s_sh[ln + 1], 0.f);
                    }
                    ob[(size_t)ln * 49] = v0;
                    ob[(size_t)(ln + 1) * 49] = v1;
                }
            }
        }
    }
}

// ===================== im2col (fp32 (img,CHtot,49) -> split bf16) =====================
__global__ void im2col_k(const float* __restrict__ in, int CHtot, int c0, int IC, int nRows,
                         __nv_bfloat16* __restrict__ hi, __nv_bfloat16* __restrict__ lo)
{
    int ICp = IC >> 1;
    long long idx = (long long)blockIdx.x * blockDim.x + threadIdx.x;
    long long tot = (long long)nRows * 9 * ICp;
    if (idx >= tot) return;
    int icp = (int)(idx % ICp);
    long long r2 = idx / ICp;
    int kk = (int)(r2 % 9);
    int row = (int)(r2 / 9);
    int img = row / 49, p = row - img * 49;
    int oh = p / 7, ow = p - oh * 7;
    int ih = oh + kk / 3 - 1, iw = ow + kk % 3 - 1;
    bool valid = (ih >= 0) && (ih < 7) && (iw >= 0) && (iw < 7);
    int q = valid ? (ih * 7 + iw) : 0;
    int ic = icp * 2;
    const float* base = in + ((size_t)img * CHtot + c0 + ic) * PIX + q;
    float v0 = valid ? base[0] : 0.f;
    float v1 = valid ? base[PIX] : 0.f;
    __nv_bfloat162 hh, ll;
    split_bf16(v0, hh.x, ll.x);
    split_bf16(v1, hh.y, ll.y);
    size_t o = (size_t)row * (IC * 9) + (size_t)kk * IC + ic;
    *(__nv_bfloat162*)(hi + o) = hh;
    *(__nv_bfloat162*)(lo + o) = ll;
}

// im2col reading x (B, 2048, T, 7, 7) directly (fused transpose)
__global__ void im2colx_k(const float* __restrict__ x,
                          __nv_bfloat16* __restrict__ hi, __nv_bfloat16* __restrict__ lo)
{
    const int ICp = 1024;
    long long idx = (long long)blockIdx.x * blockDim.x + threadIdx.x;
    long long tot = (long long)2156 * 9 * ICp;
    if (idx >= tot) return;
    int icp = (int)(idx % ICp);
    long long r2 = idx / ICp;
    int kk = (int)(r2 % 9);
    int row = (int)(r2 / 9);
    int img = row / 49, p = row - img * 49;
    int b = img / TSEG, t = img - b * TSEG;
    int oh = p / 7, ow = p - oh * 7;
    int ih = oh + kk / 3 - 1, iw = ow + kk % 3 - 1;
    bool valid = (ih >= 0) && (ih < 7) && (iw >= 0) && (iw < 7);
    int q = valid ? (ih * 7 + iw) : 0;
    int ic = icp * 2;
    const float* base = x + (((size_t)(b * 2048 + ic) * TSEG) + t) * PIX + q;
    float v0 = valid ? base[0] : 0.f;
    float v1 = valid ? base[(size_t)TSEG * PIX] : 0.f;
    __nv_bfloat162 hh, ll;
    split_bf16(v0, hh.x, ll.x);
    split_bf16(v1, hh.y, ll.y);
    size_t o = (size_t)row * K18 + (size_t)kk * 2048 + ic;
    *(__nv_bfloat162*)(hi + o) = hh;
    *(__nv_bfloat162*)(lo + o) = ll;
}

// weight repack via smem transpose: dst[oc][kk*IC+ic] = src[(oc*srcStride+c0+ic)*9+kk]
// grid (OC, IC/256), block 128
__global__ void repack2_k(const float* __restrict__ src, int srcStride, int c0, int IC,
                          __nv_bfloat16* __restrict__ hi, __nv_bfloat16* __restrict__ lo)
{
    __shared__ float s[2304];
    int oc = blockIdx.x, ic0 = blockIdx.y * 256, tid = threadIdx.x;
    const float* base = src + ((size_t)oc * srcStride + c0 + ic0) * 9;
    for (int i = tid; i < 2304; i += 128) s[i] = base[i];
    __syncthreads();
    size_t dbase = (size_t)oc * ((size_t)IC * 9) + ic0 + 2 * tid;
#pragma unroll
    for (int kk = 0; kk < 9; kk++) {
        __nv_bfloat162 hh, ll;
        split_bf16(s[(2 * tid) * 9 + kk], hh.x, ll.x);
        split_bf16(s[(2 * tid + 1) * 9 + kk], hh.y, ll.y);
        size_t o = dbase + (size_t)kk * IC;
        *(__nv_bfloat162*)(hi + o) = hh;
        *(__nv_bfloat162*)(lo + o) = ll;
    }
}

__global__ void bnconcat_k(const float* __restrict__ a, const float* __restrict__ b,
                           float* __restrict__ dst)
{
    int i = blockIdx.x * blockDim.x + threadIdx.x;
    if (i >= 4 * 2048) return;
    int pr = i / 2048, j = i - pr * 2048;
    dst[i] = (j < 1024) ? a[pr * 1024 + j] : b[pr * 1024 + (j - 1024)];
}

// ===================== small kernels =====================
__global__ void finish_k(const float* __restrict__ part, int nsplit, int chunk,
                         const float* __restrict__ bn, float* __restrict__ out,
                         int OC, int total, int postop)
{
    int i = blockIdx.x * blockDim.x + threadIdx.x;
    if (i >= total) return;
    float s = 0.f;
    for (int ks = 0; ks < nsplit; ks++) s += part[(size_t)ks * chunk + i];
    if (postop == 1) {
        int oc = (i / PIX) % OC;
        float g = bn[oc], b = bn[OC + oc], m = bn[2 * OC + oc], v = bn[3 * OC + oc];
        s = (s - m) * g * rsqrtf(v + 1e-5f) + b;
        s = fmaxf(s, 0.f);
    }
    out[i] = s;
}

__global__ void mask_final_k(const float* __restrict__ y2, const float* __restrict__ w3,
                             float* __restrict__ mask, float* __restrict__ outmask)
{
    int n = blockIdx.x;
    int p = threadIdx.x, g = threadIdx.y;
    int oh = p / 7, ow = p - oh * 7;
    float s = 0.f;
    for (int ic = g; ic < 512; ic += 8) {
        const float* row = y2 + ((size_t)n * 512 + ic) * PIX;
        const float* wr = w3 + ic * 9;
#pragma unroll
        for (int kh = 0; kh < 3; kh++)
#pragma unroll
            for (int kw = 0; kw < 3; kw++) {
                int ih = oh + kh - 1, iw = ow + kw - 1;
                if (ih >= 0 && ih < 7 && iw >= 0 && iw < 7)
                    s += row[ih * 7 + iw] * wr[kh * 3 + kw];
            }
    }
    __shared__ float red[8][49];
    red[g][p] = s;
    __syncthreads();
    if (g == 0) {
        float tot = 0.f;
#pragma unroll
        for (int q = 0; q < 8; q++) tot += red[q][p];
        float m = 1.f / (1.f + expf(-tot));
        mask[n * PIX + p] = m;
        outmask[n * PIX + p] = m;
    }
}

// mx[(bt,c,p)] = x[(b,c,t,p)] * mask[bt,p]   (fused transpose)
__global__ void mx_k(const float* __restrict__ x, const float* __restrict__ mask, float* __restrict__ mx) {
    int i = blockIdx.x * blockDim.x + threadIdx.x;
    const int total = NBT * 2048 * PIX;
    if (i >= total) return;
    int p = i % PIX;
    int c = (i / PIX) % 2048;
    int bt = i / (PIX * 2048);
    int b = bt / TSEG, t = bt - b * TSEG;
    mx[i] = x[(((size_t)(b * 2048 + c)) * TSEG + t) * PIX + p] * mask[bt * PIX + p];
}

__global__ void meanx_k(const float* __restrict__ mx, float* __restrict__ meanx) {
    int i = blockIdx.x * blockDim.x + threadIdx.x;
    const int inner = 2048 * PIX;
    if (i >= 2 * inner) return;
    int b = i / inner, r = i - b * inner;
    float s = 0.f;
    for (int t = 0; t < TSEG; t++) s += mx[((size_t)(b * TSEG + t)) * inner + r];
    meanx[i] = s * (1.f / (float)TSEG);
}

__global__ void xin_k(const float* __restrict__ mx, const float* __restrict__ aw,
                      float* __restrict__ xin)
{
    int i = blockIdx.x * blockDim.x + threadIdx.x;
    const int inner = 2048 * PIX;
    if (i >= 2 * inner) return;
    int b = i / inner, r = i - b * inner;
    float s = 0.f;
    for (int t = 0; t < TSEG; t++)
        s += aw[b * TSEG + t] * mx[((size_t)(b * TSEG + t)) * inner + r];
    xin[i] = s;
}

__global__ void mxc_k(const float* __restrict__ mx, float* __restrict__ mxc) {
    int i = blockIdx.x * blockDim.x + threadIdx.x;
    if (i >= NBT * 2048) return;
    const float* row = mx + (size_t)i * PIX;
    float s = 0.f;
    for (int p = 0; p < PIX; p++) s += row[p];
    mxc[i] = s * (1.f / (float)PIX);
}

__global__ void attfea_k(const float* __restrict__ mxc, const float* __restrict__ wf,
                         float* __restrict__ attfea)
{
    int bt = blockIdx.x;
    int tid = threadIdx.x;
    __shared__ float sr[256];
    float s = 0.f;
    for (int c = tid; c < 2048; c += 256) s += mxc[bt * 2048 + c] * wf[c];
    sr[tid] = s;
    __syncthreads();
    for (int st = 128; st > 0; st >>= 1) {
        if (tid < st) sr[tid] += sr[tid + st];
        __syncthreads();
    }
    if (tid == 0) attfea[bt] = sr[0];
}

__global__ void aw_k(const float* __restrict__ attfea, float* __restrict__ aw,
                     float* __restrict__ out_aws)
{
    int b = threadIdx.x;
    if (b >= 2) return;
    float m = -1e30f;
    for (int t = 0; t < TSEG; t++) m = fmaxf(m, attfea[b * TSEG + t]);
    float sum = 0.f;
    for (int t = 0; t < TSEG; t++) sum += expf(attfea[b * TSEG + t] - m);
    for (int t = 0; t < TSEG; t++) {
        float a = expf(attfea[b * TSEG + t] - m) / sum;
        aw[b * TSEG + t] = a;
        out_aws[b * TSEG + t] = a;
    }
}

__global__ void ginit8_k(const float* __restrict__ part, const float* __restrict__ lstm_b,
                         float* __restrict__ gates0)
{
    int i = blockIdx.x * blockDim.x + threadIdx.x;
    const int total = 2 * 2048 * PIX;
    if (i >= total) return;
    int oc = (i / PIX) % 2048;
    float s = lstm_b[oc];
#pragma unroll
    for (int ks = 0; ks < 8; ks++) s += part[(size_t)ks * total + i];
    gates0[i] = s;
}

// pointwise LSTM update + spatial mean + fused scatter of h2 into next step's
// im2col A-operand (invalid slots stay zero from module init / seed im2col).
__global__ void lstm_point_k(const float* __restrict__ gates0, const float* __restrict__ part,
                             float* __restrict__ h, float* __restrict__ cst,
                             float* __restrict__ houts, int t,
                             __nv_bfloat16* __restrict__ slh_h, __nv_bfloat16* __restrict__ slh_l)
{
    int b = blockIdx.x;
    int c = blockIdx.y * 8 + threadIdx.y;
    int p = threadIdx.x;
    size_t base = ((size_t)b * 2048) * PIX + p;
    float gi = gates0[base + (size_t)c * PIX];
    float gf = gates0[base + (size_t)(512 + c) * PIX];
    float go = gates0[base + (size_t)(1024 + c) * PIX];
    float gg = gates0[base + (size_t)(1536 + c) * PIX];
#pragma unroll
    for (int ks = 0; ks < 8; ks++) {
        size_t pb = ((size_t)(ks * 2 + b) * 2048) * PIX + p;
        gi += part[pb + (size_t)c * PIX];
        gf += part[pb + (size_t)(512 + c) * PIX];
        go += part[pb + (size_t)(1024 + c) * PIX];
        gg += part[pb + (size_t)(1536 + c) * PIX];
    }
    size_t hidx = ((size_t)b * 512 + c) * PIX + p;
    float cprev = cst[hidx];
    float si = 1.f / (1.f + expf(-gi));
    float sf = 1.f / (1.f + expf(-gf));
    float so = 1.f / (1.f + expf(-go));
    float c2 = sf * cprev + si * tanhf(gg);
    float h2 = so * tanhf(c2);
    cst[hidx] = c2;
    h[hidx] = h2;

    // scatter h2 into im2col operand for the next step's conv_h GEMM
    {
        __nv_bfloat16 hh, ll;
        split_bf16(h2, hh, ll);
        int qh = p / 7, qw = p - qh * 7;
#pragma unroll
        for (int kk = 0; kk < 9; kk++) {
            int oh = qh - (kk / 3 - 1), ow = qw - (kk % 3 - 1);
            if (oh >= 0 && oh < 7 && ow >= 0 && ow < 7) {
                size_t o = (size_t)(b * 49 + oh * 7 + ow) * K45 + kk * 512 + c;
                slh_h[o] = hh;
                slh_l[o] = ll;
            }
        }
    }

    __shared__ float red[8][49];
    red[threadIdx.y][p] = h2;
    __syncthreads();
    if (p == 0) {
        float s = 0.f;
        for (int q = 0; q < 49; q++) s += red[threadIdx.y][q];
        houts[((size_t)t * 2 + b) * 512 + c] = s * (1.f / (float)PIX);
    }
}

__global__ void final_k(const float* __restrict__ houts, const float* __restrict__ fc_w,
                        const float* __restrict__ fc_b, float* __restrict__ out)
{
    __shared__ float om[1024];
    int tid = threadIdx.x;
    for (int i = tid; i < 1024; i += 512) {
        int b = i / 512, c = i - b * 512;
        float s = 0.f;
        for (int t = 0; t < TSEG; t++) s += houts[((size_t)t * 2 + b) * 512 + c];
        om[i] = s * (1.f / (float)TSEG);
    }
    __syncthreads();
    for (int i = tid; i < 202; i += 512) {
        int b = i / 101, k = i - b * 101;
        float s = fc_b[k];
        for (int c = 0; c < 512; c++) s += om[b * 512 + c] * fc_w[k * 512 + c];
        out[i] = s;
    }
    if (tid == 0) { out[2402] = 0.f; out[2403] = 0.f; }
}

// ===================== host =====================
static float* symaddr(const void* sym) { void* p = nullptr; cudaGetSymbolAddress(&p, sym); return (float*)p; }
static __nv_bfloat16* symaddrb(const void* sym) { void* p = nullptr; cudaGetSymbolAddress(&p, sym); return (__nv_bfloat16*)p; }

static inline void launch_gemm(const __nv_bfloat16* Ah, const __nv_bfloat16* Al,
                               const __nv_bfloat16* Bh, const __nv_bfloat16* Bl,
                               float* out, int K, int ksplit, int Mreal, int N,
                               const float* bn, int postop, long long partChunk,
                               __nv_bfloat16* ich = nullptr, __nv_bfloat16* icl = nullptr)
{
    dim3 grid(N / 128, (Mreal + 127) / 128, ksplit);
    gemm_mma_k<<<grid, 256, GEMM_SMEM>>>(Ah, Al, Bh, Bl, out, K, K / ksplit, Mreal, N,
                                         bn, postop, partChunk, ich, icl);
}

extern "C" void kernel_launch(void* const* d_in, const int* in_sizes, int n_in,
                              void* d_out, int out_size)
{
    const float* x      = (const float*)d_in[0];
    const float* wf     = (const float*)d_in[1];
    const float* fc_w   = (const float*)d_in[3];
    const float* fc_b   = (const float*)d_in[4];
    const float* h0_w1  = (const float*)d_in[5];
    const float* h0_bn1 = (const float*)d_in[6];
    const float* h0_w2  = (const float*)d_in[7];
    const float* h0_bn2 = (const float*)d_in[8];
    const float* c0_w1  = (const float*)d_in[9];
    const float* c0_bn1 = (const float*)d_in[10];
    const float* c0_w2  = (const float*)d_in[11];
    const float* c0_bn2 = (const float*)d_in[12];
    const float* mk_w1  = (const float*)d_in[13];
    const float* mk_bn1 = (const float*)d_in[14];
    const float* mk_w2  = (const float*)d_in[15];
    const float* mk_bn2 = (const float*)d_in[16];
    const float* mk_w3  = (const float*)d_in[17];
    const float* lstm_w = (const float*)d_in[18];
    const float* lstm_b = (const float*)d_in[19];
    float* out = (float*)d_out;

    cudaFuncSetAttribute(gemm_mma_k, cudaFuncAttributeMaxDynamicSharedMemorySize, GEMM_SMEM);

    float *mx = symaddr(g_mx), *xin = symaddr(g_xin);
    float *y2 = symaddr(g_y2), *mask = symaddr(g_mask);
    float *meanx = symaddr(g_meanx), *mxc = symaddr(g_mxc), *attfea = symaddr(g_attfea);
    float *aw = symaddr(g_aw), *h = symaddr(g_h), *cst = symaddr(g_cst);
    float *gates0 = symaddr(g_gates0), *part = symaddr(g_part), *houts = symaddr(g_houts);
    float *tmphc = symaddr(g_tmphc), *bnc1 = symaddr(g_bnc1);

    __nv_bfloat16 *axt_h = symaddrb(g_axt_h), *axt_l = symaddrb(g_axt_l);
    __nv_bfloat16 *ay1_h = symaddrb(g_ay1_h), *ay1_l = symaddrb(g_ay1_l);
    __nv_bfloat16 *sa_h = symaddrb(g_sa_h),   *sa_l = symaddrb(g_sa_l);
    __nv_bfloat16 *slh_h = symaddrb(g_slh_h), *slh_l = symaddrb(g_slh_l);
    __nv_bfloat16 *wmk1_h = symaddrb(g_wmk1_h), *wmk1_l = symaddrb(g_wmk1_l);
    __nv_bfloat16 *wmk2_h = symaddrb(g_wmk2_h), *wmk2_l = symaddrb(g_wmk2_l);
    __nv_bfloat16 *wgx_h = symaddrb(g_wgx_h),   *wgx_l = symaddrb(g_wgx_l);
    __nv_bfloat16 *whc1_h = symaddrb(g_whc1_h), *whc1_l = symaddrb(g_whc1_l);
    __nv_bfloat16 *w2h_h = symaddrb(g_w2h_h),   *w2h_l = symaddrb(g_w2h_l);
    __nv_bfloat16 *w2c_h = symaddrb(g_w2c_h),   *w2c_l = symaddrb(g_w2c_l);
    __nv_bfloat16 *wlh_h = symaddrb(g_wlh_h),   *wlh_l = symaddrb(g_wlh_l);

    const int ETOT = NBT * 2048 * PIX;
    dim3 cb(49, 8);
    auto blk = [](long long n) { return (unsigned)((n + 255) / 256); };

    // ---- weight repacks (smem-transpose, coalesced) ----
    repack2_k<<<dim3(1024, 8), 128>>>(mk_w1, 2048, 0, 2048, wmk1_h, wmk1_l);
    repack2_k<<<dim3(512, 4), 128>>>(mk_w2, 1024, 0, 1024, wmk2_h, wmk2_l);
    repack2_k<<<dim3(2048, 8), 128>>>(lstm_w, 2560, 0, 2048, wgx_h, wgx_l);
    repack2_k<<<dim3(2048, 2), 128>>>(lstm_w, 2560, 2048, 512, wlh_h, wlh_l);
    repack2_k<<<dim3(1024, 8), 128>>>(h0_w1, 2048, 0, 2048, whc1_h, whc1_l);
    repack2_k<<<dim3(1024, 8), 128>>>(c0_w1, 2048, 0, 2048,
                                      whc1_h + (size_t)1024 * K18, whc1_l + (size_t)1024 * K18);
    repack2_k<<<dim3(512, 4), 128>>>(h0_w2, 1024, 0, 1024, w2h_h, w2h_l);
    repack2_k<<<dim3(512, 4), 128>>>(c0_w2, 1024, 0, 1024, w2c_h, w2c_l);
    bnconcat_k<<<32, 256>>>(h0_bn1, c0_bn1, bnc1);

    // ---- mask path: conv1 epilogue scatters im2col for conv2 (no y1, no extra im2col) ----
    im2colx_k<<<blk((long long)2156 * 9 * 1024), 256>>>(x, axt_h, axt_l);
    launch_gemm(axt_h, axt_l, wmk1_h, wmk1_l, part, K18, 1, 2156, 1024, mk_bn1, 2, 0, ay1_h, ay1_l);
    launch_gemm(ay1_h, ay1_l, wmk2_h, wmk2_l, part, K9, 2, 2156, 512, nullptr, 0,
                (long long)44 * 512 * PIX);
    finish_k<<<blk((long long)44 * 512 * PIX), 256>>>(part, 2, 44 * 512 * PIX, mk_bn2, y2,
                                                      512, 44 * 512 * PIX, 1);
    mask_final_k<<<NBT, cb>>>(y2, mk_w3, mask, out + 246);

    // ---- masked features + attention (constant over steps) ----
    mx_k<<<blk(ETOT), 256>>>(x, mask, mx);
    meanx_k<<<blk(2 * 2048 * PIX), 256>>>(mx, meanx);
    mxc_k<<<blk(NBT * 2048), 256>>>(mx, mxc);
    attfea_k<<<NBT, 256>>>(mxc, wf, attfea);
    aw_k<<<1, 32>>>(attfea, aw, out + 202);

    // ---- xin = sum_t aw[t]*mx_t, one conv_x GEMM (linearity) ----
    xin_k<<<blk(2 * 2048 * PIX), 256>>>(mx, aw, xin);
    im2col_k<<<blk((long long)98 * 9 * 1024), 256>>>(xin, 2048, 0, 2048, 98, sa_h, sa_l);
    launch_gemm(sa_h, sa_l, wgx_h, wgx_l, part, K18, 8, 98, 2048, nullptr, 0, (long long)2 * 2048 * PIX);
    ginit8_k<<<blk(2 * 2048 * PIX), 256>>>(part, lstm_b, gates0);

    // ---- h0/c0 init ----
    im2col_k<<<blk((long long)98 * 9 * 1024), 256>>>(meanx, 2048, 0, 2048, 98, sa_h, sa_l);
    launch_gemm(sa_h, sa_l, whc1_h, whc1_l, part, K18, 8, 98, 2048, nullptr, 0, (long long)2 * 2048 * PIX);
    finish_k<<<blk(2 * 2048 * PIX), 256>>>(part, 8, 2 * 2048 * PIX, bnc1, tmphc, 2048, 2 * 2048 * PIX, 1);

    im2col_k<<<blk((long long)98 * 9 * 512), 256>>>(tmphc, 2048, 0, 1024, 98, sa_h, sa_l);
    launch_gemm(sa_h, sa_l, w2h_h, w2h_l, part, K9, 4, 98, 512, nullptr, 0, (long long)2 * 512 * PIX);
    finish_k<<<blk(2 * 512 * PIX), 256>>>(part, 4, 2 * 512 * PIX, h0_bn2, h, 512, 2 * 512 * PIX, 1);

    im2col_k<<<blk((long long)98 * 9 * 512), 256>>>(tmphc, 2048, 1024, 1024, 98, sa_h, sa_l);
    launch_gemm(sa_h, sa_l, w2c_h, w2c_l, part, K9, 4, 98, 512, nullptr, 0, (long long)2 * 512 * PIX);
    finish_k<<<blk(2 * 512 * PIX), 256>>>(part, 4, 2 * 512 * PIX, c0_bn2, cst, 512, 2 * 512 * PIX, 1);

    // ---- seed im2col for h0, then recurrence (lstm_point scatters next A) ----
    im2col_k<<<blk((long long)98 * 9 * 256), 256>>>(h, 512, 0, 512, 98, slh_h, slh_l);
    for (int t = 0; t < TSEG; t++) {
        launch_gemm(slh_h, slh_l, wlh_h, wlh_l, part, K45, 8, 98, 2048, nullptr, 0,
                    (long long)2 * 2048 * PIX);
        lstm_point_k<<<dim3(2, 64), cb>>>(gates0, part, h, cst, houts, t, slh_h, slh_l);
    }

    final_k<<<1, 512>>>(houts, fc_w, fc_b, out);
}

// round 11
// speedup vs baseline: 12.5346x; 1.1662x over previous
#include <cuda_runtime.h>
#include <cuda_fp16.h>
#include <cstdint>

// ===================== problem constants =====================
#define TSEG 22
#define NBT  44
#define PIX  49
#define K18  18432     // 9*2048
#define K9   9216      // 9*1024
#define K45  4608      // 9*512
#define AM   2176      // 17*128 pad of 2156

// ===================== fp32 scratch =====================
__device__ float g_mx[(size_t)NBT * 2048 * PIX];
__device__ float g_xin[2 * 2048 * PIX];
__device__ float g_y2[(size_t)NBT * 512 * PIX];
__device__ float g_mask[NBT * PIX];
__device__ float g_meanx[2 * 2048 * PIX];
__device__ float g_mxc[NBT * 2048];
__device__ float g_attfea[NBT];
__device__ float g_aw[NBT];
__device__ float g_h[2 * 512 * PIX];
__device__ float g_cst[2 * 512 * PIX];
__device__ float g_gates0[2 * 2048 * PIX];
__device__ float g_part[2400000];                 // max(8*200704, 2*44*512*49)
__device__ float g_houts[TSEG * 2 * 512];
__device__ float g_tmphc[2 * 2048 * PIX];
__device__ float g_bnc1[4 * 2048];

// ===================== split-fp16 buffers (zero-init at module load) ==========
__device__ __half g_axt_h[(size_t)AM * K18],  g_axt_l[(size_t)AM * K18];
__device__ __half g_ay1_h[(size_t)AM * K9],   g_ay1_l[(size_t)AM * K9];
__device__ __half g_sa_h[(size_t)128 * K18],  g_sa_l[(size_t)128 * K18];
__device__ __half g_slh_h[(size_t)128 * K45], g_slh_l[(size_t)128 * K45];
__device__ __half g_wmk1_h[(size_t)1024 * K18];
__device__ __half g_wmk2_h[(size_t)512 * K9];
__device__ __half g_wgx_h[(size_t)2048 * K18];
__device__ __half g_whc1_h[(size_t)2048 * K18];
__device__ __half g_w2h_h[(size_t)512 * K9];
__device__ __half g_w2c_h[(size_t)512 * K9];
__device__ __half g_wlh_h[(size_t)2048 * K45], g_wlh_l[(size_t)2048 * K45];

// ===================== base-ISA tensor helpers (sm_80+) =====================
__device__ __forceinline__ uint32_t smem_u32(const void* p) {
    uint32_t a;
    asm("{ .reg .u64 t; cvta.to.shared.u64 t, %1; cvt.u32.u64 %0, t; }" : "=r"(a) : "l"(p));
    return a;
}
__device__ __forceinline__ void ldsm4(uint32_t* r, uint32_t addr) {
    asm volatile("ldmatrix.sync.aligned.m8n8.x4.shared.b16 {%0,%1,%2,%3}, [%4];"
        : "=r"(r[0]), "=r"(r[1]), "=r"(r[2]), "=r"(r[3]) : "r"(addr));
}
__device__ __forceinline__ void mma16816(float* d, const uint32_t* a, const uint32_t* b) {
    asm volatile(
        "mma.sync.aligned.m16n8k16.row.col.f32.f16.f16.f32 "
        "{%0,%1,%2,%3}, {%4,%5,%6,%7}, {%8,%9}, {%0,%1,%2,%3};"
        : "+f"(d[0]), "+f"(d[1]), "+f"(d[2]), "+f"(d[3])
        : "r"(a[0]), "r"(a[1]), "r"(a[2]), "r"(a[3]), "r"(b[0]), "r"(b[1]));
}
#define CP_COMMIT() asm volatile("cp.async.commit_group;" ::: "memory")

__device__ __forceinline__ void split_h(float v, __half& h, __half& l) {
    h = __float2half_rn(v);
    l = __float2half_rn(v - __half2float(h));
}

// ===================== split-fp16 mma.sync GEMM =====================
// NT = tiles per stage: 3 -> D = (Ahi+Alo) @ Bhi^T   (2 mma terms, feed-forward)
//                       4 -> D = Ahi@Bhi + Ahi@Blo + Alo@Bhi (3 terms, recurrent)
// grid (N/128, ceil(M/128), ksplit), block 256 (8 warps, 2x4 -> 64x32/warp).
// K-chunk 64 (128B rows, XOR-16B swizzle), 3-stage cp.async ring.
// postop: 0 raw fp32, 1 BN+ReLU fp32, 2 BN+ReLU scattered split-fp16 im2col.
template<int NT>
__global__ void __launch_bounds__(256, 1) gemm_mma_k(
    const __half* __restrict__ Ahi, const __half* __restrict__ Alo,
    const __half* __restrict__ Bhi, const __half* __restrict__ Blo,
    float* __restrict__ outp, int K, int Ktile, int Mreal, int OCtot,
    const float* __restrict__ bn, int postop, long long partChunk,
    __half* __restrict__ ic_h, __half* __restrict__ ic_l)
{
    extern __shared__ char dsm[];           // 3 stages x NT x 16KB
    __shared__ float s_sc[128], s_sh[128];
    const uint32_t STG = (uint32_t)NT * 16384u;

    int tid = threadIdx.x, lane = tid & 31, wid = tid >> 5;
    int wm = wid & 1, wn = wid >> 1;
    uint32_t sbase = smem_u32(dsm);

    int n0 = blockIdx.x * 128;
    int m0 = blockIdx.y * 128;
    long long kc0 = (long long)blockIdx.z * Ktile;
    int nChunks = Ktile / 64;

    const __half* tbase[4];
    tbase[0] = Ahi + (size_t)m0 * K + kc0;
    tbase[1] = Alo + (size_t)m0 * K + kc0;
    tbase[2] = Bhi + (size_t)n0 * K + kc0;
    tbase[3] = (NT == 4) ? Blo + (size_t)n0 * K + kc0 : tbase[2];

    auto load_chunk = [&](int c, int stg) {
        uint32_t dbase = sbase + (uint32_t)stg * STG;
#pragma unroll
        for (int j = 0; j < NT * 4; j++) {
            int tile = j >> 2;
            int within = ((j & 3) << 8) + tid;      // 0..1023
            int r = within >> 3, cs = within & 7;
            const void* g = tbase[tile] + (size_t)c * 64 + (size_t)r * K + cs * 8;
            uint32_t so = dbase + (uint32_t)tile * 16384u
                        + (uint32_t)(r * 128 + ((cs * 16) ^ ((r & 7) * 16)));
            asm volatile("cp.async.cg.shared.global [%0], [%1], 16;" :: "r"(so), "l"(g));
        }
    };

    float d[4][4][4];
#pragma unroll
    for (int a = 0; a < 4; a++)
#pragma unroll
        for (int b = 0; b < 4; b++)
#pragma unroll
            for (int c = 0; c < 4; c++) d[a][b][c] = 0.f;

    if (nChunks > 0) { load_chunk(0, 0); CP_COMMIT(); }
    if (nChunks > 1) { load_chunk(1, 1); CP_COMMIT(); }

    for (int c = 0; c < nChunks; c++) {
        if (c + 1 < nChunks) asm volatile("cp.async.wait_group 1;" ::: "memory");
        else                 asm volatile("cp.async.wait_group 0;" ::: "memory");
        __syncthreads();
        if (c + 2 < nChunks) { load_chunk(c + 2, (c + 2) % 3); CP_COMMIT(); }

        int stg = c % 3;
        uint32_t sAh = sbase + (uint32_t)stg * STG;
        uint32_t sAl = sAh + 16384u;
        uint32_t sBh = sAh + 32768u;
        uint32_t sBl = sAh + 49152u;

#pragma unroll
        for (int k16 = 0; k16 < 4; k16++) {
            uint32_t ah[4][4], al[4][4], bh[4][2], bl[4][2];
#pragma unroll
            for (int mt = 0; mt < 4; mt++) {
                uint32_t r = (uint32_t)(wm * 64 + mt * 16 + (lane & 15));
                uint32_t cby = (uint32_t)(k16 * 32 + ((lane >> 4) << 4));
                uint32_t off = r * 128 + (cby ^ ((r & 7) << 4));
                ldsm4(ah[mt], sAh + off);
                ldsm4(al[mt], sAl + off);
            }
#pragma unroll
            for (int p = 0; p < 2; p++) {
                uint32_t r = (uint32_t)(wn * 32 + p * 16 + (((lane >> 4) & 1) << 3) + (lane & 7));
                uint32_t cby = (uint32_t)(k16 * 32 + (((lane >> 3) & 1) << 4));
                uint32_t off = r * 128 + (cby ^ ((r & 7) << 4));
                uint32_t t4[4];
                ldsm4(t4, sBh + off);
                bh[2 * p][0] = t4[0]; bh[2 * p][1] = t4[1];
                bh[2 * p + 1][0] = t4[2]; bh[2 * p + 1][1] = t4[3];
                if (NT == 4) {
                    ldsm4(t4, sBl + off);
                    bl[2 * p][0] = t4[0]; bl[2 * p][1] = t4[1];
                    bl[2 * p + 1][0] = t4[2]; bl[2 * p + 1][1] = t4[3];
                }
            }
#pragma unroll
            for (int mt = 0; mt < 4; mt++)
#pragma unroll
                for (int nt = 0; nt < 4; nt++) {
                    mma16816(d[mt][nt], ah[mt], bh[nt]);
                    mma16816(d[mt][nt], al[mt], bh[nt]);
                    if (NT == 4) mma16816(d[mt][nt], ah[mt], bl[nt]);
                }
        }
        __syncthreads();
    }

    if (postop >= 1 && tid < 128) {
        int oc = n0 + tid;
        float g = bn[oc], b = bn[OCtot + oc], m = bn[2 * OCtot + oc], v = bn[3 * OCtot + oc];
        float sc = g * rsqrtf(v + 1e-5f);
        s_sc[tid] = sc;
        s_sh[tid] = b - m * sc;
    }
    __syncthreads();

    if (postop == 2) {
        // BN+ReLU, then scatter split-fp16 into next conv's im2col operand.
        int Kdst = OCtot * 9;
#pragma unroll
        for (int mt = 0; mt < 4; mt++) {
#pragma unroll
            for (int nt = 0; nt < 4; nt++) {
                int ln = wn * 32 + nt * 8 + 2 * (lane & 3);
                int r0 = m0 + wm * 64 + mt * 16 + (lane >> 2);
#pragma unroll
                for (int half = 0; half < 2; half++) {
                    int mrow = r0 + half * 8;
                    if (mrow < Mreal) {
                        int img = mrow / 49, p = mrow - img * 49;
                        float v0 = fmaxf(d[mt][nt][half * 2 + 0] * s_sc[ln] + s_sh[ln], 0.f);
                        float v1 = fmaxf(d[mt][nt][half * 2 + 1] * s_sc[ln + 1] + s_sh[ln + 1], 0.f);
                        __half2 hh, ll;
                        split_h(v0, hh.x, ll.x);
                        split_h(v1, hh.y, ll.y);
                        int qh = p / 7, qw = p - qh * 7;
                        int oc = n0 + ln;
#pragma unroll
                        for (int kk = 0; kk < 9; kk++) {
                            int oh = qh - (kk / 3 - 1), ow = qw - (kk % 3 - 1);
                            if (oh >= 0 && oh < 7 && ow >= 0 && ow < 7) {
                                size_t o = (size_t)(img * 49 + oh * 7 + ow) * Kdst + kk * OCtot + oc;
                                *(__half2*)(ic_h + o) = hh;
                                *(__half2*)(ic_l + o) = ll;
                            }
                        }
                    }
                }
            }
        }
        return;
    }

    float* obase0 = outp + (size_t)blockIdx.z * partChunk;
#pragma unroll
    for (int mt = 0; mt < 4; mt++) {
#pragma unroll
        for (int nt = 0; nt < 4; nt++) {
            int ln = wn * 32 + nt * 8 + 2 * (lane & 3);
            int r0 = m0 + wm * 64 + mt * 16 + (lane >> 2);
#pragma unroll
            for (int half = 0; half < 2; half++) {
                int mrow = r0 + half * 8;
                if (mrow < Mreal) {
                    int img = mrow / 49, p = mrow - img * 49;
                    float* ob = obase0 + ((size_t)img * OCtot + n0) * 49 + p;
                    float v0 = d[mt][nt][half * 2 + 0];
                    float v1 = d[mt][nt][half * 2 + 1];
                    if (postop) {
                        v0 = fmaxf(v0 * s_sc[ln] + s_sh[ln], 0.f);
                        v1 = fmaxf(v1 * s_sc[ln + 1] + s_sh[ln + 1], 0.f);
                    }
                    ob[(size_t)ln * 49] = v0;
                    ob[(size_t)(ln + 1) * 49] = v1;
                }
            }
        }
    }
}

// ===================== im2col (fp32 (img,CHtot,49) -> split fp16) =====================
__global__ void im2col_k(const float* __restrict__ in, int CHtot, int c0, int IC, int nRows,
                         __half* __restrict__ hi, __half* __restrict__ lo)
{
    int ICp = IC >> 1;
    long long idx = (long long)blockIdx.x * blockDim.x + threadIdx.x;
    long long tot = (long long)nRows * 9 * ICp;
    if (idx >= tot) return;
    int icp = (int)(idx % ICp);
    long long r2 = idx / ICp;
    int kk = (int)(r2 % 9);
    int row = (int)(r2 / 9);
    int img = row / 49, p = row - img * 49;
    int oh = p / 7, ow = p - oh * 7;
    int ih = oh + kk / 3 - 1, iw = ow + kk % 3 - 1;
    bool valid = (ih >= 0) && (ih < 7) && (iw >= 0) && (iw < 7);
    int q = valid ? (ih * 7 + iw) : 0;
    int ic = icp * 2;
    const float* base = in + ((size_t)img * CHtot + c0 + ic) * PIX + q;
    float v0 = valid ? base[0] : 0.f;
    float v1 = valid ? base[PIX] : 0.f;
    __half2 hh, ll;
    split_h(v0, hh.x, ll.x);
    split_h(v1, hh.y, ll.y);
    size_t o = (size_t)row * (IC * 9) + (size_t)kk * IC + ic;
    *(__half2*)(hi + o) = hh;
    *(__half2*)(lo + o) = ll;
}

// im2col reading x (B, 2048, T, 7, 7) directly (fused transpose)
__global__ void im2colx_k(const float* __restrict__ x,
                          __half* __restrict__ hi, __half* __restrict__ lo)
{
    const int ICp = 1024;
    long long idx = (long long)blockIdx.x * blockDim.x + threadIdx.x;
    long long tot = (long long)2156 * 9 * ICp;
    if (idx >= tot) return;
    int icp = (int)(idx % ICp);
    long long r2 = idx / ICp;
    int kk = (int)(r2 % 9);
    int row = (int)(r2 / 9);
    int img = row / 49, p = row - img * 49;
    int b = img / TSEG, t = img - b * TSEG;
    int oh = p / 7, ow = p - oh * 7;
    int ih = oh + kk / 3 - 1, iw = ow + kk % 3 - 1;
    bool valid = (ih >= 0) && (ih < 7) && (iw >= 0) && (iw < 7);
    int q = valid ? (ih * 7 + iw) : 0;
    int ic = icp * 2;
    const float* base = x + (((size_t)(b * 2048 + ic) * TSEG) + t) * PIX + q;
    float v0 = valid ? base[0] : 0.f;
    float v1 = valid ? base[(size_t)TSEG * PIX] : 0.f;
    __half2 hh, ll;
    split_h(v0, hh.x, ll.x);
    split_h(v1, hh.y, ll.y);
    size_t o = (size_t)row * K18 + (size_t)kk * 2048 + ic;
    *(__half2*)(hi + o) = hh;
    *(__half2*)(lo + o) = ll;
}

// weight repack via smem transpose: dst[oc][kk*IC+ic] = src[(oc*srcStride+c0+ic)*9+kk]
// hi always; lo only if non-null. grid (OC, IC/256), block 128
__global__ void repack2_k(const float* __restrict__ src, int srcStride, int c0, int IC,
                          __half* __restrict__ hi, __half* __restrict__ lo)
{
    __shared__ float s[2304];
    int oc = blockIdx.x, ic0 = blockIdx.y * 256, tid = threadIdx.x;
    const float* base = src + ((size_t)oc * srcStride + c0 + ic0) * 9;
    for (int i = tid; i < 2304; i += 128) s[i] = base[i];
    __syncthreads();
    size_t dbase = (size_t)oc * ((size_t)IC * 9) + ic0 + 2 * tid;
#pragma unroll
    for (int kk = 0; kk < 9; kk++) {
        __half2 hh, ll;
        split_h(s[(2 * tid) * 9 + kk], hh.x, ll.x);
        split_h(s[(2 * tid + 1) * 9 + kk], hh.y, ll.y);
        size_t o = dbase + (size_t)kk * IC;
        *(__half2*)(hi + o) = hh;
        if (lo) *(__half2*)(lo + o) = ll;
    }
}

__global__ void bnconcat_k(const float* __restrict__ a, const float* __restrict__ b,
                           float* __restrict__ dst)
{
    int i = blockIdx.x * blockDim.x + threadIdx.x;
    if (i >= 4 * 2048) return;
    int pr = i / 2048, j = i - pr * 2048;
    dst[i] = (j < 1024) ? a[pr * 1024 + j] : b[pr * 1024 + (j - 1024)];
}

// ===================== small kernels =====================
__global__ void finish_k(const float* __restrict__ part, int nsplit, int chunk,
                         const float* __restrict__ bn, float* __restrict__ out,
                         int OC, int total, int postop)
{
    int i = blockIdx.x * blockDim.x + threadIdx.x;
    if (i >= total) return;
    float s = 0.f;
    for (int ks = 0; ks < nsplit; ks++) s += part[(size_t)ks * chunk + i];
    if (postop == 1) {
        int oc = (i / PIX) % OC;
        float g = bn[oc], b = bn[OC + oc], m = bn[2 * OC + oc], v = bn[3 * OC + oc];
        s = (s - m) * g * rsqrtf(v + 1e-5f) + b;
        s = fmaxf(s, 0.f);
    }
    out[i] = s;
}

__global__ void mask_final_k(const float* __restrict__ y2, const float* __restrict__ w3,
                             float* __restrict__ mask, float* __restrict__ outmask)
{
    int n = blockIdx.x;
    int p = threadIdx.x, g = threadIdx.y;
    int oh = p / 7, ow = p - oh * 7;
    float s = 0.f;
    for (int ic = g; ic < 512; ic += 8) {
        const float* row = y2 + ((size_t)n * 512 + ic) * PIX;
        const float* wr = w3 + ic * 9;
#pragma unroll
        for (int kh = 0; kh < 3; kh++)
#pragma unroll
            for (int kw = 0; kw < 3; kw++) {
                int ih = oh + kh - 1, iw = ow + kw - 1;
                if (ih >= 0 && ih < 7 && iw >= 0 && iw < 7)
                    s += row[ih * 7 + iw] * wr[kh * 3 + kw];
            }
    }
    __shared__ float red[8][49];
    red[g][p] = s;
    __syncthreads();
    if (g == 0) {
        float tot = 0.f;
#pragma unroll
        for (int q = 0; q < 8; q++) tot += red[q][p];
        float m = 1.f / (1.f + expf(-tot));
        mask[n * PIX + p] = m;
        outmask[n * PIX + p] = m;
    }
}

// mx[(bt,c,p)] = x[(b,c,t,p)] * mask[bt,p]   (fused transpose)
__global__ void mx_k(const float* __restrict__ x, const float* __restrict__ mask, float* __restrict__ mx) {
    int i = blockIdx.x * blockDim.x + threadIdx.x;
    const int total = NBT * 2048 * PIX;
    if (i >= total) return;
    int p = i % PIX;
    int c = (i / PIX) % 2048;
    int bt = i / (PIX * 2048);
    int b = bt / TSEG, t = bt - b * TSEG;
    mx[i] = x[(((size_t)(b * 2048 + c)) * TSEG + t) * PIX + p] * mask[bt * PIX + p];
}

__global__ void meanx_k(const float* __restrict__ mx, float* __restrict__ meanx) {
    int i = blockIdx.x * blockDim.x + threadIdx.x;
    const int inner = 2048 * PIX;
    if (i >= 2 * inner) return;
    int b = i / inner, r = i - b * inner;
    float s = 0.f;
    for (int t = 0; t < TSEG; t++) s += mx[((size_t)(b * TSEG + t)) * inner + r];
    meanx[i] = s * (1.f / (float)TSEG);
}

__global__ void xin_k(const float* __restrict__ mx, const float* __restrict__ aw,
                      float* __restrict__ xin)
{
    int i = blockIdx.x * blockDim.x + threadIdx.x;
    const int inner = 2048 * PIX;
    if (i >= 2 * inner) return;
    int b = i / inner, r = i - b * inner;
    float s = 0.f;
    for (int t = 0; t < TSEG; t++)
        s += aw[b * TSEG + t] * mx[((size_t)(b * TSEG + t)) * inner + r];
    xin[i] = s;
}

__global__ void mxc_k(const float* __restrict__ mx, float* __restrict__ mxc) {
    int i = blockIdx.x * blockDim.x + threadIdx.x;
    if (i >= NBT * 2048) return;
    const float* row = mx + (size_t)i * PIX;
    float s = 0.f;
    for (int p = 0; p < PIX; p++) s += row[p];
    mxc[i] = s * (1.f / (float)PIX);
}

__global__ void attfea_k(const float* __restrict__ mxc, const float* __restrict__ wf,
                         float* __restrict__ attfea)
{
    int bt = blockIdx.x;
    int tid = threadIdx.x;
    __shared__ float sr[256];
    float s = 0.f;
    for (int c = tid; c < 2048; c += 256) s += mxc[bt * 2048 + c] * wf[c];
    sr[tid] = s;
    __syncthreads();
    for (int st = 128; st > 0; st >>= 1) {
        if (tid < st) sr[tid] += sr[tid + st];
        __syncthreads();
    }
    if (tid == 0) attfea[bt] = sr[0];
}

__global__ void aw_k(const float* __restrict__ attfea, float* __restrict__ aw,
                     float* __restrict__ out_aws)
{
    int b = threadIdx.x;
    if (b >= 2) return;
    float m = -1e30f;
    for (int t = 0; t < TSEG; t++) m = fmaxf(m, attfea[b * TSEG + t]);
    float sum = 0.f;
    for (int t = 0; t < TSEG; t++) sum += expf(attfea[b * TSEG + t] - m);
    for (int t = 0; t < TSEG; t++) {
        float a = expf(attfea[b * TSEG + t] - m) / sum;
        aw[b * TSEG + t] = a;
        out_aws[b * TSEG + t] = a;
    }
}

__global__ void ginit8_k(const float* __restrict__ part, const float* __restrict__ lstm_b,
                         float* __restrict__ gates0)
{
    int i = blockIdx.x * blockDim.x + threadIdx.x;
    const int total = 2 * 2048 * PIX;
    if (i >= total) return;
    int oc = (i / PIX) % 2048;
    float s = lstm_b[oc];
#pragma unroll
    for (int ks = 0; ks < 8; ks++) s += part[(size_t)ks * total + i];
    gates0[i] = s;
}

// pointwise LSTM update + spatial mean + fused scatter of h2 into next step's
// im2col A-operand (invalid slots stay zero from module init / seed im2col).
__global__ void lstm_point_k(const float* __restrict__ gates0, const float* __restrict__ part,
                             float* __restrict__ h, float* __restrict__ cst,
                             float* __restrict__ houts, int t,
                             __half* __restrict__ slh_h, __half* __restrict__ slh_l)
{
    int b = blockIdx.x;
    int c = blockIdx.y * 8 + threadIdx.y;
    int p = threadIdx.x;
    size_t base = ((size_t)b * 2048) * PIX + p;
    float gi = gates0[base + (size_t)c * PIX];
    float gf = gates0[base + (size_t)(512 + c) * PIX];
    float go = gates0[base + (size_t)(1024 + c) * PIX];
    float gg = gates0[base + (size_t)(1536 + c) * PIX];
#pragma unroll
    for (int ks = 0; ks < 8; ks++) {
        size_t pb = ((size_t)(ks * 2 + b) * 2048) * PIX + p;
        gi += part[pb + (size_t)c * PIX];
        gf += part[pb + (size_t)(512 + c) * PIX];
        go += part[pb + (size_t)(1024 + c) * PIX];
        gg += part[pb + (size_t)(1536 + c) * PIX];
    }
    size_t hidx = ((size_t)b * 512 + c) * PIX + p;
    float cprev = cst[hidx];
    float si = 1.f / (1.f + expf(-gi));
    float sf = 1.f / (1.f + expf(-gf));
    float so = 1.f / (1.f + expf(-go));
    float c2 = sf * cprev + si * tanhf(gg);
    float h2 = so * tanhf(c2);
    cst[hidx] = c2;
    h[hidx] = h2;

    {
        __half hh, ll;
        split_h(h2, hh, ll);
        int qh = p / 7, qw = p - qh * 7;
#pragma unroll
        for (int kk = 0; kk < 9; kk++) {
            int oh = qh - (kk / 3 - 1), ow = qw - (kk % 3 - 1);
            if (oh >= 0 && oh < 7 && ow >= 0 && ow < 7) {
                size_t o = (size_t)(b * 49 + oh * 7 + ow) * K45 + kk * 512 + c;
                slh_h[o] = hh;
                slh_l[o] = ll;
            }
        }
    }

    __shared__ float red[8][49];
    red[threadIdx.y][p] = h2;
    __syncthreads();
    if (p == 0) {
        float s = 0.f;
        for (int q = 0; q < 49; q++) s += red[threadIdx.y][q];
        houts[((size_t)t * 2 + b) * 512 + c] = s * (1.f / (float)PIX);
    }
}

__global__ void final_k(const float* __restrict__ houts, const float* __restrict__ fc_w,
                        const float* __restrict__ fc_b, float* __restrict__ out)
{
    __shared__ float om[1024];
    int tid = threadIdx.x;
    for (int i = tid; i < 1024; i += 512) {
        int b = i / 512, c = i - b * 512;
        float s = 0.f;
        for (int t = 0; t < TSEG; t++) s += houts[((size_t)t * 2 + b) * 512 + c];
        om[i] = s * (1.f / (float)TSEG);
    }
    __syncthreads();
    for (int i = tid; i < 202; i += 512) {
        int b = i / 101, k = i - b * 101;
        float s = fc_b[k];
        for (int c = 0; c < 512; c++) s += om[b * 512 + c] * fc_w[k * 512 + c];
        out[i] = s;
    }
    if (tid == 0) { out[2402] = 0.f; out[2403] = 0.f; }
}

// ===================== host =====================
static float* symaddr(const void* sym) { void* p = nullptr; cudaGetSymbolAddress(&p, sym); return (float*)p; }
static __half* symaddrh(const void* sym) { void* p = nullptr; cudaGetSymbolAddress(&p, sym); return (__half*)p; }

#define GEMM_SMEM3 (3 * 49152)
#define GEMM_SMEM4 (3 * 65536)

// 2-term feed-forward GEMM (A split, B hi only)
static inline void launch_gemm2(const __half* Ah, const __half* Al, const __half* Bh,
                                float* out, int K, int ksplit, int Mreal, int N,
                                const float* bn, int postop, long long partChunk,
                                __half* ich = nullptr, __half* icl = nullptr)
{
    dim3 grid(N / 128, (Mreal + 127) / 128, ksplit);
    gemm_mma_k<3><<<grid, 256, GEMM_SMEM3>>>(Ah, Al, Bh, nullptr, out, K, K / ksplit, Mreal, N,
                                             bn, postop, partChunk, ich, icl);
}

// 3-term recurrent GEMM (A split, B split)
static inline void launch_gemm3(const __half* Ah, const __half* Al,
                                const __half* Bh, const __half* Bl,
                                float* out, int K, int ksplit, int Mreal, int N,
                                long long partChunk)
{
    dim3 grid(N / 128, (Mreal + 127) / 128, ksplit);
    gemm_mma_k<4><<<grid, 256, GEMM_SMEM4>>>(Ah, Al, Bh, Bl, out, K, K / ksplit, Mreal, N,
                                             nullptr, 0, partChunk, nullptr, nullptr);
}

extern "C" void kernel_launch(void* const* d_in, const int* in_sizes, int n_in,
                              void* d_out, int out_size)
{
    const float* x      = (const float*)d_in[0];
    const float* wf     = (const float*)d_in[1];
    const float* fc_w   = (const float*)d_in[3];
    const float* fc_b   = (const float*)d_in[4];
    const float* h0_w1  = (const float*)d_in[5];
    const float* h0_bn1 = (const float*)d_in[6];
    const float* h0_w2  = (const float*)d_in[7];
    const float* h0_bn2 = (const float*)d_in[8];
    const float* c0_w1  = (const float*)d_in[9];
    const float* c0_bn1 = (const float*)d_in[10];
    const float* c0_w2  = (const float*)d_in[11];
    const float* c0_bn2 = (const float*)d_in[12];
    const float* mk_w1  = (const float*)d_in[13];
    const float* mk_bn1 = (const float*)d_in[14];
    const float* mk_w2  = (const float*)d_in[15];
    const float* mk_bn2 = (const float*)d_in[16];
    const float* mk_w3  = (const float*)d_in[17];
    const float* lstm_w = (const float*)d_in[18];
    const float* lstm_b = (const float*)d_in[19];
    float* out = (float*)d_out;

    cudaFuncSetAttribute(gemm_mma_k<3>, cudaFuncAttributeMaxDynamicSharedMemorySize, GEMM_SMEM3);
    cudaFuncSetAttribute(gemm_mma_k<4>, cudaFuncAttributeMaxDynamicSharedMemorySize, GEMM_SMEM4);

    float *mx = symaddr(g_mx), *xin = symaddr(g_xin);
    float *y2 = symaddr(g_y2), *mask = symaddr(g_mask);
    float *meanx = symaddr(g_meanx), *mxc = symaddr(g_mxc), *attfea = symaddr(g_attfea);
    float *aw = symaddr(g_aw), *h = symaddr(g_h), *cst = symaddr(g_cst);
    float *gates0 = symaddr(g_gates0), *part = symaddr(g_part), *houts = symaddr(g_houts);
    float *tmphc = symaddr(g_tmphc), *bnc1 = symaddr(g_bnc1);

    __half *axt_h = symaddrh(g_axt_h), *axt_l = symaddrh(g_axt_l);
    __half *ay1_h = symaddrh(g_ay1_h), *ay1_l = symaddrh(g_ay1_l);
    __half *sa_h = symaddrh(g_sa_h),   *sa_l = symaddrh(g_sa_l);
    __half *slh_h = symaddrh(g_slh_h), *slh_l = symaddrh(g_slh_l);
    __half *wmk1_h = symaddrh(g_wmk1_h);
    __half *wmk2_h = symaddrh(g_wmk2_h);
    __half *wgx_h = symaddrh(g_wgx_h);
    __half *whc1_h = symaddrh(g_whc1_h);
    __half *w2h_h = symaddrh(g_w2h_h);
    __half *w2c_h = symaddrh(g_w2c_h);
    __half *wlh_h = symaddrh(g_wlh_h), *wlh_l = symaddrh(g_wlh_l);

    const int ETOT = NBT * 2048 * PIX;
    dim3 cb(49, 8);
    auto blk = [](long long n) { return (unsigned)((n + 255) / 256); };

    // ---- weight repacks (hi only for feed-forward; hi+lo for recurrent) ----
    repack2_k<<<dim3(1024, 8), 128>>>(mk_w1, 2048, 0, 2048, wmk1_h, nullptr);
    repack2_k<<<dim3(512, 4), 128>>>(mk_w2, 1024, 0, 1024, wmk2_h, nullptr);
    repack2_k<<<dim3(2048, 8), 128>>>(lstm_w, 2560, 0, 2048, wgx_h, nullptr);
    repack2_k<<<dim3(2048, 2), 128>>>(lstm_w, 2560, 2048, 512, wlh_h, wlh_l);
    repack2_k<<<dim3(1024, 8), 128>>>(h0_w1, 2048, 0, 2048, whc1_h, nullptr);
    repack2_k<<<dim3(1024, 8), 128>>>(c0_w1, 2048, 0, 2048, whc1_h + (size_t)1024 * K18, nullptr);
    repack2_k<<<dim3(512, 4), 128>>>(h0_w2, 1024, 0, 1024, w2h_h, nullptr);
    repack2_k<<<dim3(512, 4), 128>>>(c0_w2, 1024, 0, 1024, w2c_h, nullptr);
    bnconcat_k<<<32, 256>>>(h0_bn1, c0_bn1, bnc1);

    // ---- mask path: conv1 epilogue scatters im2col for conv2 ----
    im2colx_k<<<blk((long long)2156 * 9 * 1024), 256>>>(x, axt_h, axt_l);
    launch_gemm2(axt_h, axt_l, wmk1_h, part, K18, 1, 2156, 1024, mk_bn1, 2, 0, ay1_h, ay1_l);
    launch_gemm2(ay1_h, ay1_l, wmk2_h, part, K9, 2, 2156, 512, nullptr, 0,
                 (long long)44 * 512 * PIX);
    finish_k<<<blk((long long)44 * 512 * PIX), 256>>>(part, 2, 44 * 512 * PIX, mk_bn2, y2,
                                                      512, 44 * 512 * PIX, 1);
    mask_final_k<<<NBT, cb>>>(y2, mk_w3, mask, out + 246);

    // ---- masked features + attention (constant over steps) ----
    mx_k<<<blk(ETOT), 256>>>(x, mask, mx);
    meanx_k<<<blk(2 * 2048 * PIX), 256>>>(mx, meanx);
    mxc_k<<<blk(NBT * 2048), 256>>>(mx, mxc);
    attfea_k<<<NBT, 256>>>(mxc, wf, attfea);
    aw_k<<<1, 32>>>(attfea, aw, out + 202);

    // ---- xin = sum_t aw[t]*mx_t, one conv_x GEMM (linearity) ----
    xin_k<<<blk(2 * 2048 * PIX), 256>>>(mx, aw, xin);
    im2col_k<<<blk((long long)98 * 9 * 1024), 256>>>(xin, 2048, 0, 2048, 98, sa_h, sa_l);
    launch_gemm2(sa_h, sa_l, wgx_h, part, K18, 8, 98, 2048, nullptr, 0, (long long)2 * 2048 * PIX);
    ginit8_k<<<blk(2 * 2048 * PIX), 256>>>(part, lstm_b, gates0);

    // ---- h0/c0 init ----
    im2col_k<<<blk((long long)98 * 9 * 1024), 256>>>(meanx, 2048, 0, 2048, 98, sa_h, sa_l);
    launch_gemm2(sa_h, sa_l, whc1_h, part, K18, 8, 98, 2048, nullptr, 0, (long long)2 * 2048 * PIX);
    finish_k<<<blk(2 * 2048 * PIX), 256>>>(part, 8, 2 * 2048 * PIX, bnc1, tmphc, 2048, 2 * 2048 * PIX, 1);

    im2col_k<<<blk((long long)98 * 9 * 512), 256>>>(tmphc, 2048, 0, 1024, 98, sa_h, sa_l);
    launch_gemm2(sa_h, sa_l, w2h_h, part, K9, 4, 98, 512, nullptr, 0, (long long)2 * 512 * PIX);
    finish_k<<<blk(2 * 512 * PIX), 256>>>(part, 4, 2 * 512 * PIX, h0_bn2, h, 512, 2 * 512 * PIX, 1);

    im2col_k<<<blk((long long)98 * 9 * 512), 256>>>(tmphc, 2048, 1024, 1024, 98, sa_h, sa_l);
    launch_gemm2(sa_h, sa_l, w2c_h, part, K9, 4, 98, 512, nullptr, 0, (long long)2 * 512 * PIX);
    finish_k<<<blk(2 * 512 * PIX), 256>>>(part, 4, 2 * 512 * PIX, c0_bn2, cst, 512, 2 * 512 * PIX, 1);

    // ---- seed im2col for h0, then recurrence (3-term fp16: error must not compound) ----
    im2col_k<<<blk((long long)98 * 9 * 256), 256>>>(h, 512, 0, 512, 98, slh_h, slh_l);
    for (int t = 0; t < TSEG; t++) {
        launch_gemm3(slh_h, slh_l, wlh_h, wlh_l, part, K45, 8, 98, 2048,
                     (long long)2 * 2048 * PIX);
        lstm_point_k<<<dim3(2, 64), cb>>>(gates0, part, h, cst, houts, t, slh_h, slh_l);
    }

    final_k<<<1, 512>>>(houts, fc_w, fc_b, out);
}

// round 12
// speedup vs baseline: 13.6606x; 1.0898x over previous
#include <cuda_runtime.h>
#include <cuda_fp16.h>
#include <cstdint>

// ===================== problem constants =====================
#define TSEG 22
#define NBT  44
#define PIX  49
#define K18  18432     // 9*2048
#define K9   9216      // 9*1024
#define K45  4608      // 9*512
#define AM   2176      // 17*128 pad of 2156

// ===================== fp32 scratch =====================
__device__ float g_mx[(size_t)NBT * 2048 * PIX];
__device__ float g_xin[2 * 2048 * PIX];
__device__ float g_y2[(size_t)NBT * 512 * PIX];
__device__ float g_mask[NBT * PIX];
__device__ float g_meanx[2 * 2048 * PIX];
__device__ float g_mxc[NBT * 2048];
__device__ float g_attfea[NBT];
__device__ float g_aw[NBT];
__device__ float g_h[2 * 512 * PIX];
__device__ float g_cst[2 * 512 * PIX];
__device__ float g_gates0[2 * 2048 * PIX];
__device__ float g_part[2400000];                 // max(8*200704, 2*44*512*49)
__device__ float g_houts[TSEG * 2 * 512];
__device__ float g_tmphc[2 * 2048 * PIX];
__device__ float g_bnc1[4 * 2048];

// ===================== split-fp16 buffers (zero-init at module load) ==========
__device__ __half g_axt_h[(size_t)AM * K18];                       // conv1 A: hi only
__device__ __half g_ay1_h[(size_t)AM * K9],   g_ay1_l[(size_t)AM * K9];
__device__ __half g_sa_h[(size_t)128 * K18],  g_sa_l[(size_t)128 * K18];
__device__ __half g_slh_h[(size_t)128 * K45], g_slh_l[(size_t)128 * K45];
__device__ __half g_wmk1_h[(size_t)1024 * K18];
__device__ __half g_wmk2_h[(size_t)512 * K9];
__device__ __half g_wgx_h[(size_t)2048 * K18];
__device__ __half g_whc1_h[(size_t)2048 * K18];
__device__ __half g_w2h_h[(size_t)512 * K9];
__device__ __half g_w2c_h[(size_t)512 * K9];
__device__ __half g_wlh_h[(size_t)2048 * K45], g_wlh_l[(size_t)2048 * K45];

// ===================== base-ISA tensor helpers (sm_80+) =====================
__device__ __forceinline__ uint32_t smem_u32(const void* p) {
    uint32_t a;
    asm("{ .reg .u64 t; cvta.to.shared.u64 t, %1; cvt.u32.u64 %0, t; }" : "=r"(a) : "l"(p));
    return a;
}
__device__ __forceinline__ void ldsm4(uint32_t* r, uint32_t addr) {
    asm volatile("ldmatrix.sync.aligned.m8n8.x4.shared.b16 {%0,%1,%2,%3}, [%4];"
        : "=r"(r[0]), "=r"(r[1]), "=r"(r[2]), "=r"(r[3]) : "r"(addr));
}
__device__ __forceinline__ void mma16816(float* d, const uint32_t* a, const uint32_t* b) {
    asm volatile(
        "mma.sync.aligned.m16n8k16.row.col.f32.f16.f16.f32 "
        "{%0,%1,%2,%3}, {%4,%5,%6,%7}, {%8,%9}, {%0,%1,%2,%3};"
        : "+f"(d[0]), "+f"(d[1]), "+f"(d[2]), "+f"(d[3])
        : "r"(a[0]), "r"(a[1]), "r"(a[2]), "r"(a[3]), "r"(b[0]), "r"(b[1]));
}
#define CP_COMMIT() asm volatile("cp.async.commit_group;" ::: "memory")

__device__ __forceinline__ void split_h(float v, __half& h, __half& l) {
    h = __float2half_rn(v);
    l = __float2half_rn(v - __half2float(h));
}

// ===================== split-fp16 mma.sync GEMM =====================
// NT = tiles/stage: 2 -> D = Ahi @ Bhi^T                 (1 term)
//                   3 -> D = (Ahi+Alo) @ Bhi^T           (2 terms)
//                   4 -> D = Ahi@Bhi + Alo@Bhi + Ahi@Blo (3 terms)
// grid (N/128, ceil(M/128), ksplit), block 256 (8 warps, 2x4 -> 64x32/warp).
// K-chunk 64 (128B rows, XOR-16B swizzle), 3-stage cp.async ring.
// postop: 0 raw fp32, 1 BN+ReLU fp32, 2 BN+ReLU scattered split-fp16 im2col.
template<int NT>
__global__ void __launch_bounds__(256, 1) gemm_mma_k(
    const __half* __restrict__ Ahi, const __half* __restrict__ Alo,
    const __half* __restrict__ Bhi, const __half* __restrict__ Blo,
    float* __restrict__ outp, int K, int Ktile, int Mreal, int OCtot,
    const float* __restrict__ bn, int postop, long long partChunk,
    __half* __restrict__ ic_h, __half* __restrict__ ic_l)
{
    extern __shared__ char dsm[];           // 3 stages x NT x 16KB
    __shared__ float s_sc[128], s_sh[128];
    const uint32_t STG = (uint32_t)NT * 16384u;
    const uint32_t OFF_BH = (NT == 2) ? 16384u : 32768u;

    int tid = threadIdx.x, lane = tid & 31, wid = tid >> 5;
    int wm = wid & 1, wn = wid >> 1;
    uint32_t sbase = smem_u32(dsm);

    int n0 = blockIdx.x * 128;
    int m0 = blockIdx.y * 128;
    long long kc0 = (long long)blockIdx.z * Ktile;
    int nChunks = Ktile / 64;

    const __half* tbase[4];
    tbase[0] = Ahi + (size_t)m0 * K + kc0;
    if (NT == 2) {
        tbase[1] = Bhi + (size_t)n0 * K + kc0;
    } else {
        tbase[1] = Alo + (size_t)m0 * K + kc0;
        tbase[2] = Bhi + (size_t)n0 * K + kc0;
        if (NT == 4) tbase[3] = Blo + (size_t)n0 * K + kc0;
    }

    auto load_chunk = [&](int c, int stg) {
        uint32_t dbase = sbase + (uint32_t)stg * STG;
#pragma unroll
        for (int j = 0; j < NT * 4; j++) {
            int tile = j >> 2;
            int within = ((j & 3) << 8) + tid;      // 0..1023
            int r = within >> 3, cs = within & 7;
            const void* g = tbase[tile] + (size_t)c * 64 + (size_t)r * K + cs * 8;
            uint32_t so = dbase + (uint32_t)tile * 16384u
                        + (uint32_t)(r * 128 + ((cs * 16) ^ ((r & 7) * 16)));
            asm volatile("cp.async.cg.shared.global [%0], [%1], 16;" :: "r"(so), "l"(g));
        }
    };

    float d[4][4][4];
#pragma unroll
    for (int a = 0; a < 4; a++)
#pragma unroll
        for (int b = 0; b < 4; b++)
#pragma unroll
            for (int c = 0; c < 4; c++) d[a][b][c] = 0.f;

    if (nChunks > 0) { load_chunk(0, 0); CP_COMMIT(); }
    if (nChunks > 1) { load_chunk(1, 1); CP_COMMIT(); }

    for (int c = 0; c < nChunks; c++) {
        if (c + 1 < nChunks) asm volatile("cp.async.wait_group 1;" ::: "memory");
        else                 asm volatile("cp.async.wait_group 0;" ::: "memory");
        __syncthreads();
        if (c + 2 < nChunks) { load_chunk(c + 2, (c + 2) % 3); CP_COMMIT(); }

        int stg = c % 3;
        uint32_t sAh = sbase + (uint32_t)stg * STG;
        uint32_t sAl = sAh + 16384u;
        uint32_t sBh = sAh + OFF_BH;
        uint32_t sBl = sAh + 49152u;

#pragma unroll
        for (int k16 = 0; k16 < 4; k16++) {
            uint32_t ah[4][4], al[4][4], bh[4][2], bl[4][2];
#pragma unroll
            for (int mt = 0; mt < 4; mt++) {
                uint32_t r = (uint32_t)(wm * 64 + mt * 16 + (lane & 15));
                uint32_t cby = (uint32_t)(k16 * 32 + ((lane >> 4) << 4));
                uint32_t off = r * 128 + (cby ^ ((r & 7) << 4));
                ldsm4(ah[mt], sAh + off);
                if (NT >= 3) ldsm4(al[mt], sAl + off);
            }
#pragma unroll
            for (int p = 0; p < 2; p++) {
                uint32_t r = (uint32_t)(wn * 32 + p * 16 + (((lane >> 4) & 1) << 3) + (lane & 7));
                uint32_t cby = (uint32_t)(k16 * 32 + (((lane >> 3) & 1) << 4));
                uint32_t off = r * 128 + (cby ^ ((r & 7) << 4));
                uint32_t t4[4];
                ldsm4(t4, sBh + off);
                bh[2 * p][0] = t4[0]; bh[2 * p][1] = t4[1];
                bh[2 * p + 1][0] = t4[2]; bh[2 * p + 1][1] = t4[3];
                if (NT == 4) {
                    ldsm4(t4, sBl + off);
                    bl[2 * p][0] = t4[0]; bl[2 * p][1] = t4[1];
                    bl[2 * p + 1][0] = t4[2]; bl[2 * p + 1][1] = t4[3];
                }
            }
#pragma unroll
            for (int mt = 0; mt < 4; mt++)
#pragma unroll
                for (int nt = 0; nt < 4; nt++) {
                    mma16816(d[mt][nt], ah[mt], bh[nt]);
                    if (NT >= 3) mma16816(d[mt][nt], al[mt], bh[nt]);
                    if (NT == 4) mma16816(d[mt][nt], ah[mt], bl[nt]);
                }
        }
        __syncthreads();
    }

    if (postop >= 1 && tid < 128) {
        int oc = n0 + tid;
        float g = bn[oc], b = bn[OCtot + oc], m = bn[2 * OCtot + oc], v = bn[3 * OCtot + oc];
        float sc = g * rsqrtf(v + 1e-5f);
        s_sc[tid] = sc;
        s_sh[tid] = b - m * sc;
    }
    __syncthreads();

    if (postop == 2) {
        // BN+ReLU, then scatter split-fp16 into next conv's im2col operand.
        int Kdst = OCtot * 9;
#pragma unroll
        for (int mt = 0; mt < 4; mt++) {
#pragma unroll
            for (int nt = 0; nt < 4; nt++) {
                int ln = wn * 32 + nt * 8 + 2 * (lane & 3);
                int r0 = m0 + wm * 64 + mt * 16 + (lane >> 2);
#pragma unroll
                for (int half = 0; half < 2; half++) {
                    int mrow = r0 + half * 8;
                    if (mrow < Mreal) {
                        int img = mrow / 49, p = mrow - img * 49;
                        float v0 = fmaxf(d[mt][nt][half * 2 + 0] * s_sc[ln] + s_sh[ln], 0.f);
                        float v1 = fmaxf(d[mt][nt][half * 2 + 1] * s_sc[ln + 1] + s_sh[ln + 1], 0.f);
                        __half2 hh, ll;
                        split_h(v0, hh.x, ll.x);
                        split_h(v1, hh.y, ll.y);
                        int qh = p / 7, qw = p - qh * 7;
                        int oc = n0 + ln;
#pragma unroll
                        for (int kk = 0; kk < 9; kk++) {
                            int oh = qh - (kk / 3 - 1), ow = qw - (kk % 3 - 1);
                            if (oh >= 0 && oh < 7 && ow >= 0 && ow < 7) {
                                size_t o = (size_t)(img * 49 + oh * 7 + ow) * Kdst + kk * OCtot + oc;
                                *(__half2*)(ic_h + o) = hh;
                                *(__half2*)(ic_l + o) = ll;
                            }
                        }
                    }
                }
            }
        }
        return;
    }

    float* obase0 = outp + (size_t)blockIdx.z * partChunk;
#pragma unroll
    for (int mt = 0; mt < 4; mt++) {
#pragma unroll
        for (int nt = 0; nt < 4; nt++) {
            int ln = wn * 32 + nt * 8 + 2 * (lane & 3);
            int r0 = m0 + wm * 64 + mt * 16 + (lane >> 2);
#pragma unroll
            for (int half = 0; half < 2; half++) {
                int mrow = r0 + half * 8;
                if (mrow < Mreal) {
                    int img = mrow / 49, p = mrow - img * 49;
                    float* ob = obase0 + ((size_t)img * OCtot + n0) * 49 + p;
                    float v0 = d[mt][nt][half * 2 + 0];
                    float v1 = d[mt][nt][half * 2 + 1];
                    if (postop) {
                        v0 = fmaxf(v0 * s_sc[ln] + s_sh[ln], 0.f);
                        v1 = fmaxf(v1 * s_sc[ln + 1] + s_sh[ln + 1], 0.f);
                    }
                    ob[(size_t)ln * 49] = v0;
                    ob[(size_t)(ln + 1) * 49] = v1;
                }
            }
        }
    }
}

// ===================== im2col (fp32 (img,CHtot,49) -> split fp16) =====================
__global__ void im2col_k(const float* __restrict__ in, int CHtot, int c0, int IC, int nRows,
                         __half* __restrict__ hi, __half* __restrict__ lo)
{
    int ICp = IC >> 1;
    long long idx = (long long)blockIdx.x * blockDim.x + threadIdx.x;
    long long tot = (long long)nRows * 9 * ICp;
    if (idx >= tot) return;
    int icp = (int)(idx % ICp);
    long long r2 = idx / ICp;
    int kk = (int)(r2 % 9);
    int row = (int)(r2 / 9);
    int img = row / 49, p = row - img * 49;
    int oh = p / 7, ow = p - oh * 7;
    int ih = oh + kk / 3 - 1, iw = ow + kk % 3 - 1;
    bool valid = (ih >= 0) && (ih < 7) && (iw >= 0) && (iw < 7);
    int q = valid ? (ih * 7 + iw) : 0;
    int ic = icp * 2;
    const float* base = in + ((size_t)img * CHtot + c0 + ic) * PIX + q;
    float v0 = valid ? base[0] : 0.f;
    float v1 = valid ? base[PIX] : 0.f;
    __half2 hh, ll;
    split_h(v0, hh.x, ll.x);
    split_h(v1, hh.y, ll.y);
    size_t o = (size_t)row * (IC * 9) + (size_t)kk * IC + ic;
    *(__half2*)(hi + o) = hh;
    *(__half2*)(lo + o) = ll;
}

// im2col reading x (B, 2048, T, 7, 7) directly (fused transpose); hi only (conv1 is 1-term)
__global__ void im2colx_k(const float* __restrict__ x, __half* __restrict__ hi)
{
    const int ICp = 1024;
    long long idx = (long long)blockIdx.x * blockDim.x + threadIdx.x;
    long long tot = (long long)2156 * 9 * ICp;
    if (idx >= tot) return;
    int icp = (int)(idx % ICp);
    long long r2 = idx / ICp;
    int kk = (int)(r2 % 9);
    int row = (int)(r2 / 9);
    int img = row / 49, p = row - img * 49;
    int b = img / TSEG, t = img - b * TSEG;
    int oh = p / 7, ow = p - oh * 7;
    int ih = oh + kk / 3 - 1, iw = ow + kk % 3 - 1;
    bool valid = (ih >= 0) && (ih < 7) && (iw >= 0) && (iw < 7);
    int q = valid ? (ih * 7 + iw) : 0;
    int ic = icp * 2;
    const float* base = x + (((size_t)(b * 2048 + ic) * TSEG) + t) * PIX + q;
    float v0 = valid ? base[0] : 0.f;
    float v1 = valid ? base[(size_t)TSEG * PIX] : 0.f;
    __half2 hh;
    hh.x = __float2half_rn(v0);
    hh.y = __float2half_rn(v1);
    size_t o = (size_t)row * K18 + (size_t)kk * 2048 + ic;
    *(__half2*)(hi + o) = hh;
}

// weight repack via smem transpose: dst[oc][kk*IC+ic] = src[(oc*srcStride+c0+ic)*9+kk]
__global__ void repack2_k(const float* __restrict__ src, int srcStride, int c0, int IC,
                          __half* __restrict__ hi, __half* __restrict__ lo)
{
    __shared__ float s[2304];
    int oc = blockIdx.x, ic0 = blockIdx.y * 256, tid = threadIdx.x;
    const float* base = src + ((size_t)oc * srcStride + c0 + ic0) * 9;
    for (int i = tid; i < 2304; i += 128) s[i] = base[i];
    __syncthreads();
    size_t dbase = (size_t)oc * ((size_t)IC * 9) + ic0 + 2 * tid;
#pragma unroll
    for (int kk = 0; kk < 9; kk++) {
        __half2 hh, ll;
        split_h(s[(2 * tid) * 9 + kk], hh.x, ll.x);
        split_h(s[(2 * tid + 1) * 9 + kk], hh.y, ll.y);
        size_t o = dbase + (size_t)kk * IC;
        *(__half2*)(hi + o) = hh;
        if (lo) *(__half2*)(lo + o) = ll;
    }
}

__global__ void bnconcat_k(const float* __restrict__ a, const float* __restrict__ b,
                           float* __restrict__ dst)
{
    int i = blockIdx.x * blockDim.x + threadIdx.x;
    if (i >= 4 * 2048) return;
    int pr = i / 2048, j = i - pr * 2048;
    dst[i] = (j < 1024) ? a[pr * 1024 + j] : b[pr * 1024 + (j - 1024)];
}

// ===================== small kernels =====================
__global__ void finish_k(const float* __restrict__ part, int nsplit, int chunk,
                         const float* __restrict__ bn, float* __restrict__ out,
                         int OC, int total, int postop)
{
    int i = blockIdx.x * blockDim.x + threadIdx.x;
    if (i >= total) return;
    float s = 0.f;
    for (int ks = 0; ks < nsplit; ks++) s += part[(size_t)ks * chunk + i];
    if (postop == 1) {
        int oc = (i / PIX) % OC;
        float g = bn[oc], b = bn[OC + oc], m = bn[2 * OC + oc], v = bn[3 * OC + oc];
        s = (s - m) * g * rsqrtf(v + 1e-5f) + b;
        s = fmaxf(s, 0.f);
    }
    out[i] = s;
}

__global__ void mask_final_k(const float* __restrict__ y2, const float* __restrict__ w3,
                             float* __restrict__ mask, float* __restrict__ outmask)
{
    int n = blockIdx.x;
    int p = threadIdx.x, g = threadIdx.y;
    int oh = p / 7, ow = p - oh * 7;
    float s = 0.f;
    for (int ic = g; ic < 512; ic += 8) {
        const float* row = y2 + ((size_t)n * 512 + ic) * PIX;
        const float* wr = w3 + ic * 9;
#pragma unroll
        for (int kh = 0; kh < 3; kh++)
#pragma unroll
            for (int kw = 0; kw < 3; kw++) {
                int ih = oh + kh - 1, iw = ow + kw - 1;
                if (ih >= 0 && ih < 7 && iw >= 0 && iw < 7)
                    s += row[ih * 7 + iw] * wr[kh * 3 + kw];
            }
    }
    __shared__ float red[8][49];
    red[g][p] = s;
    __syncthreads();
    if (g == 0) {
        float tot = 0.f;
#pragma unroll
        for (int q = 0; q < 8; q++) tot += red[q][p];
        float m = 1.f / (1.f + expf(-tot));
        mask[n * PIX + p] = m;
        outmask[n * PIX + p] = m;
    }
}

// mx[(bt,c,p)] = x[(b,c,t,p)] * mask[bt,p]  + fused per-(bt,c) spatial mean (mxc)
// grid (NBT, 256), block (49, 8)
__global__ void mxmxc_k(const float* __restrict__ x, const float* __restrict__ mask,
                        float* __restrict__ mx, float* __restrict__ mxc)
{
    int bt = blockIdx.x;
    int c = blockIdx.y * 8 + threadIdx.y;
    int p = threadIdx.x;
    int b = bt / TSEG, t = bt - b * TSEG;
    float v = x[(((size_t)(b * 2048 + c)) * TSEG + t) * PIX + p] * mask[bt * PIX + p];
    mx[((size_t)bt * 2048 + c) * PIX + p] = v;
    __shared__ float red[8][49];
    red[threadIdx.y][p] = v;
    __syncthreads();
    if (p == 0) {
        float s = 0.f;
        for (int q = 0; q < 49; q++) s += red[threadIdx.y][q];
        mxc[bt * 2048 + c] = s * (1.f / (float)PIX);
    }
}

// fused: meanx = mean_t(mx), xin = sum_t aw[t]*mx  (single pass over mx)
__global__ void meanxin_k(const float* __restrict__ mx, const float* __restrict__ aw,
                          float* __restrict__ meanx, float* __restrict__ xin)
{
    int i = blockIdx.x * blockDim.x + threadIdx.x;
    const int inner = 2048 * PIX;
    if (i >= 2 * inner) return;
    int b = i / inner, r = i - b * inner;
    float sm = 0.f, sx = 0.f;
    for (int t = 0; t < TSEG; t++) {
        float v = mx[((size_t)(b * TSEG + t)) * inner + r];
        sm += v;
        sx += aw[b * TSEG + t] * v;
    }
    meanx[i] = sm * (1.f / (float)TSEG);
    xin[i] = sx;
}

__global__ void attfea_k(const float* __restrict__ mxc, const float* __restrict__ wf,
                         float* __restrict__ attfea)
{
    int bt = blockIdx.x;
    int tid = threadIdx.x;
    __shared__ float sr[256];
    float s = 0.f;
    for (int c = tid; c < 2048; c += 256) s += mxc[bt * 2048 + c] * wf[c];
    sr[tid] = s;
    __syncthreads();
    for (int st = 128; st > 0; st >>= 1) {
        if (tid < st) sr[tid] += sr[tid + st];
        __syncthreads();
    }
    if (tid == 0) attfea[bt] = sr[0];
}

__global__ void aw_k(const float* __restrict__ attfea, float* __restrict__ aw,
                     float* __restrict__ out_aws)
{
    int b = threadIdx.x;
    if (b >= 2) return;
    float m = -1e30f;
    for (int t = 0; t < TSEG; t++) m = fmaxf(m, attfea[b * TSEG + t]);
    float sum = 0.f;
    for (int t = 0; t < TSEG; t++) sum += expf(attfea[b * TSEG + t] - m);
    for (int t = 0; t < TSEG; t++) {
        float a = expf(attfea[b * TSEG + t] - m) / sum;
        aw[b * TSEG + t] = a;
        out_aws[b * TSEG + t] = a;
    }
}

__global__ void ginit8_k(const float* __restrict__ part, const float* __restrict__ lstm_b,
                         float* __restrict__ gates0)
{
    int i = blockIdx.x * blockDim.x + threadIdx.x;
    const int total = 2 * 2048 * PIX;
    if (i >= total) return;
    int oc = (i / PIX) % 2048;
    float s = lstm_b[oc];
#pragma unroll
    for (int ks = 0; ks < 8; ks++) s += part[(size_t)ks * total + i];
    gates0[i] = s;
}

// pointwise LSTM update + spatial mean + fused scatter of h2 into next step's
// im2col A-operand (invalid slots stay zero from module init / seed im2col).
__global__ void lstm_point_k(const float* __restrict__ gates0, const float* __restrict__ part,
                             float* __restrict__ h, float* __restrict__ cst,
                             float* __restrict__ houts, int t,
                             __half* __restrict__ slh_h, __half* __restrict__ slh_l)
{
    int b = blockIdx.x;
    int c = blockIdx.y * 8 + threadIdx.y;
    int p = threadIdx.x;
    size_t base = ((size_t)b * 2048) * PIX + p;
    float gi = gates0[base + (size_t)c * PIX];
    float gf = gates0[base + (size_t)(512 + c) * PIX];
    float go = gates0[base + (size_t)(1024 + c) * PIX];
    float gg = gates0[base + (size_t)(1536 + c) * PIX];
#pragma unroll
    for (int ks = 0; ks < 8; ks++) {
        size_t pb = ((size_t)(ks * 2 + b) * 2048) * PIX + p;
        gi += part[pb + (size_t)c * PIX];
        gf += part[pb + (size_t)(512 + c) * PIX];
        go += part[pb + (size_t)(1024 + c) * PIX];
        gg += part[pb + (size_t)(1536 + c) * PIX];
    }
    size_t hidx = ((size_t)b * 512 + c) * PIX + p;
    float cprev = cst[hidx];
    float si = 1.f / (1.f + expf(-gi));
    float sf = 1.f / (1.f + expf(-gf));
    float so = 1.f / (1.f + expf(-go));
    float c2 = sf * cprev + si * tanhf(gg);
    float h2 = so * tanhf(c2);
    cst[hidx] = c2;
    h[hidx] = h2;

    {
        __half hh, ll;
        split_h(h2, hh, ll);
        int qh = p / 7, qw = p - qh * 7;
#pragma unroll
        for (int kk = 0; kk < 9; kk++) {
            int oh = qh - (kk / 3 - 1), ow = qw - (kk % 3 - 1);
            if (oh >= 0 && oh < 7 && ow >= 0 && ow < 7) {
                size_t o = (size_t)(b * 49 + oh * 7 + ow) * K45 + kk * 512 + c;
                slh_h[o] = hh;
                slh_l[o] = ll;
            }
        }
    }

    __shared__ float red[8][49];
    red[threadIdx.y][p] = h2;
    __syncthreads();
    if (p == 0) {
        float s = 0.f;
        for (int q = 0; q < 49; q++) s += red[threadIdx.y][q];
        houts[((size_t)t * 2 + b) * 512 + c] = s * (1.f / (float)PIX);
    }
}

__global__ void final_k(const float* __restrict__ houts, const float* __restrict__ fc_w,
                        const float* __restrict__ fc_b, float* __restrict__ out)
{
    __shared__ float om[1024];
    int tid = threadIdx.x;
    for (int i = tid; i < 1024; i += 512) {
        int b = i / 512, c = i - b * 512;
        float s = 0.f;
        for (int t = 0; t < TSEG; t++) s += houts[((size_t)t * 2 + b) * 512 + c];
        om[i] = s * (1.f / (float)TSEG);
    }
    __syncthreads();
    for (int i = tid; i < 202; i += 512) {
        int b = i / 101, k = i - b * 101;
        float s = fc_b[k];
        for (int c = 0; c < 512; c++) s += om[b * 512 + c] * fc_w[k * 512 + c];
        out[i] = s;
    }
    if (tid == 0) { out[2402] = 0.f; out[2403] = 0.f; }
}

// ===================== host =====================
static float* symaddr(const void* sym) { void* p = nullptr; cudaGetSymbolAddress(&p, sym); return (float*)p; }
static __half* symaddrh(const void* sym) { void* p = nullptr; cudaGetSymbolAddress(&p, sym); return (__half*)p; }

#define GEMM_SMEM2 (3 * 32768)
#define GEMM_SMEM3 (3 * 49152)
#define GEMM_SMEM4 (3 * 65536)

// 1-term GEMM (A hi, B hi) — mask conv1
static inline void launch_gemm1(const __half* Ah, const __half* Bh,
                                float* out, int K, int ksplit, int Mreal, int N,
                                const float* bn, int postop, long long partChunk,
                                __half* ich = nullptr, __half* icl = nullptr)
{
    dim3 grid(N / 128, (Mreal + 127) / 128, ksplit);
    gemm_mma_k<2><<<grid, 256, GEMM_SMEM2>>>(Ah, nullptr, Bh, nullptr, out, K, K / ksplit, Mreal, N,
                                             bn, postop, partChunk, ich, icl);
}

// 2-term feed-forward GEMM (A split, B hi only)
static inline void launch_gemm2(const __half* Ah, const __half* Al, const __half* Bh,
                                float* out, int K, int ksplit, int Mreal, int N,
                                const float* bn, int postop, long long partChunk,
                                __half* ich = nullptr, __half* icl = nullptr)
{
    dim3 grid(N / 128, (Mreal + 127) / 128, ksplit);
    gemm_mma_k<3><<<grid, 256, GEMM_SMEM3>>>(Ah, Al, Bh, nullptr, out, K, K / ksplit, Mreal, N,
                                             bn, postop, partChunk, ich, icl);
}

// 3-term recurrent GEMM (A split, B split)
static inline void launch_gemm3(const __half* Ah, const __half* Al,
                                const __half* Bh, const __half* Bl,
                                float* out, int K, int ksplit, int Mreal, int N,
                                long long partChunk)
{
    dim3 grid(N / 128, (Mreal + 127) / 128, ksplit);
    gemm_mma_k<4><<<grid, 256, GEMM_SMEM4>>>(Ah, Al, Bh, Bl, out, K, K / ksplit, Mreal, N,
                                             nullptr, 0, partChunk, nullptr, nullptr);
}

extern "C" void kernel_launch(void* const* d_in, const int* in_sizes, int n_in,
                              void* d_out, int out_size)
{
    const float* x      = (const float*)d_in[0];
    const float* wf     = (const float*)d_in[1];
    const float* fc_w   = (const float*)d_in[3];
    const float* fc_b   = (const float*)d_in[4];
    const float* h0_w1  = (const float*)d_in[5];
    const float* h0_bn1 = (const float*)d_in[6];
    const float* h0_w2  = (const float*)d_in[7];
    const float* h0_bn2 = (const float*)d_in[8];
    const float* c0_w1  = (const float*)d_in[9];
    const float* c0_bn1 = (const float*)d_in[10];
    const float* c0_w2  = (const float*)d_in[11];
    const float* c0_bn2 = (const float*)d_in[12];
    const float* mk_w1  = (const float*)d_in[13];
    const float* mk_bn1 = (const float*)d_in[14];
    const float* mk_w2  = (const float*)d_in[15];
    const float* mk_bn2 = (const float*)d_in[16];
    const float* mk_w3  = (const float*)d_in[17];
    const float* lstm_w = (const float*)d_in[18];
    const float* lstm_b = (const float*)d_in[19];
    float* out = (float*)d_out;

    cudaFuncSetAttribute(gemm_mma_k<2>, cudaFuncAttributeMaxDynamicSharedMemorySize, GEMM_SMEM2);
    cudaFuncSetAttribute(gemm_mma_k<3>, cudaFuncAttributeMaxDynamicSharedMemorySize, GEMM_SMEM3);
    cudaFuncSetAttribute(gemm_mma_k<4>, cudaFuncAttributeMaxDynamicSharedMemorySize, GEMM_SMEM4);

    float *mx = symaddr(g_mx), *xin = symaddr(g_xin);
    float *y2 = symaddr(g_y2), *mask = symaddr(g_mask);
    float *meanx = symaddr(g_meanx), *mxc = symaddr(g_mxc), *attfea = symaddr(g_attfea);
    float *aw = symaddr(g_aw), *h = symaddr(g_h), *cst = symaddr(g_cst);
    float *gates0 = symaddr(g_gates0), *part = symaddr(g_part), *houts = symaddr(g_houts);
    float *tmphc = symaddr(g_tmphc), *bnc1 = symaddr(g_bnc1);

    __half *axt_h = symaddrh(g_axt_h);
    __half *ay1_h = symaddrh(g_ay1_h), *ay1_l = symaddrh(g_ay1_l);
    __half *sa_h = symaddrh(g_sa_h),   *sa_l = symaddrh(g_sa_l);
    __half *slh_h = symaddrh(g_slh_h), *slh_l = symaddrh(g_slh_l);
    __half *wmk1_h = symaddrh(g_wmk1_h);
    __half *wmk2_h = symaddrh(g_wmk2_h);
    __half *wgx_h = symaddrh(g_wgx_h);
    __half *whc1_h = symaddrh(g_whc1_h);
    __half *w2h_h = symaddrh(g_w2h_h);
    __half *w2c_h = symaddrh(g_w2c_h);
    __half *wlh_h = symaddrh(g_wlh_h), *wlh_l = symaddrh(g_wlh_l);

    auto blk = [](long long n) { return (unsigned)((n + 255) / 256); };
    dim3 cb(49, 8);

    // ---- weight repacks ----
    repack2_k<<<dim3(1024, 8), 128>>>(mk_w1, 2048, 0, 2048, wmk1_h, nullptr);
    repack2_k<<<dim3(512, 4), 128>>>(mk_w2, 1024, 0, 1024, wmk2_h, nullptr);
    repack2_k<<<dim3(2048, 8), 128>>>(lstm_w, 2560, 0, 2048, wgx_h, nullptr);
    repack2_k<<<dim3(2048, 2), 128>>>(lstm_w, 2560, 2048, 512, wlh_h, wlh_l);
    repack2_k<<<dim3(1024, 8), 128>>>(h0_w1, 2048, 0, 2048, whc1_h, nullptr);
    repack2_k<<<dim3(1024, 8), 128>>>(c0_w1, 2048, 0, 2048, whc1_h + (size_t)1024 * K18, nullptr);
    repack2_k<<<dim3(512, 4), 128>>>(h0_w2, 1024, 0, 1024, w2h_h, nullptr);
    repack2_k<<<dim3(512, 4), 128>>>(c0_w2, 1024, 0, 1024, w2c_h, nullptr);
    bnconcat_k<<<32, 256>>>(h0_bn1, c0_bn1, bnc1);

    // ---- mask path: conv1 1-term fp16; epilogue scatters split im2col for conv2 ----
    im2colx_k<<<blk((long long)2156 * 9 * 1024), 256>>>(x, axt_h);
    launch_gemm1(axt_h, wmk1_h, part, K18, 1, 2156, 1024, mk_bn1, 2, 0, ay1_h, ay1_l);
    launch_gemm2(ay1_h, ay1_l, wmk2_h, part, K9, 2, 2156, 512, nullptr, 0,
                 (long long)44 * 512 * PIX);
    finish_k<<<blk((long long)44 * 512 * PIX), 256>>>(part, 2, 44 * 512 * PIX, mk_bn2, y2,
                                                      512, 44 * 512 * PIX, 1);
    mask_final_k<<<NBT, cb>>>(y2, mk_w3, mask, out + 246);

    // ---- masked features + attention (mxc fused into mx; meanx+xin fused) ----
    mxmxc_k<<<dim3(NBT, 256), cb>>>(x, mask, mx, mxc);
    attfea_k<<<NBT, 256>>>(mxc, wf, attfea);
    aw_k<<<1, 32>>>(attfea, aw, out + 202);
    meanxin_k<<<blk(2 * 2048 * PIX), 256>>>(mx, aw, meanx, xin);

    // ---- xin conv_x GEMM (linearity) ----
    im2col_k<<<blk((long long)98 * 9 * 1024), 256>>>(xin, 2048, 0, 2048, 98, sa_h, sa_l);
    launch_gemm2(sa_h, sa_l, wgx_h, part, K18, 8, 98, 2048, nullptr, 0, (long long)2 * 2048 * PIX);
    ginit8_k<<<blk(2 * 2048 * PIX), 256>>>(part, lstm_b, gates0);

    // ---- h0/c0 init ----
    im2col_k<<<blk((long long)98 * 9 * 1024), 256>>>(meanx, 2048, 0, 2048, 98, sa_h, sa_l);
    launch_gemm2(sa_h, sa_l, whc1_h, part, K18, 8, 98, 2048, nullptr, 0, (long long)2 * 2048 * PIX);
    finish_k<<<blk(2 * 2048 * PIX), 256>>>(part, 8, 2 * 2048 * PIX, bnc1, tmphc, 2048, 2 * 2048 * PIX, 1);

    im2col_k<<<blk((long long)98 * 9 * 512), 256>>>(tmphc, 2048, 0, 1024, 98, sa_h, sa_l);
    launch_gemm2(sa_h, sa_l, w2h_h, part, K9, 4, 98, 512, nullptr, 0, (long long)2 * 512 * PIX);
    finish_k<<<blk(2 * 512 * PIX), 256>>>(part, 4, 2 * 512 * PIX, h0_bn2, h, 512, 2 * 512 * PIX, 1);

    im2col_k<<<blk((long long)98 * 9 * 512), 256>>>(tmphc, 2048, 1024, 1024, 98, sa_h, sa_l);
    launch_gemm2(sa_h, sa_l, w2c_h, part, K9, 4, 98, 512, nullptr, 0, (long long)2 * 512 * PIX);
    finish_k<<<blk(2 * 512 * PIX), 256>>>(part, 4, 2 * 512 * PIX, c0_bn2, cst, 512, 2 * 512 * PIX, 1);

    // ---- seed im2col for h0, then recurrence (3-term: no error compounding) ----
    im2col_k<<<blk((long long)98 * 9 * 256), 256>>>(h, 512, 0, 512, 98, slh_h, slh_l);
    for (int t = 0; t < TSEG; t++) {
        launch_gemm3(slh_h, slh_l, wlh_h, wlh_l, part, K45, 8, 98, 2048,
                     (long long)2 * 2048 * PIX);
        lstm_point_k<<<dim3(2, 64), cb>>>(gates0, part, h, cst, houts, t, slh_h, slh_l);
    }

    final_k<<<1, 512>>>(houts, fc_w, fc_b, out);
}

// round 13
// speedup vs baseline: 15.0786x; 1.1038x over previous
#include <cuda_runtime.h>
#include <cuda_fp16.h>
#include <cstdint>

// ===================== problem constants =====================
#define TSEG 22
#define NBT  44
#define PIX  49
#define K18  18432     // 9*2048
#define K9   9216      // 9*1024
#define K45  4608      // 9*512
#define AM   2176      // 17*128 pad of 2156

// ===================== fp32 scratch =====================
__device__ float g_mx[(size_t)NBT * 2048 * PIX];
__device__ float g_xin[2 * 2048 * PIX];
__device__ float g_y2[(size_t)NBT * 512 * PIX];
__device__ float g_mask[NBT * PIX];
__device__ float g_meanx[2 * 2048 * PIX];
__device__ float g_mxc[NBT * 2048];
__device__ float g_attfea[NBT];
__device__ float g_aw[NBT];
__device__ float g_h[2 * 512 * PIX];
__device__ float g_cst[2 * 512 * PIX];
__device__ float g_gates0[2 * 2048 * PIX];
__device__ float g_part[3300000];          // 16*200704 (merged) / conv2 partials
__device__ float g_houts[TSEG * 2 * 512];
__device__ float g_tmphc[2 * 2048 * PIX];
__device__ float g_bnc1[4 * 2048];

// ===================== split-fp16 buffers (zero-init at module load) ==========
__device__ __half g_axt_h[(size_t)AM * K18];                       // conv1 A: hi only
__device__ __half g_ay1_h[(size_t)AM * K9];                        // conv2 A: hi only
__device__ __half g_sa_h[(size_t)128 * K18],  g_sa_l[(size_t)128 * K18];
__device__ __half g_sb_h[(size_t)128 * K18],  g_sb_l[(size_t)128 * K18];
__device__ __half g_slh_h[(size_t)128 * K45], g_slh_l[(size_t)128 * K45];
__device__ __half g_wmk1_h[(size_t)1024 * K18];
__device__ __half g_wmk2_h[(size_t)512 * K9];
__device__ __half g_wgx_h[(size_t)2048 * K18];
__device__ __half g_whc1_h[(size_t)2048 * K18];
__device__ __half g_w2h_h[(size_t)512 * K9];
__device__ __half g_w2c_h[(size_t)512 * K9];
__device__ __half g_wlh_h[(size_t)2048 * K45];

// ===================== base-ISA tensor helpers (sm_80+) =====================
__device__ __forceinline__ uint32_t smem_u32(const void* p) {
    uint32_t a;
    asm("{ .reg .u64 t; cvta.to.shared.u64 t, %1; cvt.u32.u64 %0, t; }" : "=r"(a) : "l"(p));
    return a;
}
__device__ __forceinline__ void ldsm4(uint32_t* r, uint32_t addr) {
    asm volatile("ldmatrix.sync.aligned.m8n8.x4.shared.b16 {%0,%1,%2,%3}, [%4];"
        : "=r"(r[0]), "=r"(r[1]), "=r"(r[2]), "=r"(r[3]) : "r"(addr));
}
__device__ __forceinline__ void mma16816(float* d, const uint32_t* a, const uint32_t* b) {
    asm volatile(
        "mma.sync.aligned.m16n8k16.row.col.f32.f16.f16.f32 "
        "{%0,%1,%2,%3}, {%4,%5,%6,%7}, {%8,%9}, {%0,%1,%2,%3};"
        : "+f"(d[0]), "+f"(d[1]), "+f"(d[2]), "+f"(d[3])
        : "r"(a[0]), "r"(a[1]), "r"(a[2]), "r"(a[3]), "r"(b[0]), "r"(b[1]));
}
#define CP_COMMIT() asm volatile("cp.async.commit_group;" ::: "memory")

__device__ __forceinline__ void split_h(float v, __half& h, __half& l) {
    h = __float2half_rn(v);
    l = __float2half_rn(v - __half2float(h));
}

// ===================== split-fp16 mma.sync GEMM =====================
// NT=2: D = Ahi @ Bhi^T (1 term).  NT=3: D = (Ahi+Alo) @ Bhi^T (2 terms).
// grid (N/128, ceil(M/128), z), block 256 (8 warps, 2x4 -> 64x32/warp).
// Dual-launch: if zhalf>0 and blockIdx.z>=zhalf, use (A2hi,A2lo,B2hi,out2).
// postop: 0 raw fp32, 1 BN+ReLU fp32, 2 BN+ReLU scattered fp16-hi im2col.
template<int NT>
__global__ void __launch_bounds__(256, 1) gemm_mma_k(
    const __half* Ahi, const __half* Alo, const __half* Bhi,
    float* outp, int K, int Ktile, int Mreal, int OCtot,
    const float* __restrict__ bn, int postop, long long partChunk,
    __half* __restrict__ ic_h,
    const __half* A2hi, const __half* A2lo, const __half* B2hi,
    float* out2, int zhalf)
{
    extern __shared__ char dsm[];           // 3 stages x NT x 16KB
    __shared__ float s_sc[128], s_sh[128];
    const uint32_t STG = (uint32_t)NT * 16384u;
    const uint32_t OFF_BH = (NT == 2) ? 16384u : 32768u;

    int tid = threadIdx.x, lane = tid & 31, wid = tid >> 5;
    int wm = wid & 1, wn = wid >> 1;
    uint32_t sbase = smem_u32(dsm);

    int zz = blockIdx.z;
    if (zhalf > 0 && zz >= zhalf) {
        Ahi = A2hi; Alo = A2lo; Bhi = B2hi; outp = out2; zz -= zhalf;
    }

    int n0 = blockIdx.x * 128;
    int m0 = blockIdx.y * 128;
    long long kc0 = (long long)zz * Ktile;
    int nChunks = Ktile / 64;

    const __half* tbase[NT == 2 ? 2 : 3];
    tbase[0] = Ahi + (size_t)m0 * K + kc0;
    if (NT == 2) {
        tbase[1] = Bhi + (size_t)n0 * K + kc0;
    } else {
        tbase[1] = Alo + (size_t)m0 * K + kc0;
        tbase[2] = Bhi + (size_t)n0 * K + kc0;
    }

    auto load_chunk = [&](int c, int stg) {
        uint32_t dbase = sbase + (uint32_t)stg * STG;
#pragma unroll
        for (int j = 0; j < NT * 4; j++) {
            int tile = j >> 2;
            int within = ((j & 3) << 8) + tid;      // 0..1023
            int r = within >> 3, cs = within & 7;
            const void* g = tbase[tile] + (size_t)c * 64 + (size_t)r * K + cs * 8;
            uint32_t so = dbase + (uint32_t)tile * 16384u
                        + (uint32_t)(r * 128 + ((cs * 16) ^ ((r & 7) * 16)));
            asm volatile("cp.async.cg.shared.global [%0], [%1], 16;" :: "r"(so), "l"(g));
        }
    };

    float d[4][4][4];
#pragma unroll
    for (int a = 0; a < 4; a++)
#pragma unroll
        for (int b = 0; b < 4; b++)
#pragma unroll
            for (int c = 0; c < 4; c++) d[a][b][c] = 0.f;

    if (nChunks > 0) { load_chunk(0, 0); CP_COMMIT(); }
    if (nChunks > 1) { load_chunk(1, 1); CP_COMMIT(); }

    for (int c = 0; c < nChunks; c++) {
        if (c + 1 < nChunks) asm volatile("cp.async.wait_group 1;" ::: "memory");
        else                 asm volatile("cp.async.wait_group 0;" ::: "memory");
        __syncthreads();
        if (c + 2 < nChunks) { load_chunk(c + 2, (c + 2) % 3); CP_COMMIT(); }

        int stg = c % 3;
        uint32_t sAh = sbase + (uint32_t)stg * STG;
        uint32_t sAl = sAh + 16384u;
        uint32_t sBh = sAh + OFF_BH;

#pragma unroll
        for (int k16 = 0; k16 < 4; k16++) {
            uint32_t ah[4][4], al[4][4], bh[4][2];
#pragma unroll
            for (int mt = 0; mt < 4; mt++) {
                uint32_t r = (uint32_t)(wm * 64 + mt * 16 + (lane & 15));
                uint32_t cby = (uint32_t)(k16 * 32 + ((lane >> 4) << 4));
                uint32_t off = r * 128 + (cby ^ ((r & 7) << 4));
                ldsm4(ah[mt], sAh + off);
                if (NT >= 3) ldsm4(al[mt], sAl + off);
            }
#pragma unroll
            for (int p = 0; p < 2; p++) {
                uint32_t r = (uint32_t)(wn * 32 + p * 16 + (((lane >> 4) & 1) << 3) + (lane & 7));
                uint32_t cby = (uint32_t)(k16 * 32 + (((lane >> 3) & 1) << 4));
                uint32_t off = r * 128 + (cby ^ ((r & 7) << 4));
                uint32_t t4[4];
                ldsm4(t4, sBh + off);
                bh[2 * p][0] = t4[0]; bh[2 * p][1] = t4[1];
                bh[2 * p + 1][0] = t4[2]; bh[2 * p + 1][1] = t4[3];
            }
#pragma unroll
            for (int mt = 0; mt < 4; mt++)
#pragma unroll
                for (int nt = 0; nt < 4; nt++) {
                    mma16816(d[mt][nt], ah[mt], bh[nt]);
                    if (NT >= 3) mma16816(d[mt][nt], al[mt], bh[nt]);
                }
        }
        __syncthreads();
    }

    if (postop >= 1 && tid < 128) {
        int oc = n0 + tid;
        float g = bn[oc], b = bn[OCtot + oc], m = bn[2 * OCtot + oc], v = bn[3 * OCtot + oc];
        float sc = g * rsqrtf(v + 1e-5f);
        s_sc[tid] = sc;
        s_sh[tid] = b - m * sc;
    }
    __syncthreads();

    if (postop == 2) {
        // BN+ReLU, then scatter fp16-hi into next conv's im2col operand.
        int Kdst = OCtot * 9;
#pragma unroll
        for (int mt = 0; mt < 4; mt++) {
#pragma unroll
            for (int nt = 0; nt < 4; nt++) {
                int ln = wn * 32 + nt * 8 + 2 * (lane & 3);
                int r0 = m0 + wm * 64 + mt * 16 + (lane >> 2);
#pragma unroll
                for (int half = 0; half < 2; half++) {
                    int mrow = r0 + half * 8;
                    if (mrow < Mreal) {
                        int img = mrow / 49, p = mrow - img * 49;
                        float v0 = fmaxf(d[mt][nt][half * 2 + 0] * s_sc[ln] + s_sh[ln], 0.f);
                        float v1 = fmaxf(d[mt][nt][half * 2 + 1] * s_sc[ln + 1] + s_sh[ln + 1], 0.f);
                        __half2 hh;
                        hh.x = __float2half_rn(v0);
                        hh.y = __float2half_rn(v1);
                        int qh = p / 7, qw = p - qh * 7;
                        int oc = n0 + ln;
#pragma unroll
                        for (int kk = 0; kk < 9; kk++) {
                            int oh = qh - (kk / 3 - 1), ow = qw - (kk % 3 - 1);
                            if (oh >= 0 && oh < 7 && ow >= 0 && ow < 7) {
                                size_t o = (size_t)(img * 49 + oh * 7 + ow) * Kdst + kk * OCtot + oc;
                                *(__half2*)(ic_h + o) = hh;
                            }
                        }
                    }
                }
            }
        }
        return;
    }

    float* obase0 = outp + (size_t)zz * partChunk;
#pragma unroll
    for (int mt = 0; mt < 4; mt++) {
#pragma unroll
        for (int nt = 0; nt < 4; nt++) {
            int ln = wn * 32 + nt * 8 + 2 * (lane & 3);
            int r0 = m0 + wm * 64 + mt * 16 + (lane >> 2);
#pragma unroll
            for (int half = 0; half < 2; half++) {
                int mrow = r0 + half * 8;
                if (mrow < Mreal) {
                    int img = mrow / 49, p = mrow - img * 49;
                    float* ob = obase0 + ((size_t)img * OCtot + n0) * 49 + p;
                    float v0 = d[mt][nt][half * 2 + 0];
                    float v1 = d[mt][nt][half * 2 + 1];
                    if (postop) {
                        v0 = fmaxf(v0 * s_sc[ln] + s_sh[ln], 0.f);
                        v1 = fmaxf(v1 * s_sc[ln + 1] + s_sh[ln + 1], 0.f);
                    }
                    ob[(size_t)ln * 49] = v0;
                    ob[(size_t)(ln + 1) * 49] = v1;
                }
            }
        }
    }
}

// ===================== im2col (fp32 (img,CHtot,49) -> split fp16) =====================
__global__ void im2col_k(const float* __restrict__ in, int CHtot, int c0, int IC, int nRows,
                         __half* __restrict__ hi, __half* __restrict__ lo)
{
    int ICp = IC >> 1;
    long long idx = (long long)blockIdx.x * blockDim.x + threadIdx.x;
    long long tot = (long long)nRows * 9 * ICp;
    if (idx >= tot) return;
    int icp = (int)(idx % ICp);
    long long r2 = idx / ICp;
    int kk = (int)(r2 % 9);
    int row = (int)(r2 / 9);
    int img = row / 49, p = row - img * 49;
    int oh = p / 7, ow = p - oh * 7;
    int ih = oh + kk / 3 - 1, iw = ow + kk % 3 - 1;
    bool valid = (ih >= 0) && (ih < 7) && (iw >= 0) && (iw < 7);
    int q = valid ? (ih * 7 + iw) : 0;
    int ic = icp * 2;
    const float* base = in + ((size_t)img * CHtot + c0 + ic) * PIX + q;
    float v0 = valid ? base[0] : 0.f;
    float v1 = valid ? base[PIX] : 0.f;
    __half2 hh, ll;
    split_h(v0, hh.x, ll.x);
    split_h(v1, hh.y, ll.y);
    size_t o = (size_t)row * (IC * 9) + (size_t)kk * IC + ic;
    *(__half2*)(hi + o) = hh;
    *(__half2*)(lo + o) = ll;
}

// im2col reading x (B, 2048, T, 7, 7) directly (fused transpose); hi only
__global__ void im2colx_k(const float* __restrict__ x, __half* __restrict__ hi)
{
    const int ICp = 1024;
    long long idx = (long long)blockIdx.x * blockDim.x + threadIdx.x;
    long long tot = (long long)2156 * 9 * ICp;
    if (idx >= tot) return;
    int icp = (int)(idx % ICp);
    long long r2 = idx / ICp;
    int kk = (int)(r2 % 9);
    int row = (int)(r2 / 9);
    int img = row / 49, p = row - img * 49;
    int b = img / TSEG, t = img - b * TSEG;
    int oh = p / 7, ow = p - oh * 7;
    int ih = oh + kk / 3 - 1, iw = ow + kk % 3 - 1;
    bool valid = (ih >= 0) && (ih < 7) && (iw >= 0) && (iw < 7);
    int q = valid ? (ih * 7 + iw) : 0;
    int ic = icp * 2;
    const float* base = x + (((size_t)(b * 2048 + ic) * TSEG) + t) * PIX + q;
    float v0 = valid ? base[0] : 0.f;
    float v1 = valid ? base[(size_t)TSEG * PIX] : 0.f;
    __half2 hh;
    hh.x = __float2half_rn(v0);
    hh.y = __float2half_rn(v1);
    size_t o = (size_t)row * K18 + (size_t)kk * 2048 + ic;
    *(__half2*)(hi + o) = hh;
}

// ===================== ALL weight repacks in ONE launch =====================
// dst[oc][kk*IC+ic] = (half)src[(oc*stride + c0 + ic)*9 + kk]; hi only.
// Jobs flattened over blockIdx.x; block = 128 threads, 256 ic per block.
__global__ void __launch_bounds__(128) repack_all_k(
    const float* s0, const float* s1, const float* s2, const float* s3,
    const float* s4, const float* s5, const float* s6, const float* s7,
    __half* d0, __half* d1, __half* d2, __half* d3,
    __half* d4, __half* d5, __half* d6, __half* d7)
{
    // job:        mk_w1  mk_w2  wgx    wlh    h0w1   c0w1   h0w2   c0w2
    const int cum[9]    = {0, 8192, 10240, 26624, 30720, 38912, 47104, 49152, 51200};
    const int OCt[8]    = {1024, 512, 2048, 2048, 1024, 1024, 512, 512};
    const int stridet[8]= {2048, 1024, 2560, 2560, 2048, 2048, 1024, 1024};
    const int c0t[8]    = {0, 0, 0, 2048, 0, 0, 0, 0};
    const int ICt[8]    = {2048, 1024, 2048, 512, 2048, 2048, 1024, 1024};

    __shared__ float s[2304];
    int bid = blockIdx.x;
    int j = 0;
    while (bid >= cum[j + 1]) j++;
    int bi = bid - cum[j];
    const float* src = (j == 0) ? s0 : (j == 1) ? s1 : (j == 2) ? s2 : (j == 3) ? s3
                     : (j == 4) ? s4 : (j == 5) ? s5 : (j == 6) ? s6 : s7;
    __half* dst = (j == 0) ? d0 : (j == 1) ? d1 : (j == 2) ? d2 : (j == 3) ? d3
                : (j == 4) ? d4 : (j == 5) ? d5 : (j == 6) ? d6 : d7;
    int OC = OCt[j], IC = ICt[j], srcStride = stridet[j], c0 = c0t[j];

    int oc = bi % OC, ic0 = (bi / OC) * 256, tid = threadIdx.x;
    const float* base = src + ((size_t)oc * srcStride + c0 + ic0) * 9;
    for (int i = tid; i < 2304; i += 128) s[i] = base[i];
    __syncthreads();
    size_t dbase = (size_t)oc * ((size_t)IC * 9) + ic0 + 2 * tid;
#pragma unroll
    for (int kk = 0; kk < 9; kk++) {
        __half2 hh;
        hh.x = __float2half_rn(s[(2 * tid) * 9 + kk]);
        hh.y = __float2half_rn(s[(2 * tid + 1) * 9 + kk]);
        *(__half2*)(dst + dbase + (size_t)kk * IC) = hh;
    }
}

__global__ void bnconcat_k(const float* __restrict__ a, const float* __restrict__ b,
                           float* __restrict__ dst)
{
    int i = blockIdx.x * blockDim.x + threadIdx.x;
    if (i >= 4 * 2048) return;
    int pr = i / 2048, j = i - pr * 2048;
    dst[i] = (j < 1024) ? a[pr * 1024 + j] : b[pr * 1024 + (j - 1024)];
}

// ===================== small kernels =====================
__global__ void finish_k(const float* __restrict__ part, int nsplit, int chunk,
                         const float* __restrict__ bn, float* __restrict__ out,
                         int OC, int total, int postop)
{
    int i = blockIdx.x * blockDim.x + threadIdx.x;
    if (i >= total) return;
    float s = 0.f;
    for (int ks = 0; ks < nsplit; ks++) s += part[(size_t)ks * chunk + i];
    if (postop == 1) {
        int oc = (i / PIX) % OC;
        float g = bn[oc], b = bn[OC + oc], m = bn[2 * OC + oc], v = bn[3 * OC + oc];
        s = (s - m) * g * rsqrtf(v + 1e-5f) + b;
        s = fmaxf(s, 0.f);
    }
    out[i] = s;
}

__global__ void mask_final_k(const float* __restrict__ y2, const float* __restrict__ w3,
                             float* __restrict__ mask, float* __restrict__ outmask)
{
    int n = blockIdx.x;
    int p = threadIdx.x, g = threadIdx.y;
    int oh = p / 7, ow = p - oh * 7;
    float s = 0.f;
    for (int ic = g; ic < 512; ic += 8) {
        const float* row = y2 + ((size_t)n * 512 + ic) * PIX;
        const float* wr = w3 + ic * 9;
#pragma unroll
        for (int kh = 0; kh < 3; kh++)
#pragma unroll
            for (int kw = 0; kw < 3; kw++) {
                int ih = oh + kh - 1, iw = ow + kw - 1;
                if (ih >= 0 && ih < 7 && iw >= 0 && iw < 7)
                    s += row[ih * 7 + iw] * wr[kh * 3 + kw];
            }
    }
    __shared__ float red[8][49];
    red[g][p] = s;
    __syncthreads();
    if (g == 0) {
        float tot = 0.f;
#pragma unroll
        for (int q = 0; q < 8; q++) tot += red[q][p];
        float m = 1.f / (1.f + expf(-tot));
        mask[n * PIX + p] = m;
        outmask[n * PIX + p] = m;
    }
}

// mx = x*mask (fused transpose) + fused per-(bt,c) spatial mean (mxc)
__global__ void mxmxc_k(const float* __restrict__ x, const float* __restrict__ mask,
                        float* __restrict__ mx, float* __restrict__ mxc)
{
    int bt = blockIdx.x;
    int c = blockIdx.y * 8 + threadIdx.y;
    int p = threadIdx.x;
    int b = bt / TSEG, t = bt - b * TSEG;
    float v = x[(((size_t)(b * 2048 + c)) * TSEG + t) * PIX + p] * mask[bt * PIX + p];
    mx[((size_t)bt * 2048 + c) * PIX + p] = v;
    __shared__ float red[8][49];
    red[threadIdx.y][p] = v;
    __syncthreads();
    if (p == 0) {
        float s = 0.f;
        for (int q = 0; q < 49; q++) s += red[threadIdx.y][q];
        mxc[bt * 2048 + c] = s * (1.f / (float)PIX);
    }
}

// fused: meanx = mean_t(mx), xin = sum_t aw[t]*mx
__global__ void meanxin_k(const float* __restrict__ mx, const float* __restrict__ aw,
                          float* __restrict__ meanx, float* __restrict__ xin)
{
    int i = blockIdx.x * blockDim.x + threadIdx.x;
    const int inner = 2048 * PIX;
    if (i >= 2 * inner) return;
    int b = i / inner, r = i - b * inner;
    float sm = 0.f, sx = 0.f;
    for (int t = 0; t < TSEG; t++) {
        float v = mx[((size_t)(b * TSEG + t)) * inner + r];
        sm += v;
        sx += aw[b * TSEG + t] * v;
    }
    meanx[i] = sm * (1.f / (float)TSEG);
    xin[i] = sx;
}

__global__ void attfea_k(const float* __restrict__ mxc, const float* __restrict__ wf,
                         float* __restrict__ attfea)
{
    int bt = blockIdx.x;
    int tid = threadIdx.x;
    __shared__ float sr[256];
    float s = 0.f;
    for (int c = tid; c < 2048; c += 256) s += mxc[bt * 2048 + c] * wf[c];
    sr[tid] = s;
    __syncthreads();
    for (int st = 128; st > 0; st >>= 1) {
        if (tid < st) sr[tid] += sr[tid + st];
        __syncthreads();
    }
    if (tid == 0) attfea[bt] = sr[0];
}

__global__ void aw_k(const float* __restrict__ attfea, float* __restrict__ aw,
                     float* __restrict__ out_aws)
{
    int b = threadIdx.x;
    if (b >= 2) return;
    float m = -1e30f;
    for (int t = 0; t < TSEG; t++) m = fmaxf(m, attfea[b * TSEG + t]);
    float sum = 0.f;
    for (int t = 0; t < TSEG; t++) sum += expf(attfea[b * TSEG + t] - m);
    for (int t = 0; t < TSEG; t++) {
        float a = expf(attfea[b * TSEG + t] - m) / sum;
        aw[b * TSEG + t] = a;
        out_aws[b * TSEG + t] = a;
    }
}

__global__ void ginit8_k(const float* __restrict__ part, const float* __restrict__ lstm_b,
                         float* __restrict__ gates0)
{
    int i = blockIdx.x * blockDim.x + threadIdx.x;
    const int total = 2 * 2048 * PIX;
    if (i >= total) return;
    int oc = (i / PIX) % 2048;
    float s = lstm_b[oc];
#pragma unroll
    for (int ks = 0; ks < 8; ks++) s += part[(size_t)ks * total + i];
    gates0[i] = s;
}

// pointwise LSTM update + spatial mean + fused split-fp16 scatter of h2 into
// next step's im2col A-operand.
__global__ void lstm_point_k(const float* __restrict__ gates0, const float* __restrict__ part,
                             float* __restrict__ h, float* __restrict__ cst,
                             float* __restrict__ houts, int t,
                             __half* __restrict__ slh_h, __half* __restrict__ slh_l)
{
    int b = blockIdx.x;
    int c = blockIdx.y * 8 + threadIdx.y;
    int p = threadIdx.x;
    size_t base = ((size_t)b * 2048) * PIX + p;
    float gi = gates0[base + (size_t)c * PIX];
    float gf = gates0[base + (size_t)(512 + c) * PIX];
    float go = gates0[base + (size_t)(1024 + c) * PIX];
    float gg = gates0[base + (size_t)(1536 + c) * PIX];
#pragma unroll
    for (int ks = 0; ks < 8; ks++) {
        size_t pb = ((size_t)(ks * 2 + b) * 2048) * PIX + p;
        gi += part[pb + (size_t)c * PIX];
        gf += part[pb + (size_t)(512 + c) * PIX];
        go += part[pb + (size_t)(1024 + c) * PIX];
        gg += part[pb + (size_t)(1536 + c) * PIX];
    }
    size_t hidx = ((size_t)b * 512 + c) * PIX + p;
    float cprev = cst[hidx];
    float si = 1.f / (1.f + expf(-gi));
    float sf = 1.f / (1.f + expf(-gf));
    float so = 1.f / (1.f + expf(-go));
    float c2 = sf * cprev + si * tanhf(gg);
    float h2 = so * tanhf(c2);
    cst[hidx] = c2;
    h[hidx] = h2;

    {
        __half hh, ll;
        split_h(h2, hh, ll);
        int qh = p / 7, qw = p - qh * 7;
#pragma unroll
        for (int kk = 0; kk < 9; kk++) {
            int oh = qh - (kk / 3 - 1), ow = qw - (kk % 3 - 1);
            if (oh >= 0 && oh < 7 && ow >= 0 && ow < 7) {
                size_t o = (size_t)(b * 49 + oh * 7 + ow) * K45 + kk * 512 + c;
                slh_h[o] = hh;
                slh_l[o] = ll;
            }
        }
    }

    __shared__ float red[8][49];
    red[threadIdx.y][p] = h2;
    __syncthreads();
    if (p == 0) {
        float s = 0.f;
        for (int q = 0; q < 49; q++) s += red[threadIdx.y][q];
        houts[((size_t)t * 2 + b) * 512 + c] = s * (1.f / (float)PIX);
    }
}

__global__ void final_k(const float* __restrict__ houts, const float* __restrict__ fc_w,
                        const float* __restrict__ fc_b, float* __restrict__ out)
{
    __shared__ float om[1024];
    int tid = threadIdx.x;
    for (int i = tid; i < 1024; i += 512) {
        int b = i / 512, c = i - b * 512;
        float s = 0.f;
        for (int t = 0; t < TSEG; t++) s += houts[((size_t)t * 2 + b) * 512 + c];
        om[i] = s * (1.f / (float)TSEG);
    }
    __syncthreads();
    for (int i = tid; i < 202; i += 512) {
        int b = i / 101, k = i - b * 101;
        float s = fc_b[k];
        for (int c = 0; c < 512; c++) s += om[b * 512 + c] * fc_w[k * 512 + c];
        out[i] = s;
    }
    if (tid == 0) { out[2402] = 0.f; out[2403] = 0.f; }
}

// ===================== host =====================
static float* symaddr(const void* sym) { void* p = nullptr; cudaGetSymbolAddress(&p, sym); return (float*)p; }
static __half* symaddrh(const void* sym) { void* p = nullptr; cudaGetSymbolAddress(&p, sym); return (__half*)p; }

#define GEMM_SMEM2 (3 * 32768)
#define GEMM_SMEM3 (3 * 49152)

extern "C" void kernel_launch(void* const* d_in, const int* in_sizes, int n_in,
                              void* d_out, int out_size)
{
    const float* x      = (const float*)d_in[0];
    const float* wf     = (const float*)d_in[1];
    const float* fc_w   = (const float*)d_in[3];
    const float* fc_b   = (const float*)d_in[4];
    const float* h0_w1  = (const float*)d_in[5];
    const float* h0_bn1 = (const float*)d_in[6];
    const float* h0_w2  = (const float*)d_in[7];
    const float* h0_bn2 = (const float*)d_in[8];
    const float* c0_w1  = (const float*)d_in[9];
    const float* c0_bn1 = (const float*)d_in[10];
    const float* c0_w2  = (const float*)d_in[11];
    const float* c0_bn2 = (const float*)d_in[12];
    const float* mk_w1  = (const float*)d_in[13];
    const float* mk_bn1 = (const float*)d_in[14];
    const float* mk_w2  = (const float*)d_in[15];
    const float* mk_bn2 = (const float*)d_in[16];
    const float* mk_w3  = (const float*)d_in[17];
    const float* lstm_w = (const float*)d_in[18];
    const float* lstm_b = (const float*)d_in[19];
    float* out = (float*)d_out;

    cudaFuncSetAttribute(gemm_mma_k<2>, cudaFuncAttributeMaxDynamicSharedMemorySize, GEMM_SMEM2);
    cudaFuncSetAttribute(gemm_mma_k<3>, cudaFuncAttributeMaxDynamicSharedMemorySize, GEMM_SMEM3);

    float *mx = symaddr(g_mx), *xin = symaddr(g_xin);
    float *y2 = symaddr(g_y2), *mask = symaddr(g_mask);
    float *meanx = symaddr(g_meanx), *mxc = symaddr(g_mxc), *attfea = symaddr(g_attfea);
    float *aw = symaddr(g_aw), *h = symaddr(g_h), *cst = symaddr(g_cst);
    float *gates0 = symaddr(g_gates0), *part = symaddr(g_part), *houts = symaddr(g_houts);
    float *tmphc = symaddr(g_tmphc), *bnc1 = symaddr(g_bnc1);

    __half *axt_h = symaddrh(g_axt_h);
    __half *ay1_h = symaddrh(g_ay1_h);
    __half *sa_h = symaddrh(g_sa_h),   *sa_l = symaddrh(g_sa_l);
    __half *sb_h = symaddrh(g_sb_h),   *sb_l = symaddrh(g_sb_l);
    __half *slh_h = symaddrh(g_slh_h), *slh_l = symaddrh(g_slh_l);
    __half *wmk1_h = symaddrh(g_wmk1_h);
    __half *wmk2_h = symaddrh(g_wmk2_h);
    __half *wgx_h = symaddrh(g_wgx_h);
    __half *whc1_h = symaddrh(g_whc1_h);
    __half *w2h_h = symaddrh(g_w2h_h);
    __half *w2c_h = symaddrh(g_w2c_h);
    __half *wlh_h = symaddrh(g_wlh_h);

    auto blk = [](long long n) { return (unsigned)((n + 255) / 256); };
    dim3 cb(49, 8);
    const long long GCH = 2 * 2048 * PIX;   // 200704, gate partial chunk
    const long long HCH = 2 * 512 * PIX;    // 50176

    // ---- ALL weight repacks in one launch (hi only) ----
    repack_all_k<<<51200, 128>>>(mk_w1, mk_w2, lstm_w, lstm_w, h0_w1, c0_w1, h0_w2, c0_w2,
                                 wmk1_h, wmk2_h, wgx_h, wlh_h,
                                 whc1_h, whc1_h + (size_t)1024 * K18, w2h_h, w2c_h);
    bnconcat_k<<<32, 256>>>(h0_bn1, c0_bn1, bnc1);

    // ---- mask path: conv1 1-term; epilogue scatters fp16-hi im2col for conv2 (1-term) ----
    im2colx_k<<<blk((long long)2156 * 9 * 1024), 256>>>(x, axt_h);
    {
        dim3 grid(8, 17, 1);
        gemm_mma_k<2><<<grid, 256, GEMM_SMEM2>>>(axt_h, nullptr, wmk1_h, part, K18, K18, 2156, 1024,
                                                 mk_bn1, 2, 0, ay1_h,
                                                 nullptr, nullptr, nullptr, nullptr, 0);
    }
    {
        dim3 grid(4, 17, 2);
        gemm_mma_k<2><<<grid, 256, GEMM_SMEM2>>>(ay1_h, nullptr, wmk2_h, part, K9, K9 / 2, 2156, 512,
                                                 nullptr, 0, (long long)44 * 512 * PIX, nullptr,
                                                 nullptr, nullptr, nullptr, nullptr, 0);
    }
    finish_k<<<blk((long long)44 * 512 * PIX), 256>>>(part, 2, 44 * 512 * PIX, mk_bn2, y2,
                                                      512, 44 * 512 * PIX, 1);
    mask_final_k<<<NBT, cb>>>(y2, mk_w3, mask, out + 246);

    // ---- masked features + attention ----
    mxmxc_k<<<dim3(NBT, 256), cb>>>(x, mask, mx, mxc);
    attfea_k<<<NBT, 256>>>(mxc, wf, attfea);
    aw_k<<<1, 32>>>(attfea, aw, out + 202);
    meanxin_k<<<blk(2 * 2048 * PIX), 256>>>(mx, aw, meanx, xin);

    // ---- xin GEMM + hc1 GEMM merged into ONE launch (z-multiplex) ----
    im2col_k<<<blk((long long)98 * 9 * 1024), 256>>>(xin, 2048, 0, 2048, 98, sa_h, sa_l);
    im2col_k<<<blk((long long)98 * 9 * 1024), 256>>>(meanx, 2048, 0, 2048, 98, sb_h, sb_l);
    {
        dim3 grid(16, 1, 16);   // z 0..7 xin->wgx->part[0..8); z 8..15 meanx->whc1->part[8..16)
        gemm_mma_k<3><<<grid, 256, GEMM_SMEM3>>>(sa_h, sa_l, wgx_h, part, K18, K18 / 8, 98, 2048,
                                                 nullptr, 0, GCH, nullptr,
                                                 sb_h, sb_l, whc1_h, part + 8 * GCH, 8);
    }
    ginit8_k<<<blk(GCH), 256>>>(part, lstm_b, gates0);
    finish_k<<<blk(GCH), 256>>>(part + 8 * GCH, 8, (int)GCH, bnc1, tmphc, 2048, (int)GCH, 1);

    // ---- hc2: both branches in ONE launch ----
    im2col_k<<<blk((long long)98 * 9 * 512), 256>>>(tmphc, 2048, 0, 1024, 98, sa_h, sa_l);
    im2col_k<<<blk((long long)98 * 9 * 512), 256>>>(tmphc, 2048, 1024, 1024, 98, sb_h, sb_l);
    {
        dim3 grid(4, 1, 8);     // z 0..3 h-branch; z 4..7 c-branch
        gemm_mma_k<3><<<grid, 256, GEMM_SMEM3>>>(sa_h, sa_l, w2h_h, part, K9, K9 / 4, 98, 512,
                                                 nullptr, 0, HCH, nullptr,
                                                 sb_h, sb_l, w2c_h, part + 4 * HCH, 4);
    }
    finish_k<<<blk(HCH), 256>>>(part, 4, (int)HCH, h0_bn2, h, 512, (int)HCH, 1);
    finish_k<<<blk(HCH), 256>>>(part + 4 * HCH, 4, (int)HCH, c0_bn2, cst, 512, (int)HCH, 1);

    // ---- seed im2col for h0, then recurrence (2-term: A=h split, B=wlh hi) ----
    im2col_k<<<blk((long long)98 * 9 * 256), 256>>>(h, 512, 0, 512, 98, slh_h, slh_l);
    for (int t = 0; t < TSEG; t++) {
        dim3 grid(16, 1, 8);
        gemm_mma_k<3><<<grid, 256, GEMM_SMEM3>>>(slh_h, slh_l, wlh_h, part, K45, K45 / 8, 98, 2048,
                                                 nullptr, 0, GCH, nullptr,
                                                 nullptr, nullptr, nullptr, nullptr, 0);
        lstm_point_k<<<dim3(2, 64), cb>>>(gates0, part, h, cst, houts, t, slh_h, slh_l);
    }

    final_k<<<1, 512>>>(houts, fc_w, fc_b, out);
}